// round 12
// baseline (speedup 1.0000x reference)
#include <cuda_runtime.h>
#include <cuda_fp16.h>
#include <math.h>
#include <stdint.h>

#define Bc   64
#define Sc   512
#define Dc   512
#define Hc   8
#define DKc  64
#define Lc   4
#define DFFc 2048
#define NSKc 300
#define NSKp 384
#define FC1c 512
#define FC2c 256
#define Mr   (Bc * Sc)

// ---------------- fp32 scratch ----------------
__device__ float g_qe[(size_t)Mr * Dc];
__device__ float g_x [(size_t)Mr * Dc];
__device__ float g_K [(size_t)Mr * Dc];
__device__ float g_V [(size_t)Mr * Dc];
__device__ float g_P [(size_t)Mr * Dc];

// ---------------- fp16 activations (hi only) ----------------
__device__ __half g_xh [(size_t)Mr * Dc];
__device__ __half g_yh [(size_t)Mr * Dc];
__device__ __half g_Oh [(size_t)Mr * Dc];
__device__ __half g_F1h[(size_t)Mr * DFFc];
__device__ __half g_Ch [(size_t)Mr * 2 * Dc];
__device__ __half g_H1h[(size_t)Mr * FC1c];
__device__ __half g_H2h[(size_t)Mr * FC2c];

// ---------------- fp16 weights (transposed [N][K]) ----------------
__device__ __half g_Wk_h[(size_t)Lc * Dc * Dc];
__device__ __half g_Wv_h[(size_t)Lc * Dc * Dc];
__device__ __half g_Wo_h[(size_t)Lc * Dc * Dc];
__device__ __half g_W1_h[(size_t)Lc * Dc * DFFc];
__device__ __half g_W2_h[(size_t)Lc * DFFc * Dc];
__device__ __half g_Wo1_h[(size_t)2 * Dc * FC1c], g_Wo1_l[(size_t)2 * Dc * FC1c];
__device__ __half g_Wo2_h[(size_t)FC1c * FC2c],   g_Wo2_l[(size_t)FC1c * FC2c];
__device__ __half g_Wo3_h[(size_t)NSKp * FC2c],   g_Wo3_l[(size_t)NSKp * FC2c];

// ---------------- helpers ----------------
__device__ __forceinline__ uint32_t smem_u32(const void* p) {
    uint32_t a;
    asm("{ .reg .u64 t; cvta.to.shared.u64 t, %1; cvt.u32.u64 %0, t; }"
        : "=r"(a) : "l"(p));
    return a;
}
__device__ __forceinline__ void split2(float v, __half& h, __half& l) {
    h = __float2half_rn(v);
    l = __float2half_rn(v - __half2float(h));
}

#define CPA16(dst, src)                                                       \
    asm volatile("cp.async.cg.shared.global [%0], [%1], 16;"                  \
                 :: "r"(dst), "l"(src) : "memory")

#define LDMX4(R, addr)                                                        \
    asm volatile("ldmatrix.sync.aligned.m8n8.x4.shared.b16 {%0,%1,%2,%3}, [%4];" \
        : "=r"((R)[0]), "=r"((R)[1]), "=r"((R)[2]), "=r"((R)[3]) : "r"(addr))

#define LDMX2(R, addr)                                                        \
    asm volatile("ldmatrix.sync.aligned.m8n8.x2.shared.b16 {%0,%1}, [%2];"    \
        : "=r"((R)[0]), "=r"((R)[1]) : "r"(addr))

#define MMA16816(d, a, b)                                                     \
    asm volatile("mma.sync.aligned.m16n8k16.row.col.f32.f16.f16.f32 "         \
        "{%0,%1,%2,%3}, {%4,%5,%6,%7}, {%8,%9}, {%0,%1,%2,%3};"               \
        : "+f"((d)[0]), "+f"((d)[1]), "+f"((d)[2]), "+f"((d)[3])              \
        : "r"((a)[0]), "r"((a)[1]), "r"((a)[2]), "r"((a)[3]),                 \
          "r"((b)[0]), "r"((b)[1]))

// ---------------- weight prep: transpose + hi/lo split ----------------
__global__ void split_w_kernel(const float* __restrict__ W,
                               __half* __restrict__ Oh, __half* __restrict__ Ol,
                               int K, int N) {
    __shared__ float t[32][33];
    int k0 = blockIdx.y * 32, n0 = blockIdx.x * 32;
    #pragma unroll
    for (int i = 0; i < 4; i++) {
        int k = k0 + threadIdx.y + i * 8;
        int n = n0 + threadIdx.x;
        t[threadIdx.y + i * 8][threadIdx.x] = (n < N) ? W[(size_t)k * N + n] : 0.f;
    }
    __syncthreads();
    #pragma unroll
    for (int i = 0; i < 4; i++) {
        int n = n0 + threadIdx.y + i * 8;
        int k = k0 + threadIdx.x;
        float v = t[threadIdx.x][threadIdx.y + i * 8];
        __half h, l; split2(v, h, l);
        Oh[(size_t)n * K + k] = h;
        if (Ol) Ol[(size_t)n * K + k] = l;
    }
}

#define APITCH 40
#define TILE_B (128 * APITCH * 2)     // 10240

// ================= 1-term GEMM: C = Ah @ Bh + bias (layer GEMMs) ============
// 3-stage cp.async pipeline, prefetch depth 2, wait_group 1.
#define STAGE1_B (2 * TILE_B)         // 20480
#define GEMM1_DSMEM (3 * STAGE1_B)    // 61440

__device__ __forceinline__ void issue_stage1(
    uint32_t sb, const __half* Ah_g, const __half* Bh_g,
    int m0, int n0, int K, int kk, int tid) {
    #pragma unroll
    for (int p = 0; p < 2; p++) {
        int c = p * 256 + tid;
        int row = c >> 2, q = c & 3;
        uint32_t d = sb + (uint32_t)(row * 80 + q * 16);
        size_t ao = (size_t)(m0 + row) * K + kk + q * 8;
        size_t bo = (size_t)(n0 + row) * K + kk + q * 8;
        CPA16(d,          Ah_g + ao);
        CPA16(d + TILE_B, Bh_g + bo);
    }
    asm volatile("cp.async.commit_group;" ::: "memory");
}

__global__ __launch_bounds__(256, 2)
void gemm1_mma_kernel(const __half* __restrict__ Ah_g,
                      const __half* __restrict__ Bh_g,
                      const float* __restrict__ bias,
                      float* __restrict__ Cf,
                      __half* __restrict__ Coh,
                      int K, int N, int relu) {
    extern __shared__ char smem[];
    const int tid  = threadIdx.x;
    const int wid  = tid >> 5;
    const int lane = tid & 31;
    const int m0 = blockIdx.y * 128;
    const int n0 = blockIdx.x * 128;
    const int warp_m = (wid >> 2) * 64;
    const int warp_n = (wid & 3) * 32;

    const uint32_t sbase = smem_u32(smem);

    float acc[4][4][4];
    #pragma unroll
    for (int i = 0; i < 4; i++)
        #pragma unroll
        for (int j = 0; j < 4; j++)
            #pragma unroll
            for (int e = 0; e < 4; e++) acc[i][j][e] = 0.f;

    const int KT = K >> 5;
    const int r8  = lane & 7;
    const int sub = lane >> 3;
    const uint32_t a_lane_off =
        (uint32_t)(((warp_m + r8 + (sub & 1) * 8) * APITCH + (sub >> 1) * 8) * 2);
    const uint32_t b_lane_off =
        (uint32_t)(((warp_n + r8) * APITCH + (sub & 1) * 8) * 2);

    // prefetch depth 2 (stage buffers indexed kt % 3)
    issue_stage1(sbase, Ah_g, Bh_g, m0, n0, K, 0, tid);
    if (KT > 1)
        issue_stage1(sbase + STAGE1_B, Ah_g, Bh_g, m0, n0, K, 32, tid);

    int stage = 0;
    for (int kt = 0; kt < KT; kt++) {
        if (kt + 1 < KT)
            asm volatile("cp.async.wait_group 1;" ::: "memory");
        else
            asm volatile("cp.async.wait_group 0;" ::: "memory");
        __syncthreads();
        if (kt + 2 < KT) {
            int nst = stage + 2; if (nst >= 3) nst -= 3;
            issue_stage1(sbase + nst * STAGE1_B, Ah_g, Bh_g,
                         m0, n0, K, (kt + 2) << 5, tid);
        }

        const uint32_t stoff = stage * STAGE1_B;
        const uint32_t abase = sbase + stoff + a_lane_off;
        const uint32_t bbase = sbase + stoff + TILE_B + b_lane_off;

        #pragma unroll
        for (int ks = 0; ks < 2; ks++) {
            const uint32_t ak = abase + ks * 32;
            const uint32_t bk = bbase + ks * 32;

            uint32_t Ahf[4][4], Bhf[4][2];
            #pragma unroll
            for (int fi = 0; fi < 4; fi++)
                LDMX4(Ahf[fi], ak + fi * (16 * APITCH * 2));
            #pragma unroll
            for (int fj = 0; fj < 4; fj++)
                LDMX2(Bhf[fj], bk + fj * (8 * APITCH * 2));
            #pragma unroll
            for (int fi = 0; fi < 4; fi++)
                #pragma unroll
                for (int fj = 0; fj < 4; fj++)
                    MMA16816(acc[fi][fj], Ahf[fi], Bhf[fj]);
        }
        if (++stage == 3) stage = 0;
    }

    #pragma unroll
    for (int fj = 0; fj < 4; fj++) {
        const int c0 = n0 + warp_n + fj * 8 + 2 * (lane & 3);
        const bool c0ok = (c0 < N), c1ok = (c0 + 1 < N);
        const float b0 = c0ok ? bias[c0] : 0.f;
        const float b1 = c1ok ? bias[c0 + 1] : 0.f;
        #pragma unroll
        for (int fi = 0; fi < 4; fi++) {
            const int r0 = m0 + warp_m + fi * 16 + (lane >> 2);
            float v0 = acc[fi][fj][0] + b0;
            float v1 = acc[fi][fj][1] + b1;
            float v2 = acc[fi][fj][2] + b0;
            float v3 = acc[fi][fj][3] + b1;
            if (relu) {
                v0 = fmaxf(v0, 0.f); v1 = fmaxf(v1, 0.f);
                v2 = fmaxf(v2, 0.f); v3 = fmaxf(v3, 0.f);
            }
            if (Cf) {
                if (c0ok) {
                    Cf[(size_t)r0 * N + c0]       = v0;
                    Cf[(size_t)(r0 + 8) * N + c0] = v2;
                }
                if (c1ok) {
                    Cf[(size_t)r0 * N + c0 + 1]       = v1;
                    Cf[(size_t)(r0 + 8) * N + c0 + 1] = v3;
                }
            } else {
                if (c0ok) {
                    Coh[(size_t)r0 * N + c0]       = __float2half_rn(v0);
                    Coh[(size_t)(r0 + 8) * N + c0] = __float2half_rn(v2);
                }
                if (c1ok) {
                    Coh[(size_t)r0 * N + c0 + 1]       = __float2half_rn(v1);
                    Coh[(size_t)(r0 + 8) * N + c0 + 1] = __float2half_rn(v3);
                }
            }
        }
    }
}

// ================= 2-term GEMM: C = Ah @ (Bh + Bl) + bias (head) ============
#define STAGE2_B (3 * TILE_B)         // 30720
#define GEMM2_DSMEM (3 * STAGE2_B)    // 92160

__device__ __forceinline__ void issue_stage2(
    uint32_t sb, const __half* Ah_g, const __half* Bh_g, const __half* Bl_g,
    int m0, int n0, int K, int kk, int tid) {
    #pragma unroll
    for (int p = 0; p < 2; p++) {
        int c = p * 256 + tid;
        int row = c >> 2, q = c & 3;
        uint32_t d = sb + (uint32_t)(row * 80 + q * 16);
        size_t ao = (size_t)(m0 + row) * K + kk + q * 8;
        size_t bo = (size_t)(n0 + row) * K + kk + q * 8;
        CPA16(d,              Ah_g + ao);
        CPA16(d + TILE_B,     Bh_g + bo);
        CPA16(d + 2 * TILE_B, Bl_g + bo);
    }
    asm volatile("cp.async.commit_group;" ::: "memory");
}

__global__ __launch_bounds__(256, 2)
void gemm2_mma_kernel(const __half* __restrict__ Ah_g,
                      const __half* __restrict__ Bh_g,
                      const __half* __restrict__ Bl_g,
                      const float* __restrict__ bias,
                      float* __restrict__ Cf,
                      __half* __restrict__ Coh,
                      int K, int N, int relu) {
    extern __shared__ char smem[];
    const int tid  = threadIdx.x;
    const int wid  = tid >> 5;
    const int lane = tid & 31;
    const int m0 = blockIdx.y * 128;
    const int n0 = blockIdx.x * 128;
    const int warp_m = (wid >> 2) * 64;
    const int warp_n = (wid & 3) * 32;

    const uint32_t sbase = smem_u32(smem);

    float acc[4][4][4];
    #pragma unroll
    for (int i = 0; i < 4; i++)
        #pragma unroll
        for (int j = 0; j < 4; j++)
            #pragma unroll
            for (int e = 0; e < 4; e++) acc[i][j][e] = 0.f;

    const int KT = K >> 5;
    const int r8  = lane & 7;
    const int sub = lane >> 3;
    const uint32_t a_lane_off =
        (uint32_t)(((warp_m + r8 + (sub & 1) * 8) * APITCH + (sub >> 1) * 8) * 2);
    const uint32_t b_lane_off =
        (uint32_t)(((warp_n + r8) * APITCH + (sub & 1) * 8) * 2);

    issue_stage2(sbase, Ah_g, Bh_g, Bl_g, m0, n0, K, 0, tid);
    if (KT > 1)
        issue_stage2(sbase + STAGE2_B, Ah_g, Bh_g, Bl_g, m0, n0, K, 32, tid);

    int stage = 0;
    for (int kt = 0; kt < KT; kt++) {
        if (kt + 1 < KT)
            asm volatile("cp.async.wait_group 1;" ::: "memory");
        else
            asm volatile("cp.async.wait_group 0;" ::: "memory");
        __syncthreads();
        if (kt + 2 < KT) {
            int nst = stage + 2; if (nst >= 3) nst -= 3;
            issue_stage2(sbase + nst * STAGE2_B, Ah_g, Bh_g, Bl_g,
                         m0, n0, K, (kt + 2) << 5, tid);
        }

        const uint32_t stoff = stage * STAGE2_B;
        const uint32_t abase = sbase + stoff + a_lane_off;
        const uint32_t bbase = sbase + stoff + TILE_B + b_lane_off;

        #pragma unroll
        for (int ks = 0; ks < 2; ks++) {
            const uint32_t ak = abase + ks * 32;
            const uint32_t bk = bbase + ks * 32;

            uint32_t Ahf[4][4], Bhf[4][2], Blf[4][2];
            #pragma unroll
            for (int fi = 0; fi < 4; fi++)
                LDMX4(Ahf[fi], ak + fi * (16 * APITCH * 2));
            #pragma unroll
            for (int fj = 0; fj < 4; fj++)
                LDMX2(Bhf[fj], bk + fj * (8 * APITCH * 2));
            #pragma unroll
            for (int fi = 0; fi < 4; fi++)
                #pragma unroll
                for (int fj = 0; fj < 4; fj++)
                    MMA16816(acc[fi][fj], Ahf[fi], Bhf[fj]);

            #pragma unroll
            for (int fj = 0; fj < 4; fj++)
                LDMX2(Blf[fj], bk + TILE_B + fj * (8 * APITCH * 2));
            #pragma unroll
            for (int fi = 0; fi < 4; fi++)
                #pragma unroll
                for (int fj = 0; fj < 4; fj++)
                    MMA16816(acc[fi][fj], Ahf[fi], Blf[fj]);
        }
        if (++stage == 3) stage = 0;
    }

    #pragma unroll
    for (int fj = 0; fj < 4; fj++) {
        const int c0 = n0 + warp_n + fj * 8 + 2 * (lane & 3);
        const bool c0ok = (c0 < N), c1ok = (c0 + 1 < N);
        const float b0 = c0ok ? bias[c0] : 0.f;
        const float b1 = c1ok ? bias[c0 + 1] : 0.f;
        #pragma unroll
        for (int fi = 0; fi < 4; fi++) {
            const int r0 = m0 + warp_m + fi * 16 + (lane >> 2);
            float v0 = acc[fi][fj][0] + b0;
            float v1 = acc[fi][fj][1] + b1;
            float v2 = acc[fi][fj][2] + b0;
            float v3 = acc[fi][fj][3] + b1;
            if (relu) {
                v0 = fmaxf(v0, 0.f); v1 = fmaxf(v1, 0.f);
                v2 = fmaxf(v2, 0.f); v3 = fmaxf(v3, 0.f);
            }
            if (Cf) {
                if (c0ok) {
                    Cf[(size_t)r0 * N + c0]       = v0;
                    Cf[(size_t)(r0 + 8) * N + c0] = v2;
                }
                if (c1ok) {
                    Cf[(size_t)r0 * N + c0 + 1]       = v1;
                    Cf[(size_t)(r0 + 8) * N + c0 + 1] = v3;
                }
            } else {
                if (c0ok) {
                    Coh[(size_t)r0 * N + c0]       = __float2half_rn(v0);
                    Coh[(size_t)(r0 + 8) * N + c0] = __float2half_rn(v2);
                }
                if (c1ok) {
                    Coh[(size_t)r0 * N + c0 + 1]       = __float2half_rn(v1);
                    Coh[(size_t)(r0 + 8) * N + c0 + 1] = __float2half_rn(v3);
                }
            }
        }
    }
}

// ---------------- embed ----------------
__global__ void embed_kernel(const int* __restrict__ q_data,
                             const int* __restrict__ target,
                             const float* __restrict__ pe,
                             const float* __restrict__ q_emb,
                             const float* __restrict__ qa_emb) {
    size_t idx = (size_t)blockIdx.x * blockDim.x + threadIdx.x;
    if (idx >= (size_t)Mr * Dc) return;
    int bs = (int)(idx / Dc);
    int d  = (int)(idx % Dc);
    int s  = bs % Sc;
    float qe = q_emb[(size_t)q_data[bs] * Dc + d];
    float p  = pe[(size_t)s * Dc + d];
    float x  = qe + p;
    float y  = qa_emb[(size_t)target[bs] * Dc + d] + qe + p;
    g_qe[idx] = qe;
    g_x [idx] = x;
    g_xh[idx] = __float2half_rn(x);
    g_yh[idx] = __float2half_rn(y);
}

// ---------------- flash attention (fp32 in, fp16 hi out) ----------------
__global__ __launch_bounds__(256)
void attn_kernel() {
    const int qt = blockIdx.x, hh = blockIdx.y, b = blockIdx.z;
    const int tid = threadIdx.x;
    const int r = tid >> 2;
    const int p = tid & 3;
    const int i = qt * 64 + r;
    const float scale = 0.125f;

    __shared__ float Kt[64][64];
    __shared__ float Vt[64][64];

    float q[16];
    {
        const float* qp = g_K + ((size_t)(b * Sc + i)) * Dc + hh * DKc + p * 16;
        #pragma unroll
        for (int w = 0; w < 4; w++) {
            float4 v = *(const float4*)(qp + w * 4);
            q[w * 4 + 0] = v.x; q[w * 4 + 1] = v.y;
            q[w * 4 + 2] = v.z; q[w * 4 + 3] = v.w;
        }
    }

    float m_run = -1e30f, l_run = 0.f;
    float o[16];
    #pragma unroll
    for (int d = 0; d < 16; d++) o[d] = 0.f;

    for (int jt = 0; jt <= qt; jt++) {
        const size_t base = ((size_t)(b * Sc + jt * 64 + r)) * Dc + hh * DKc + p * 16;
        #pragma unroll
        for (int w = 0; w < 4; w++) {
            *(float4*)&Kt[r][p * 16 + w * 4] = *(const float4*)(g_K + base + w * 4);
            *(float4*)&Vt[r][p * 16 + w * 4] = *(const float4*)(g_V + base + w * 4);
        }
        __syncthreads();

        for (int j = 0; j < 64; j++) {
            float s = 0.f;
            #pragma unroll
            for (int d = 0; d < 16; d++) s += q[d] * Kt[j][p * 16 + d];
            s += __shfl_xor_sync(0xffffffffu, s, 1);
            s += __shfl_xor_sync(0xffffffffu, s, 2);
            s *= scale;
            if (jt * 64 + j < i) {
                float m_new = fmaxf(m_run, s);
                float corr  = __expf(m_run - m_new);
                float pj    = __expf(s - m_new);
                l_run = l_run * corr + pj;
                #pragma unroll
                for (int d = 0; d < 16; d++)
                    o[d] = o[d] * corr + pj * Vt[j][p * 16 + d];
                m_run = m_new;
            }
        }
        __syncthreads();
    }

    float inv = (l_run > 0.f) ? (1.f / l_run) : 0.f;
    size_t ob = ((size_t)(b * Sc + i)) * Dc + hh * DKc + p * 16;
    #pragma unroll
    for (int d = 0; d < 16; d++)
        g_Oh[ob + d] = __float2half_rn(o[d] * inv);
}

// ---------------- fused add + LayerNorm (+ fp16 hi out) ----------------
__global__ __launch_bounds__(256)
void add_ln_kernel(float* __restrict__ x, const float* __restrict__ resid,
                   const float* __restrict__ g, const float* __restrict__ b) {
    const int row = blockIdx.x;
    const int tid = threadIdx.x;
    const size_t base = (size_t)row * Dc;
    float v0 = x[base + tid]       + resid[base + tid];
    float v1 = x[base + tid + 256] + resid[base + tid + 256];
    float s  = v0 + v1;
    float ss = v0 * v0 + v1 * v1;

    __shared__ float sbuf[8], ssbuf[8];
    #pragma unroll
    for (int o = 16; o > 0; o >>= 1) {
        s  += __shfl_xor_sync(0xffffffffu, s, o);
        ss += __shfl_xor_sync(0xffffffffu, ss, o);
    }
    if ((tid & 31) == 0) { sbuf[tid >> 5] = s; ssbuf[tid >> 5] = ss; }
    __syncthreads();
    if (tid < 32) {
        s  = (tid < 8) ? sbuf[tid]  : 0.f;
        ss = (tid < 8) ? ssbuf[tid] : 0.f;
        #pragma unroll
        for (int o = 4; o > 0; o >>= 1) {
            s  += __shfl_xor_sync(0xffffffffu, s, o);
            ss += __shfl_xor_sync(0xffffffffu, ss, o);
        }
        if (tid == 0) { sbuf[0] = s; ssbuf[0] = ss; }
    }
    __syncthreads();
    float mean = sbuf[0] * (1.f / 512.f);
    float var  = ssbuf[0] * (1.f / 512.f) - mean * mean;
    float rstd = rsqrtf(var + 1e-5f);
    float o0 = (v0 - mean) * rstd * g[tid]       + b[tid];
    float o1 = (v1 - mean) * rstd * g[tid + 256] + b[tid + 256];
    x[base + tid]       = o0;
    x[base + tid + 256] = o1;
    g_xh[base + tid]       = __float2half_rn(o0);
    g_xh[base + tid + 256] = __float2half_rn(o1);
}

// ---------------- concat [x | qe] -> fp16 hi ----------------
__global__ void concat_kernel() {
    size_t idx = (size_t)blockIdx.x * blockDim.x + threadIdx.x;
    if (idx >= (size_t)Mr * 2 * Dc) return;
    int bs = (int)(idx / (2 * Dc));
    int c  = (int)(idx % (2 * Dc));
    float v = (c < Dc) ? g_x[(size_t)bs * Dc + c]
                       : g_qe[(size_t)bs * Dc + (c - Dc)];
    g_Ch[idx] = __float2half_rn(v);
}

// ---------------- host ----------------
static inline void split_w(const float* W, __half* oh, __half* ol,
                           int K, int N, int Npad) {
    split_w_kernel<<<dim3(Npad / 32, K / 32), dim3(32, 8)>>>(W, oh, ol, K, N);
}
static inline void gemm1F32(const __half* ah, const __half* bh,
                            const float* bias, float* C, int K, int N, int Npad,
                            int relu) {
    gemm1_mma_kernel<<<dim3(Npad / 128, Mr / 128), 256, GEMM1_DSMEM>>>(
        ah, bh, bias, C, nullptr, K, N, relu);
}
static inline void gemm1F16(const __half* ah, const __half* bh,
                            const float* bias, __half* oh, int K, int N,
                            int Npad, int relu) {
    gemm1_mma_kernel<<<dim3(Npad / 128, Mr / 128), 256, GEMM1_DSMEM>>>(
        ah, bh, bias, nullptr, oh, K, N, relu);
}
static inline void gemm2F32(const __half* ah, const __half* bh, const __half* bl,
                            const float* bias, float* C, int K, int N, int Npad,
                            int relu) {
    gemm2_mma_kernel<<<dim3(Npad / 128, Mr / 128), 256, GEMM2_DSMEM>>>(
        ah, bh, bl, bias, C, nullptr, K, N, relu);
}
static inline void gemm2F16(const __half* ah, const __half* bh, const __half* bl,
                            const float* bias, __half* oh, int K, int N,
                            int Npad, int relu) {
    gemm2_mma_kernel<<<dim3(Npad / 128, Mr / 128), 256, GEMM2_DSMEM>>>(
        ah, bh, bl, bias, nullptr, oh, K, N, relu);
}

extern "C" void kernel_launch(void* const* d_in, const int* in_sizes, int n_in,
                              void* d_out, int out_size) {
    const int*   q_data = (const int*)d_in[0];
    const int*   target = (const int*)d_in[1];
    const float* pe     = (const float*)d_in[2];
    const float* q_emb  = (const float*)d_in[3];
    const float* qa_emb = (const float*)d_in[4];
    const float* Wk     = (const float*)d_in[5];
    const float* bk     = (const float*)d_in[6];
    const float* Wv     = (const float*)d_in[7];
    const float* bv     = (const float*)d_in[8];
    const float* Wo     = (const float*)d_in[9];
    const float* bo     = (const float*)d_in[10];
    const float* ln1_g  = (const float*)d_in[11];
    const float* ln1_b  = (const float*)d_in[12];
    const float* W1     = (const float*)d_in[13];
    const float* b1     = (const float*)d_in[14];
    const float* W2     = (const float*)d_in[15];
    const float* b2     = (const float*)d_in[16];
    const float* ln2_g  = (const float*)d_in[17];
    const float* ln2_b  = (const float*)d_in[18];
    const float* Wout1  = (const float*)d_in[19];
    const float* bout1  = (const float*)d_in[20];
    const float* Wout2  = (const float*)d_in[21];
    const float* bout2  = (const float*)d_in[22];
    const float* Wout3  = (const float*)d_in[23];
    const float* bout3  = (const float*)d_in[24];
    float* out = (float*)d_out;

    cudaFuncSetAttribute(gemm1_mma_kernel,
                         cudaFuncAttributeMaxDynamicSharedMemorySize, GEMM1_DSMEM);
    cudaFuncSetAttribute(gemm2_mma_kernel,
                         cudaFuncAttributeMaxDynamicSharedMemorySize, GEMM2_DSMEM);

    float *p_x, *p_K, *p_V, *p_P;
    cudaGetSymbolAddress((void**)&p_x, g_x);
    cudaGetSymbolAddress((void**)&p_K, g_K);
    cudaGetSymbolAddress((void**)&p_V, g_V);
    cudaGetSymbolAddress((void**)&p_P, g_P);

    __half *xh, *yh, *oh, *f1h, *ch, *h1h, *h2h;
    cudaGetSymbolAddress((void**)&xh, g_xh);
    cudaGetSymbolAddress((void**)&yh, g_yh);
    cudaGetSymbolAddress((void**)&oh, g_Oh);
    cudaGetSymbolAddress((void**)&f1h, g_F1h);
    cudaGetSymbolAddress((void**)&ch, g_Ch);
    cudaGetSymbolAddress((void**)&h1h, g_H1h);
    cudaGetSymbolAddress((void**)&h2h, g_H2h);

    __half *wk_h, *wv_h, *wo_h, *w1_h, *w2_h;
    __half *wo1_h, *wo1_l, *wo2_h, *wo2_l, *wo3_h, *wo3_l;
    cudaGetSymbolAddress((void**)&wk_h, g_Wk_h);
    cudaGetSymbolAddress((void**)&wv_h, g_Wv_h);
    cudaGetSymbolAddress((void**)&wo_h, g_Wo_h);
    cudaGetSymbolAddress((void**)&w1_h, g_W1_h);
    cudaGetSymbolAddress((void**)&w2_h, g_W2_h);
    cudaGetSymbolAddress((void**)&wo1_h, g_Wo1_h); cudaGetSymbolAddress((void**)&wo1_l, g_Wo1_l);
    cudaGetSymbolAddress((void**)&wo2_h, g_Wo2_h); cudaGetSymbolAddress((void**)&wo2_l, g_Wo2_l);
    cudaGetSymbolAddress((void**)&wo3_h, g_Wo3_h); cudaGetSymbolAddress((void**)&wo3_l, g_Wo3_l);

    // embed + weight prep
    {
        size_t tot = (size_t)Mr * Dc;
        embed_kernel<<<(unsigned)((tot + 255) / 256), 256>>>(q_data, target, pe,
                                                             q_emb, qa_emb);
    }
    for (int l = 0; l < Lc; l++) {
        size_t oDD = (size_t)l * Dc * Dc;
        size_t oDF = (size_t)l * Dc * DFFc;
        split_w(Wk + oDD, wk_h + oDD, nullptr, Dc, Dc, Dc);
        split_w(Wv + oDD, wv_h + oDD, nullptr, Dc, Dc, Dc);
        split_w(Wo + oDD, wo_h + oDD, nullptr, Dc, Dc, Dc);
        split_w(W1 + oDF, w1_h + oDF, nullptr, Dc, DFFc, DFFc);
        split_w(W2 + oDF, w2_h + oDF, nullptr, DFFc, Dc, Dc);
    }
    split_w(Wout1, wo1_h, wo1_l, 2 * Dc, FC1c, FC1c);
    split_w(Wout2, wo2_h, wo2_l, FC1c, FC2c, FC2c);
    split_w(Wout3, wo3_h, wo3_l, FC2c, NSKc, NSKp);

    // transformer layers (single-term hi-only GEMMs)
    for (int l = 0; l < Lc; l++) {
        size_t oDD = (size_t)l * Dc * Dc;
        size_t oDF = (size_t)l * Dc * DFFc;
        gemm1F32(xh, wk_h + oDD, bk + l * Dc, p_K, Dc, Dc, Dc, 0);
        gemm1F32(yh, wv_h + oDD, bv + l * Dc, p_V, Dc, Dc, Dc, 0);
        attn_kernel<<<dim3(Sc / 64, Hc, Bc), 256>>>();
        gemm1F32(oh, wo_h + oDD, bo + l * Dc, p_P, Dc, Dc, Dc, 0);
        add_ln_kernel<<<Mr, 256>>>(p_x, p_P, ln1_g + l * Dc, ln1_b + l * Dc);
        gemm1F16(xh, w1_h + oDF, b1 + l * DFFc, f1h, Dc, DFFc, DFFc, 1);
        gemm1F32(f1h, w2_h + oDF, b2 + l * Dc, p_P, DFFc, Dc, Dc, 0);
        add_ln_kernel<<<Mr, 256>>>(p_x, p_P, ln2_g + l * Dc, ln2_b + l * Dc);
    }

    // head (two-term)
    {
        size_t tot = (size_t)Mr * 2 * Dc;
        concat_kernel<<<(unsigned)((tot + 255) / 256), 256>>>();
    }
    gemm2F16(ch, wo1_h, wo1_l, bout1, h1h, 2 * Dc, FC1c, FC1c, 1);
    gemm2F16(h1h, wo2_h, wo2_l, bout2, h2h, FC1c, FC2c, FC2c, 1);
    gemm2F32(h2h, wo3_h, wo3_l, bout3, out, FC2c, NSKc, NSKp, 0);
}

// round 13
// speedup vs baseline: 1.0342x; 1.0342x over previous
#include <cuda_runtime.h>
#include <cuda_fp16.h>
#include <math.h>
#include <stdint.h>

#define Bc   64
#define Sc   512
#define Dc   512
#define Hc   8
#define DKc  64
#define Lc   4
#define DFFc 2048
#define NSKc 300
#define NSKp 384
#define FC1c 512
#define FC2c 256
#define Mr   (Bc * Sc)

// ---------------- fp32 scratch ----------------
__device__ float g_qe[(size_t)Mr * Dc];
__device__ float g_x [(size_t)Mr * Dc];
__device__ float g_K [(size_t)Mr * Dc];
__device__ float g_V [(size_t)Mr * Dc];
__device__ float g_P [(size_t)Mr * Dc];

// ---------------- fp16 activations (hi only) ----------------
__device__ __half g_xh [(size_t)Mr * Dc];
__device__ __half g_yh [(size_t)Mr * Dc];
__device__ __half g_Oh [(size_t)Mr * Dc];
__device__ __half g_F1h[(size_t)Mr * DFFc];
__device__ __half g_Ch [(size_t)Mr * 2 * Dc];
__device__ __half g_H1h[(size_t)Mr * FC1c];
__device__ __half g_H2h[(size_t)Mr * FC2c];

// ---------------- fp16 weights (transposed [N][K]) ----------------
__device__ __half g_Wk_h[(size_t)Lc * Dc * Dc];
__device__ __half g_Wv_h[(size_t)Lc * Dc * Dc];
__device__ __half g_Wo_h[(size_t)Lc * Dc * Dc];
__device__ __half g_W1_h[(size_t)Lc * Dc * DFFc];
__device__ __half g_W2_h[(size_t)Lc * DFFc * Dc];
__device__ __half g_Wo1_h[(size_t)2 * Dc * FC1c], g_Wo1_l[(size_t)2 * Dc * FC1c];
__device__ __half g_Wo2_h[(size_t)FC1c * FC2c],   g_Wo2_l[(size_t)FC1c * FC2c];
__device__ __half g_Wo3_h[(size_t)NSKp * FC2c],   g_Wo3_l[(size_t)NSKp * FC2c];

// ---------------- helpers ----------------
__device__ __forceinline__ uint32_t smem_u32(const void* p) {
    uint32_t a;
    asm("{ .reg .u64 t; cvta.to.shared.u64 t, %1; cvt.u32.u64 %0, t; }"
        : "=r"(a) : "l"(p));
    return a;
}
__device__ __forceinline__ void split2(float v, __half& h, __half& l) {
    h = __float2half_rn(v);
    l = __float2half_rn(v - __half2float(h));
}

#define CPA16(dst, src)                                                       \
    asm volatile("cp.async.cg.shared.global [%0], [%1], 16;"                  \
                 :: "r"(dst), "l"(src) : "memory")

#define LDMX4(R, addr)                                                        \
    asm volatile("ldmatrix.sync.aligned.m8n8.x4.shared.b16 {%0,%1,%2,%3}, [%4];" \
        : "=r"((R)[0]), "=r"((R)[1]), "=r"((R)[2]), "=r"((R)[3]) : "r"(addr))

#define LDMX2(R, addr)                                                        \
    asm volatile("ldmatrix.sync.aligned.m8n8.x2.shared.b16 {%0,%1}, [%2];"    \
        : "=r"((R)[0]), "=r"((R)[1]) : "r"(addr))

#define MMA16816(d, a, b)                                                     \
    asm volatile("mma.sync.aligned.m16n8k16.row.col.f32.f16.f16.f32 "         \
        "{%0,%1,%2,%3}, {%4,%5,%6,%7}, {%8,%9}, {%0,%1,%2,%3};"               \
        : "+f"((d)[0]), "+f"((d)[1]), "+f"((d)[2]), "+f"((d)[3])              \
        : "r"((a)[0]), "r"((a)[1]), "r"((a)[2]), "r"((a)[3]),                 \
          "r"((b)[0]), "r"((b)[1]))

// ---------------- weight prep: transpose + hi/lo split ----------------
__global__ void split_w_kernel(const float* __restrict__ W,
                               __half* __restrict__ Oh, __half* __restrict__ Ol,
                               int K, int N) {
    __shared__ float t[32][33];
    int k0 = blockIdx.y * 32, n0 = blockIdx.x * 32;
    #pragma unroll
    for (int i = 0; i < 4; i++) {
        int k = k0 + threadIdx.y + i * 8;
        int n = n0 + threadIdx.x;
        t[threadIdx.y + i * 8][threadIdx.x] = (n < N) ? W[(size_t)k * N + n] : 0.f;
    }
    __syncthreads();
    #pragma unroll
    for (int i = 0; i < 4; i++) {
        int n = n0 + threadIdx.y + i * 8;
        int k = k0 + threadIdx.x;
        float v = t[threadIdx.x][threadIdx.y + i * 8];
        __half h, l; split2(v, h, l);
        Oh[(size_t)n * K + k] = h;
        if (Ol) Ol[(size_t)n * K + k] = l;
    }
}

// BK = 64: rows of 64 halfs (128 B) + 16 B pad -> APITCH 72 halfs (144 B)
#define APITCH 72
#define TILE_B (128 * APITCH * 2)     // 18432

// ================= 1-term GEMM: C = Ah @ Bh + bias (layer GEMMs) ============
#define STAGE1_B (2 * TILE_B)         // 36864
#define GEMM1_DSMEM (2 * STAGE1_B)    // 73728

__device__ __forceinline__ void issue_stage1(
    uint32_t sb, const __half* Ah_g, const __half* Bh_g,
    int m0, int n0, int K, int kk, int tid) {
    #pragma unroll
    for (int p = 0; p < 4; p++) {
        int c = p * 256 + tid;
        int row = c >> 3, q = c & 7;
        uint32_t d = sb + (uint32_t)(row * 144 + q * 16);
        size_t ao = (size_t)(m0 + row) * K + kk + q * 8;
        size_t bo = (size_t)(n0 + row) * K + kk + q * 8;
        CPA16(d,          Ah_g + ao);
        CPA16(d + TILE_B, Bh_g + bo);
    }
    asm volatile("cp.async.commit_group;" ::: "memory");
}

__global__ __launch_bounds__(256, 2)
void gemm1_mma_kernel(const __half* __restrict__ Ah_g,
                      const __half* __restrict__ Bh_g,
                      const float* __restrict__ bias,
                      float* __restrict__ Cf,
                      __half* __restrict__ Coh,
                      int K, int N, int relu) {
    extern __shared__ char smem[];
    const int tid  = threadIdx.x;
    const int wid  = tid >> 5;
    const int lane = tid & 31;
    const int m0 = blockIdx.y * 128;
    const int n0 = blockIdx.x * 128;
    const int warp_m = (wid >> 2) * 64;
    const int warp_n = (wid & 3) * 32;

    const uint32_t sbase = smem_u32(smem);

    float acc[4][4][4];
    #pragma unroll
    for (int i = 0; i < 4; i++)
        #pragma unroll
        for (int j = 0; j < 4; j++)
            #pragma unroll
            for (int e = 0; e < 4; e++) acc[i][j][e] = 0.f;

    const int KT = K >> 6;
    const int r8  = lane & 7;
    const int sub = lane >> 3;
    const uint32_t a_lane_off =
        (uint32_t)(((warp_m + r8 + (sub & 1) * 8) * APITCH + (sub >> 1) * 8) * 2);
    const uint32_t b_lane_off =
        (uint32_t)(((warp_n + r8) * APITCH + (sub & 1) * 8) * 2);

    issue_stage1(sbase, Ah_g, Bh_g, m0, n0, K, 0, tid);

    for (int kt = 0; kt < KT; kt++) {
        asm volatile("cp.async.wait_group 0;" ::: "memory");
        __syncthreads();
        if (kt + 1 < KT)
            issue_stage1(sbase + ((kt + 1) & 1) * STAGE1_B, Ah_g, Bh_g,
                         m0, n0, K, (kt + 1) << 6, tid);

        const uint32_t stoff = (kt & 1) * STAGE1_B;
        const uint32_t abase = sbase + stoff + a_lane_off;
        const uint32_t bbase = sbase + stoff + TILE_B + b_lane_off;

        #pragma unroll
        for (int ks = 0; ks < 4; ks++) {
            const uint32_t ak = abase + ks * 32;
            const uint32_t bk = bbase + ks * 32;

            uint32_t Ahf[4][4], Bhf[4][2];
            #pragma unroll
            for (int fi = 0; fi < 4; fi++)
                LDMX4(Ahf[fi], ak + fi * (16 * APITCH * 2));
            #pragma unroll
            for (int fj = 0; fj < 4; fj++)
                LDMX2(Bhf[fj], bk + fj * (8 * APITCH * 2));
            #pragma unroll
            for (int fi = 0; fi < 4; fi++)
                #pragma unroll
                for (int fj = 0; fj < 4; fj++)
                    MMA16816(acc[fi][fj], Ahf[fi], Bhf[fj]);
        }
    }

    #pragma unroll
    for (int fj = 0; fj < 4; fj++) {
        const int c0 = n0 + warp_n + fj * 8 + 2 * (lane & 3);
        const bool c0ok = (c0 < N), c1ok = (c0 + 1 < N);
        const float b0 = c0ok ? bias[c0] : 0.f;
        const float b1 = c1ok ? bias[c0 + 1] : 0.f;
        #pragma unroll
        for (int fi = 0; fi < 4; fi++) {
            const int r0 = m0 + warp_m + fi * 16 + (lane >> 2);
            float v0 = acc[fi][fj][0] + b0;
            float v1 = acc[fi][fj][1] + b1;
            float v2 = acc[fi][fj][2] + b0;
            float v3 = acc[fi][fj][3] + b1;
            if (relu) {
                v0 = fmaxf(v0, 0.f); v1 = fmaxf(v1, 0.f);
                v2 = fmaxf(v2, 0.f); v3 = fmaxf(v3, 0.f);
            }
            if (Cf) {
                if (c0ok) {
                    Cf[(size_t)r0 * N + c0]       = v0;
                    Cf[(size_t)(r0 + 8) * N + c0] = v2;
                }
                if (c1ok) {
                    Cf[(size_t)r0 * N + c0 + 1]       = v1;
                    Cf[(size_t)(r0 + 8) * N + c0 + 1] = v3;
                }
            } else {
                if (c0ok) {
                    Coh[(size_t)r0 * N + c0]       = __float2half_rn(v0);
                    Coh[(size_t)(r0 + 8) * N + c0] = __float2half_rn(v2);
                }
                if (c1ok) {
                    Coh[(size_t)r0 * N + c0 + 1]       = __float2half_rn(v1);
                    Coh[(size_t)(r0 + 8) * N + c0 + 1] = __float2half_rn(v3);
                }
            }
        }
    }
}

// ================= 2-term GEMM: C = Ah @ (Bh + Bl) + bias (head) ============
#define STAGE2_B (3 * TILE_B)         // 55296
#define GEMM2_DSMEM (2 * STAGE2_B)    // 110592

__device__ __forceinline__ void issue_stage2(
    uint32_t sb, const __half* Ah_g, const __half* Bh_g, const __half* Bl_g,
    int m0, int n0, int K, int kk, int tid) {
    #pragma unroll
    for (int p = 0; p < 4; p++) {
        int c = p * 256 + tid;
        int row = c >> 3, q = c & 7;
        uint32_t d = sb + (uint32_t)(row * 144 + q * 16);
        size_t ao = (size_t)(m0 + row) * K + kk + q * 8;
        size_t bo = (size_t)(n0 + row) * K + kk + q * 8;
        CPA16(d,              Ah_g + ao);
        CPA16(d + TILE_B,     Bh_g + bo);
        CPA16(d + 2 * TILE_B, Bl_g + bo);
    }
    asm volatile("cp.async.commit_group;" ::: "memory");
}

__global__ __launch_bounds__(256, 2)
void gemm2_mma_kernel(const __half* __restrict__ Ah_g,
                      const __half* __restrict__ Bh_g,
                      const __half* __restrict__ Bl_g,
                      const float* __restrict__ bias,
                      float* __restrict__ Cf,
                      __half* __restrict__ Coh,
                      int K, int N, int relu) {
    extern __shared__ char smem[];
    const int tid  = threadIdx.x;
    const int wid  = tid >> 5;
    const int lane = tid & 31;
    const int m0 = blockIdx.y * 128;
    const int n0 = blockIdx.x * 128;
    const int warp_m = (wid >> 2) * 64;
    const int warp_n = (wid & 3) * 32;

    const uint32_t sbase = smem_u32(smem);

    float acc[4][4][4];
    #pragma unroll
    for (int i = 0; i < 4; i++)
        #pragma unroll
        for (int j = 0; j < 4; j++)
            #pragma unroll
            for (int e = 0; e < 4; e++) acc[i][j][e] = 0.f;

    const int KT = K >> 6;
    const int r8  = lane & 7;
    const int sub = lane >> 3;
    const uint32_t a_lane_off =
        (uint32_t)(((warp_m + r8 + (sub & 1) * 8) * APITCH + (sub >> 1) * 8) * 2);
    const uint32_t b_lane_off =
        (uint32_t)(((warp_n + r8) * APITCH + (sub & 1) * 8) * 2);

    issue_stage2(sbase, Ah_g, Bh_g, Bl_g, m0, n0, K, 0, tid);

    for (int kt = 0; kt < KT; kt++) {
        asm volatile("cp.async.wait_group 0;" ::: "memory");
        __syncthreads();
        if (kt + 1 < KT)
            issue_stage2(sbase + ((kt + 1) & 1) * STAGE2_B, Ah_g, Bh_g, Bl_g,
                         m0, n0, K, (kt + 1) << 6, tid);

        const uint32_t stoff = (kt & 1) * STAGE2_B;
        const uint32_t abase = sbase + stoff + a_lane_off;
        const uint32_t bbase = sbase + stoff + TILE_B + b_lane_off;

        #pragma unroll
        for (int ks = 0; ks < 4; ks++) {
            const uint32_t ak = abase + ks * 32;
            const uint32_t bk = bbase + ks * 32;

            uint32_t Ahf[4][4], Bhf[4][2], Blf[4][2];
            #pragma unroll
            for (int fi = 0; fi < 4; fi++)
                LDMX4(Ahf[fi], ak + fi * (16 * APITCH * 2));
            #pragma unroll
            for (int fj = 0; fj < 4; fj++)
                LDMX2(Bhf[fj], bk + fj * (8 * APITCH * 2));
            #pragma unroll
            for (int fi = 0; fi < 4; fi++)
                #pragma unroll
                for (int fj = 0; fj < 4; fj++)
                    MMA16816(acc[fi][fj], Ahf[fi], Bhf[fj]);

            #pragma unroll
            for (int fj = 0; fj < 4; fj++)
                LDMX2(Blf[fj], bk + TILE_B + fj * (8 * APITCH * 2));
            #pragma unroll
            for (int fi = 0; fi < 4; fi++)
                #pragma unroll
                for (int fj = 0; fj < 4; fj++)
                    MMA16816(acc[fi][fj], Ahf[fi], Blf[fj]);
        }
    }

    #pragma unroll
    for (int fj = 0; fj < 4; fj++) {
        const int c0 = n0 + warp_n + fj * 8 + 2 * (lane & 3);
        const bool c0ok = (c0 < N), c1ok = (c0 + 1 < N);
        const float b0 = c0ok ? bias[c0] : 0.f;
        const float b1 = c1ok ? bias[c0 + 1] : 0.f;
        #pragma unroll
        for (int fi = 0; fi < 4; fi++) {
            const int r0 = m0 + warp_m + fi * 16 + (lane >> 2);
            float v0 = acc[fi][fj][0] + b0;
            float v1 = acc[fi][fj][1] + b1;
            float v2 = acc[fi][fj][2] + b0;
            float v3 = acc[fi][fj][3] + b1;
            if (relu) {
                v0 = fmaxf(v0, 0.f); v1 = fmaxf(v1, 0.f);
                v2 = fmaxf(v2, 0.f); v3 = fmaxf(v3, 0.f);
            }
            if (Cf) {
                if (c0ok) {
                    Cf[(size_t)r0 * N + c0]       = v0;
                    Cf[(size_t)(r0 + 8) * N + c0] = v2;
                }
                if (c1ok) {
                    Cf[(size_t)r0 * N + c0 + 1]       = v1;
                    Cf[(size_t)(r0 + 8) * N + c0 + 1] = v3;
                }
            } else {
                if (c0ok) {
                    Coh[(size_t)r0 * N + c0]       = __float2half_rn(v0);
                    Coh[(size_t)(r0 + 8) * N + c0] = __float2half_rn(v2);
                }
                if (c1ok) {
                    Coh[(size_t)r0 * N + c0 + 1]       = __float2half_rn(v1);
                    Coh[(size_t)(r0 + 8) * N + c0 + 1] = __float2half_rn(v3);
                }
            }
        }
    }
}

// ---------------- embed ----------------
__global__ void embed_kernel(const int* __restrict__ q_data,
                             const int* __restrict__ target,
                             const float* __restrict__ pe,
                             const float* __restrict__ q_emb,
                             const float* __restrict__ qa_emb) {
    size_t idx = (size_t)blockIdx.x * blockDim.x + threadIdx.x;
    if (idx >= (size_t)Mr * Dc) return;
    int bs = (int)(idx / Dc);
    int d  = (int)(idx % Dc);
    int s  = bs % Sc;
    float qe = q_emb[(size_t)q_data[bs] * Dc + d];
    float p  = pe[(size_t)s * Dc + d];
    float x  = qe + p;
    float y  = qa_emb[(size_t)target[bs] * Dc + d] + qe + p;
    g_qe[idx] = qe;
    g_x [idx] = x;
    g_xh[idx] = __float2half_rn(x);
    g_yh[idx] = __float2half_rn(y);
}

// ---------------- flash attention (fp32 in, fp16 hi out) ----------------
__global__ __launch_bounds__(256)
void attn_kernel() {
    const int qt = blockIdx.x, hh = blockIdx.y, b = blockIdx.z;
    const int tid = threadIdx.x;
    const int r = tid >> 2;
    const int p = tid & 3;
    const int i = qt * 64 + r;
    const float scale = 0.125f;

    __shared__ float Kt[64][64];
    __shared__ float Vt[64][64];

    float q[16];
    {
        const float* qp = g_K + ((size_t)(b * Sc + i)) * Dc + hh * DKc + p * 16;
        #pragma unroll
        for (int w = 0; w < 4; w++) {
            float4 v = *(const float4*)(qp + w * 4);
            q[w * 4 + 0] = v.x; q[w * 4 + 1] = v.y;
            q[w * 4 + 2] = v.z; q[w * 4 + 3] = v.w;
        }
    }

    float m_run = -1e30f, l_run = 0.f;
    float o[16];
    #pragma unroll
    for (int d = 0; d < 16; d++) o[d] = 0.f;

    for (int jt = 0; jt <= qt; jt++) {
        const size_t base = ((size_t)(b * Sc + jt * 64 + r)) * Dc + hh * DKc + p * 16;
        #pragma unroll
        for (int w = 0; w < 4; w++) {
            *(float4*)&Kt[r][p * 16 + w * 4] = *(const float4*)(g_K + base + w * 4);
            *(float4*)&Vt[r][p * 16 + w * 4] = *(const float4*)(g_V + base + w * 4);
        }
        __syncthreads();

        for (int j = 0; j < 64; j++) {
            float s = 0.f;
            #pragma unroll
            for (int d = 0; d < 16; d++) s += q[d] * Kt[j][p * 16 + d];
            s += __shfl_xor_sync(0xffffffffu, s, 1);
            s += __shfl_xor_sync(0xffffffffu, s, 2);
            s *= scale;
            if (jt * 64 + j < i) {
                float m_new = fmaxf(m_run, s);
                float corr  = __expf(m_run - m_new);
                float pj    = __expf(s - m_new);
                l_run = l_run * corr + pj;
                #pragma unroll
                for (int d = 0; d < 16; d++)
                    o[d] = o[d] * corr + pj * Vt[j][p * 16 + d];
                m_run = m_new;
            }
        }
        __syncthreads();
    }

    float inv = (l_run > 0.f) ? (1.f / l_run) : 0.f;
    size_t ob = ((size_t)(b * Sc + i)) * Dc + hh * DKc + p * 16;
    #pragma unroll
    for (int d = 0; d < 16; d++)
        g_Oh[ob + d] = __float2half_rn(o[d] * inv);
}

// ---------------- fused add + LayerNorm (+ fp16 hi out) ----------------
__global__ __launch_bounds__(256)
void add_ln_kernel(float* __restrict__ x, const float* __restrict__ resid,
                   const float* __restrict__ g, const float* __restrict__ b) {
    const int row = blockIdx.x;
    const int tid = threadIdx.x;
    const size_t base = (size_t)row * Dc;
    float v0 = x[base + tid]       + resid[base + tid];
    float v1 = x[base + tid + 256] + resid[base + tid + 256];
    float s  = v0 + v1;
    float ss = v0 * v0 + v1 * v1;

    __shared__ float sbuf[8], ssbuf[8];
    #pragma unroll
    for (int o = 16; o > 0; o >>= 1) {
        s  += __shfl_xor_sync(0xffffffffu, s, o);
        ss += __shfl_xor_sync(0xffffffffu, ss, o);
    }
    if ((tid & 31) == 0) { sbuf[tid >> 5] = s; ssbuf[tid >> 5] = ss; }
    __syncthreads();
    if (tid < 32) {
        s  = (tid < 8) ? sbuf[tid]  : 0.f;
        ss = (tid < 8) ? ssbuf[tid] : 0.f;
        #pragma unroll
        for (int o = 4; o > 0; o >>= 1) {
            s  += __shfl_xor_sync(0xffffffffu, s, o);
            ss += __shfl_xor_sync(0xffffffffu, ss, o);
        }
        if (tid == 0) { sbuf[0] = s; ssbuf[0] = ss; }
    }
    __syncthreads();
    float mean = sbuf[0] * (1.f / 512.f);
    float var  = ssbuf[0] * (1.f / 512.f) - mean * mean;
    float rstd = rsqrtf(var + 1e-5f);
    float o0 = (v0 - mean) * rstd * g[tid]       + b[tid];
    float o1 = (v1 - mean) * rstd * g[tid + 256] + b[tid + 256];
    x[base + tid]       = o0;
    x[base + tid + 256] = o1;
    g_xh[base + tid]       = __float2half_rn(o0);
    g_xh[base + tid + 256] = __float2half_rn(o1);
}

// ---------------- concat [x | qe] -> fp16 hi ----------------
__global__ void concat_kernel() {
    size_t idx = (size_t)blockIdx.x * blockDim.x + threadIdx.x;
    if (idx >= (size_t)Mr * 2 * Dc) return;
    int bs = (int)(idx / (2 * Dc));
    int c  = (int)(idx % (2 * Dc));
    float v = (c < Dc) ? g_x[(size_t)bs * Dc + c]
                       : g_qe[(size_t)bs * Dc + (c - Dc)];
    g_Ch[idx] = __float2half_rn(v);
}

// ---------------- host ----------------
static inline void split_w(const float* W, __half* oh, __half* ol,
                           int K, int N, int Npad) {
    split_w_kernel<<<dim3(Npad / 32, K / 32), dim3(32, 8)>>>(W, oh, ol, K, N);
}
static inline void gemm1F32(const __half* ah, const __half* bh,
                            const float* bias, float* C, int K, int N, int Npad,
                            int relu) {
    gemm1_mma_kernel<<<dim3(Npad / 128, Mr / 128), 256, GEMM1_DSMEM>>>(
        ah, bh, bias, C, nullptr, K, N, relu);
}
static inline void gemm1F16(const __half* ah, const __half* bh,
                            const float* bias, __half* oh, int K, int N,
                            int Npad, int relu) {
    gemm1_mma_kernel<<<dim3(Npad / 128, Mr / 128), 256, GEMM1_DSMEM>>>(
        ah, bh, bias, nullptr, oh, K, N, relu);
}
static inline void gemm2F32(const __half* ah, const __half* bh, const __half* bl,
                            const float* bias, float* C, int K, int N, int Npad,
                            int relu) {
    gemm2_mma_kernel<<<dim3(Npad / 128, Mr / 128), 256, GEMM2_DSMEM>>>(
        ah, bh, bl, bias, C, nullptr, K, N, relu);
}
static inline void gemm2F16(const __half* ah, const __half* bh, const __half* bl,
                            const float* bias, __half* oh, int K, int N,
                            int Npad, int relu) {
    gemm2_mma_kernel<<<dim3(Npad / 128, Mr / 128), 256, GEMM2_DSMEM>>>(
        ah, bh, bl, bias, nullptr, oh, K, N, relu);
}

extern "C" void kernel_launch(void* const* d_in, const int* in_sizes, int n_in,
                              void* d_out, int out_size) {
    const int*   q_data = (const int*)d_in[0];
    const int*   target = (const int*)d_in[1];
    const float* pe     = (const float*)d_in[2];
    const float* q_emb  = (const float*)d_in[3];
    const float* qa_emb = (const float*)d_in[4];
    const float* Wk     = (const float*)d_in[5];
    const float* bk     = (const float*)d_in[6];
    const float* Wv     = (const float*)d_in[7];
    const float* bv     = (const float*)d_in[8];
    const float* Wo     = (const float*)d_in[9];
    const float* bo     = (const float*)d_in[10];
    const float* ln1_g  = (const float*)d_in[11];
    const float* ln1_b  = (const float*)d_in[12];
    const float* W1     = (const float*)d_in[13];
    const float* b1     = (const float*)d_in[14];
    const float* W2     = (const float*)d_in[15];
    const float* b2     = (const float*)d_in[16];
    const float* ln2_g  = (const float*)d_in[17];
    const float* ln2_b  = (const float*)d_in[18];
    const float* Wout1  = (const float*)d_in[19];
    const float* bout1  = (const float*)d_in[20];
    const float* Wout2  = (const float*)d_in[21];
    const float* bout2  = (const float*)d_in[22];
    const float* Wout3  = (const float*)d_in[23];
    const float* bout3  = (const float*)d_in[24];
    float* out = (float*)d_out;

    cudaFuncSetAttribute(gemm1_mma_kernel,
                         cudaFuncAttributeMaxDynamicSharedMemorySize, GEMM1_DSMEM);
    cudaFuncSetAttribute(gemm2_mma_kernel,
                         cudaFuncAttributeMaxDynamicSharedMemorySize, GEMM2_DSMEM);

    float *p_x, *p_K, *p_V, *p_P;
    cudaGetSymbolAddress((void**)&p_x, g_x);
    cudaGetSymbolAddress((void**)&p_K, g_K);
    cudaGetSymbolAddress((void**)&p_V, g_V);
    cudaGetSymbolAddress((void**)&p_P, g_P);

    __half *xh, *yh, *oh, *f1h, *ch, *h1h, *h2h;
    cudaGetSymbolAddress((void**)&xh, g_xh);
    cudaGetSymbolAddress((void**)&yh, g_yh);
    cudaGetSymbolAddress((void**)&oh, g_Oh);
    cudaGetSymbolAddress((void**)&f1h, g_F1h);
    cudaGetSymbolAddress((void**)&ch, g_Ch);
    cudaGetSymbolAddress((void**)&h1h, g_H1h);
    cudaGetSymbolAddress((void**)&h2h, g_H2h);

    __half *wk_h, *wv_h, *wo_h, *w1_h, *w2_h;
    __half *wo1_h, *wo1_l, *wo2_h, *wo2_l, *wo3_h, *wo3_l;
    cudaGetSymbolAddress((void**)&wk_h, g_Wk_h);
    cudaGetSymbolAddress((void**)&wv_h, g_Wv_h);
    cudaGetSymbolAddress((void**)&wo_h, g_Wo_h);
    cudaGetSymbolAddress((void**)&w1_h, g_W1_h);
    cudaGetSymbolAddress((void**)&w2_h, g_W2_h);
    cudaGetSymbolAddress((void**)&wo1_h, g_Wo1_h); cudaGetSymbolAddress((void**)&wo1_l, g_Wo1_l);
    cudaGetSymbolAddress((void**)&wo2_h, g_Wo2_h); cudaGetSymbolAddress((void**)&wo2_l, g_Wo2_l);
    cudaGetSymbolAddress((void**)&wo3_h, g_Wo3_h); cudaGetSymbolAddress((void**)&wo3_l, g_Wo3_l);

    // embed + weight prep
    {
        size_t tot = (size_t)Mr * Dc;
        embed_kernel<<<(unsigned)((tot + 255) / 256), 256>>>(q_data, target, pe,
                                                             q_emb, qa_emb);
    }
    for (int l = 0; l < Lc; l++) {
        size_t oDD = (size_t)l * Dc * Dc;
        size_t oDF = (size_t)l * Dc * DFFc;
        split_w(Wk + oDD, wk_h + oDD, nullptr, Dc, Dc, Dc);
        split_w(Wv + oDD, wv_h + oDD, nullptr, Dc, Dc, Dc);
        split_w(Wo + oDD, wo_h + oDD, nullptr, Dc, Dc, Dc);
        split_w(W1 + oDF, w1_h + oDF, nullptr, Dc, DFFc, DFFc);
        split_w(W2 + oDF, w2_h + oDF, nullptr, DFFc, Dc, Dc);
    }
    split_w(Wout1, wo1_h, wo1_l, 2 * Dc, FC1c, FC1c);
    split_w(Wout2, wo2_h, wo2_l, FC1c, FC2c, FC2c);
    split_w(Wout3, wo3_h, wo3_l, FC2c, NSKc, NSKp);

    // transformer layers (single-term hi-only GEMMs)
    for (int l = 0; l < Lc; l++) {
        size_t oDD = (size_t)l * Dc * Dc;
        size_t oDF = (size_t)l * Dc * DFFc;
        gemm1F32(xh, wk_h + oDD, bk + l * Dc, p_K, Dc, Dc, Dc, 0);
        gemm1F32(yh, wv_h + oDD, bv + l * Dc, p_V, Dc, Dc, Dc, 0);
        attn_kernel<<<dim3(Sc / 64, Hc, Bc), 256>>>();
        gemm1F32(oh, wo_h + oDD, bo + l * Dc, p_P, Dc, Dc, Dc, 0);
        add_ln_kernel<<<Mr, 256>>>(p_x, p_P, ln1_g + l * Dc, ln1_b + l * Dc);
        gemm1F16(xh, w1_h + oDF, b1 + l * DFFc, f1h, Dc, DFFc, DFFc, 1);
        gemm1F32(f1h, w2_h + oDF, b2 + l * Dc, p_P, DFFc, Dc, Dc, 0);
        add_ln_kernel<<<Mr, 256>>>(p_x, p_P, ln2_g + l * Dc, ln2_b + l * Dc);
    }

    // head (two-term)
    {
        size_t tot = (size_t)Mr * 2 * Dc;
        concat_kernel<<<(unsigned)((tot + 255) / 256), 256>>>();
    }
    gemm2F16(ch, wo1_h, wo1_l, bout1, h1h, 2 * Dc, FC1c, FC1c, 1);
    gemm2F16(h1h, wo2_h, wo2_l, bout2, h2h, FC1c, FC2c, FC2c, 1);
    gemm2F32(h2h, wo3_h, wo3_l, bout3, out, FC2c, NSKc, NSKp, 0);
}

// round 14
// speedup vs baseline: 1.1246x; 1.0873x over previous
#include <cuda_runtime.h>
#include <cuda_fp16.h>
#include <math.h>
#include <stdint.h>

#define Bc   64
#define Sc   512
#define Dc   512
#define Hc   8
#define DKc  64
#define Lc   4
#define DFFc 2048
#define NSKc 300
#define NSKp 384
#define FC1c 512
#define FC2c 256
#define Mr   (Bc * Sc)

// ---------------- fp32 scratch ----------------
__device__ float g_qe[(size_t)Mr * Dc];
__device__ float g_x [(size_t)Mr * Dc];
__device__ float g_K [(size_t)Mr * Dc];
__device__ float g_V [(size_t)Mr * Dc];
__device__ float g_P [(size_t)Mr * Dc];

// ---------------- fp16 activations (hi only) ----------------
__device__ __half g_xh [(size_t)Mr * Dc];
__device__ __half g_yh [(size_t)Mr * Dc];
__device__ __half g_Oh [(size_t)Mr * Dc];
__device__ __half g_F1h[(size_t)Mr * DFFc];
__device__ __half g_Ch [(size_t)Mr * 2 * Dc];
__device__ __half g_H1h[(size_t)Mr * FC1c];
__device__ __half g_H2h[(size_t)Mr * FC2c];

// ---------------- fp16 weights (transposed [N][K]) ----------------
__device__ __half g_Wk_h[(size_t)Lc * Dc * Dc];
__device__ __half g_Wv_h[(size_t)Lc * Dc * Dc];
__device__ __half g_Wo_h[(size_t)Lc * Dc * Dc];
__device__ __half g_W1_h[(size_t)Lc * Dc * DFFc];
__device__ __half g_W2_h[(size_t)Lc * DFFc * Dc];
__device__ __half g_Wo1_h[(size_t)2 * Dc * FC1c], g_Wo1_l[(size_t)2 * Dc * FC1c];
__device__ __half g_Wo2_h[(size_t)FC1c * FC2c],   g_Wo2_l[(size_t)FC1c * FC2c];
__device__ __half g_Wo3_h[(size_t)NSKp * FC2c],   g_Wo3_l[(size_t)NSKp * FC2c];

// ---------------- helpers ----------------
__device__ __forceinline__ uint32_t smem_u32(const void* p) {
    uint32_t a;
    asm("{ .reg .u64 t; cvta.to.shared.u64 t, %1; cvt.u32.u64 %0, t; }"
        : "=r"(a) : "l"(p));
    return a;
}
__device__ __forceinline__ void split2(float v, __half& h, __half& l) {
    h = __float2half_rn(v);
    l = __float2half_rn(v - __half2float(h));
}

#define CPA16(dst, src)                                                       \
    asm volatile("cp.async.cg.shared.global [%0], [%1], 16;"                  \
                 :: "r"(dst), "l"(src) : "memory")

#define LDMX4(R, addr)                                                        \
    asm volatile("ldmatrix.sync.aligned.m8n8.x4.shared.b16 {%0,%1,%2,%3}, [%4];" \
        : "=r"((R)[0]), "=r"((R)[1]), "=r"((R)[2]), "=r"((R)[3]) : "r"(addr))

#define LDMX2(R, addr)                                                        \
    asm volatile("ldmatrix.sync.aligned.m8n8.x2.shared.b16 {%0,%1}, [%2];"    \
        : "=r"((R)[0]), "=r"((R)[1]) : "r"(addr))

#define MMA16816(d, a, b)                                                     \
    asm volatile("mma.sync.aligned.m16n8k16.row.col.f32.f16.f16.f32 "         \
        "{%0,%1,%2,%3}, {%4,%5,%6,%7}, {%8,%9}, {%0,%1,%2,%3};"               \
        : "+f"((d)[0]), "+f"((d)[1]), "+f"((d)[2]), "+f"((d)[3])              \
        : "r"((a)[0]), "r"((a)[1]), "r"((a)[2]), "r"((a)[3]),                 \
          "r"((b)[0]), "r"((b)[1]))

// ---------------- weight prep: transpose + hi/lo split ----------------
__global__ void split_w_kernel(const float* __restrict__ W,
                               __half* __restrict__ Oh, __half* __restrict__ Ol,
                               int K, int N) {
    __shared__ float t[32][33];
    int k0 = blockIdx.y * 32, n0 = blockIdx.x * 32;
    #pragma unroll
    for (int i = 0; i < 4; i++) {
        int k = k0 + threadIdx.y + i * 8;
        int n = n0 + threadIdx.x;
        t[threadIdx.y + i * 8][threadIdx.x] = (n < N) ? W[(size_t)k * N + n] : 0.f;
    }
    __syncthreads();
    #pragma unroll
    for (int i = 0; i < 4; i++) {
        int n = n0 + threadIdx.y + i * 8;
        int k = k0 + threadIdx.x;
        float v = t[threadIdx.x][threadIdx.y + i * 8];
        __half h, l; split2(v, h, l);
        Oh[(size_t)n * K + k] = h;
        if (Ol) Ol[(size_t)n * K + k] = l;
    }
}

// BK = 64: rows of 64 halfs (128 B) + 16 B pad -> APITCH 72 halfs (144 B)
#define APITCH 72
#define TILE_B (128 * APITCH * 2)     // 18432

// ---- shared epilogue (writes fp32 C or fp16 Coh) ----
__device__ __forceinline__ void gemm_epilogue(
    float acc[4][4][4], const float* bias, float* Cf, __half* Coh,
    int m0, int n0, int warp_m, int warp_n, int lane, int N, int relu) {
    #pragma unroll
    for (int fj = 0; fj < 4; fj++) {
        const int c0 = n0 + warp_n + fj * 8 + 2 * (lane & 3);
        const bool c0ok = (c0 < N), c1ok = (c0 + 1 < N);
        const float b0 = c0ok ? bias[c0] : 0.f;
        const float b1 = c1ok ? bias[c0 + 1] : 0.f;
        #pragma unroll
        for (int fi = 0; fi < 4; fi++) {
            const int r0 = m0 + warp_m + fi * 16 + (lane >> 2);
            float v0 = acc[fi][fj][0] + b0;
            float v1 = acc[fi][fj][1] + b1;
            float v2 = acc[fi][fj][2] + b0;
            float v3 = acc[fi][fj][3] + b1;
            if (relu) {
                v0 = fmaxf(v0, 0.f); v1 = fmaxf(v1, 0.f);
                v2 = fmaxf(v2, 0.f); v3 = fmaxf(v3, 0.f);
            }
            if (Cf) {
                if (c1ok) {  // c0 even -> float2 aligned
                    *(float2*)(Cf + (size_t)r0 * N + c0)       = make_float2(v0, v1);
                    *(float2*)(Cf + (size_t)(r0 + 8) * N + c0) = make_float2(v2, v3);
                } else if (c0ok) {
                    Cf[(size_t)r0 * N + c0]       = v0;
                    Cf[(size_t)(r0 + 8) * N + c0] = v2;
                }
            } else {
                if (c1ok) {
                    *(__half2*)(Coh + (size_t)r0 * N + c0) =
                        __halves2half2(__float2half_rn(v0), __float2half_rn(v1));
                    *(__half2*)(Coh + (size_t)(r0 + 8) * N + c0) =
                        __halves2half2(__float2half_rn(v2), __float2half_rn(v3));
                } else if (c0ok) {
                    Coh[(size_t)r0 * N + c0]       = __float2half_rn(v0);
                    Coh[(size_t)(r0 + 8) * N + c0] = __float2half_rn(v2);
                }
            }
        }
    }
}

// ================= 1-term GEMM: C = Ah @ Bh + bias (layer GEMMs) ============
#define STAGE1_B (2 * TILE_B)         // 36864
#define GEMM1_DSMEM (2 * STAGE1_B)    // 73728

__device__ __forceinline__ void issue_stage1(
    uint32_t sb, const __half* Ah_g, const __half* Bh_g,
    int m0, int n0, int K, int kk, int tid) {
    #pragma unroll
    for (int p = 0; p < 4; p++) {
        int c = p * 256 + tid;
        int row = c >> 3, q = c & 7;
        uint32_t d = sb + (uint32_t)(row * 144 + q * 16);
        size_t ao = (size_t)(m0 + row) * K + kk + q * 8;
        size_t bo = (size_t)(n0 + row) * K + kk + q * 8;
        CPA16(d,          Ah_g + ao);
        CPA16(d + TILE_B, Bh_g + bo);
    }
    asm volatile("cp.async.commit_group;" ::: "memory");
}

__global__ __launch_bounds__(256, 2)
void gemm1_mma_kernel(const __half* __restrict__ Ah_g,
                      const __half* __restrict__ Bh_g,
                      const float* __restrict__ bias,
                      float* __restrict__ Cf,
                      __half* __restrict__ Coh,
                      int K, int N, int relu) {
    extern __shared__ char smem[];
    const int tid  = threadIdx.x;
    const int wid  = tid >> 5;
    const int lane = tid & 31;
    const int m0 = blockIdx.y * 128;
    const int n0 = blockIdx.x * 128;
    const int warp_m = (wid >> 2) * 64;
    const int warp_n = (wid & 3) * 32;

    const uint32_t sbase = smem_u32(smem);

    float acc[4][4][4];
    #pragma unroll
    for (int i = 0; i < 4; i++)
        #pragma unroll
        for (int j = 0; j < 4; j++)
            #pragma unroll
            for (int e = 0; e < 4; e++) acc[i][j][e] = 0.f;

    const int KT = K >> 6;
    const int r8  = lane & 7;
    const int sub = lane >> 3;
    const uint32_t a_lane_off =
        (uint32_t)(((warp_m + r8 + (sub & 1) * 8) * APITCH + (sub >> 1) * 8) * 2);
    const uint32_t b_lane_off =
        (uint32_t)(((warp_n + r8) * APITCH + (sub & 1) * 8) * 2);

    issue_stage1(sbase, Ah_g, Bh_g, m0, n0, K, 0, tid);

    for (int kt = 0; kt < KT; kt++) {
        asm volatile("cp.async.wait_group 0;" ::: "memory");
        __syncthreads();
        if (kt + 1 < KT)
            issue_stage1(sbase + ((kt + 1) & 1) * STAGE1_B, Ah_g, Bh_g,
                         m0, n0, K, (kt + 1) << 6, tid);

        const uint32_t stoff = (kt & 1) * STAGE1_B;
        const uint32_t abase = sbase + stoff + a_lane_off;
        const uint32_t bbase = sbase + stoff + TILE_B + b_lane_off;

        #pragma unroll
        for (int ks = 0; ks < 4; ks++) {
            const uint32_t ak = abase + ks * 32;
            const uint32_t bk = bbase + ks * 32;

            uint32_t Ahf[4][4], Bhf[4][2];
            #pragma unroll
            for (int fi = 0; fi < 4; fi++)
                LDMX4(Ahf[fi], ak + fi * (16 * APITCH * 2));
            #pragma unroll
            for (int fj = 0; fj < 4; fj++)
                LDMX2(Bhf[fj], bk + fj * (8 * APITCH * 2));
            #pragma unroll
            for (int fi = 0; fi < 4; fi++)
                #pragma unroll
                for (int fj = 0; fj < 4; fj++)
                    MMA16816(acc[fi][fj], Ahf[fi], Bhf[fj]);
        }
    }

    gemm_epilogue(acc, bias, Cf, Coh, m0, n0, warp_m, warp_n, lane, N, relu);
}

// ================= 2-term GEMM: C = Ah @ (Bh + Bl) + bias (head) ============
#define STAGE2_B (3 * TILE_B)         // 55296
#define GEMM2_DSMEM (2 * STAGE2_B)    // 110592

__device__ __forceinline__ void issue_stage2(
    uint32_t sb, const __half* Ah_g, const __half* Bh_g, const __half* Bl_g,
    int m0, int n0, int K, int kk, int tid) {
    #pragma unroll
    for (int p = 0; p < 4; p++) {
        int c = p * 256 + tid;
        int row = c >> 3, q = c & 7;
        uint32_t d = sb + (uint32_t)(row * 144 + q * 16);
        size_t ao = (size_t)(m0 + row) * K + kk + q * 8;
        size_t bo = (size_t)(n0 + row) * K + kk + q * 8;
        CPA16(d,              Ah_g + ao);
        CPA16(d + TILE_B,     Bh_g + bo);
        CPA16(d + 2 * TILE_B, Bl_g + bo);
    }
    asm volatile("cp.async.commit_group;" ::: "memory");
}

__global__ __launch_bounds__(256, 2)
void gemm2_mma_kernel(const __half* __restrict__ Ah_g,
                      const __half* __restrict__ Bh_g,
                      const __half* __restrict__ Bl_g,
                      const float* __restrict__ bias,
                      float* __restrict__ Cf,
                      __half* __restrict__ Coh,
                      int K, int N, int relu) {
    extern __shared__ char smem[];
    const int tid  = threadIdx.x;
    const int wid  = tid >> 5;
    const int lane = tid & 31;
    const int m0 = blockIdx.y * 128;
    const int n0 = blockIdx.x * 128;
    const int warp_m = (wid >> 2) * 64;
    const int warp_n = (wid & 3) * 32;

    const uint32_t sbase = smem_u32(smem);

    float acc[4][4][4];
    #pragma unroll
    for (int i = 0; i < 4; i++)
        #pragma unroll
        for (int j = 0; j < 4; j++)
            #pragma unroll
            for (int e = 0; e < 4; e++) acc[i][j][e] = 0.f;

    const int KT = K >> 6;
    const int r8  = lane & 7;
    const int sub = lane >> 3;
    const uint32_t a_lane_off =
        (uint32_t)(((warp_m + r8 + (sub & 1) * 8) * APITCH + (sub >> 1) * 8) * 2);
    const uint32_t b_lane_off =
        (uint32_t)(((warp_n + r8) * APITCH + (sub & 1) * 8) * 2);

    issue_stage2(sbase, Ah_g, Bh_g, Bl_g, m0, n0, K, 0, tid);

    for (int kt = 0; kt < KT; kt++) {
        asm volatile("cp.async.wait_group 0;" ::: "memory");
        __syncthreads();
        if (kt + 1 < KT)
            issue_stage2(sbase + ((kt + 1) & 1) * STAGE2_B, Ah_g, Bh_g, Bl_g,
                         m0, n0, K, (kt + 1) << 6, tid);

        const uint32_t stoff = (kt & 1) * STAGE2_B;
        const uint32_t abase = sbase + stoff + a_lane_off;
        const uint32_t bbase = sbase + stoff + TILE_B + b_lane_off;

        #pragma unroll
        for (int ks = 0; ks < 4; ks++) {
            const uint32_t ak = abase + ks * 32;
            const uint32_t bk = bbase + ks * 32;

            uint32_t Ahf[4][4], Bhf[4][2], Blf[4][2];
            #pragma unroll
            for (int fi = 0; fi < 4; fi++)
                LDMX4(Ahf[fi], ak + fi * (16 * APITCH * 2));
            #pragma unroll
            for (int fj = 0; fj < 4; fj++)
                LDMX2(Bhf[fj], bk + fj * (8 * APITCH * 2));
            #pragma unroll
            for (int fi = 0; fi < 4; fi++)
                #pragma unroll
                for (int fj = 0; fj < 4; fj++)
                    MMA16816(acc[fi][fj], Ahf[fi], Bhf[fj]);

            #pragma unroll
            for (int fj = 0; fj < 4; fj++)
                LDMX2(Blf[fj], bk + TILE_B + fj * (8 * APITCH * 2));
            #pragma unroll
            for (int fi = 0; fi < 4; fi++)
                #pragma unroll
                for (int fj = 0; fj < 4; fj++)
                    MMA16816(acc[fi][fj], Ahf[fi], Blf[fj]);
        }
    }

    gemm_epilogue(acc, bias, Cf, Coh, m0, n0, warp_m, warp_n, lane, N, relu);
}

// ---------------- embed ----------------
__global__ void embed_kernel(const int* __restrict__ q_data,
                             const int* __restrict__ target,
                             const float* __restrict__ pe,
                             const float* __restrict__ q_emb,
                             const float* __restrict__ qa_emb) {
    size_t idx = (size_t)blockIdx.x * blockDim.x + threadIdx.x;
    if (idx >= (size_t)Mr * Dc) return;
    int bs = (int)(idx / Dc);
    int d  = (int)(idx % Dc);
    int s  = bs % Sc;
    float qe = q_emb[(size_t)q_data[bs] * Dc + d];
    float p  = pe[(size_t)s * Dc + d];
    float x  = qe + p;
    float y  = qa_emb[(size_t)target[bs] * Dc + d] + qe + p;
    g_qe[idx] = qe;
    g_x [idx] = x;
    g_xh[idx] = __float2half_rn(x);
    g_yh[idx] = __float2half_rn(y);
}

// ---------------- flash attention (deferred-rescale softmax) ----------------
__global__ __launch_bounds__(256)
void attn_kernel() {
    const int qt = blockIdx.x, hh = blockIdx.y, b = blockIdx.z;
    const int tid = threadIdx.x;
    const int r = tid >> 2;
    const int p = tid & 3;
    const int i = qt * 64 + r;
    const float scale = 0.125f;

    __shared__ float Kt[64][64];
    __shared__ float Vt[64][64];

    float q[16];
    {
        const float* qp = g_K + ((size_t)(b * Sc + i)) * Dc + hh * DKc + p * 16;
        #pragma unroll
        for (int w = 0; w < 4; w++) {
            float4 v = *(const float4*)(qp + w * 4);
            q[w * 4 + 0] = v.x; q[w * 4 + 1] = v.y;
            q[w * 4 + 2] = v.z; q[w * 4 + 3] = v.w;
        }
    }

    float m_run = -1e30f, l_run = 0.f;
    float o[16];
    #pragma unroll
    for (int d = 0; d < 16; d++) o[d] = 0.f;

    for (int jt = 0; jt <= qt; jt++) {
        const size_t base = ((size_t)(b * Sc + jt * 64 + r)) * Dc + hh * DKc + p * 16;
        #pragma unroll
        for (int w = 0; w < 4; w++) {
            *(float4*)&Kt[r][p * 16 + w * 4] = *(const float4*)(g_K + base + w * 4);
            *(float4*)&Vt[r][p * 16 + w * 4] = *(const float4*)(g_V + base + w * 4);
        }
        __syncthreads();

        // warp-uniform loop bound: diagonal tile needs only j < max row in warp
        const int jlim = (jt == qt) ? (r | 7) : 64;
        for (int j = 0; j < jlim; j++) {
            float s = 0.f;
            #pragma unroll
            for (int d = 0; d < 16; d++) s += q[d] * Kt[j][p * 16 + d];
            s += __shfl_xor_sync(0xffffffffu, s, 1);
            s += __shfl_xor_sync(0xffffffffu, s, 2);
            s *= scale;
            if (jt * 64 + j < i) {
                if (s <= m_run) {
                    float pj = __expf(s - m_run);
                    l_run += pj;
                    #pragma unroll
                    for (int d = 0; d < 16; d++)
                        o[d] = fmaf(pj, Vt[j][p * 16 + d], o[d]);
                } else {
                    float corr = __expf(m_run - s);
                    m_run = s;
                    l_run = fmaf(l_run, corr, 1.f);
                    #pragma unroll
                    for (int d = 0; d < 16; d++)
                        o[d] = fmaf(o[d], corr, Vt[j][p * 16 + d]);
                }
            }
        }
        __syncthreads();
    }

    float inv = (l_run > 0.f) ? (1.f / l_run) : 0.f;
    size_t ob = ((size_t)(b * Sc + i)) * Dc + hh * DKc + p * 16;
    #pragma unroll
    for (int d = 0; d < 16; d++)
        g_Oh[ob + d] = __float2half_rn(o[d] * inv);
}

// ---------------- fused add + LayerNorm (+ fp16 hi out) ----------------
__global__ __launch_bounds__(256)
void add_ln_kernel(float* __restrict__ x, const float* __restrict__ resid,
                   const float* __restrict__ g, const float* __restrict__ b) {
    const int row = blockIdx.x;
    const int tid = threadIdx.x;
    const size_t base = (size_t)row * Dc;
    float v0 = x[base + tid]       + resid[base + tid];
    float v1 = x[base + tid + 256] + resid[base + tid + 256];
    float s  = v0 + v1;
    float ss = v0 * v0 + v1 * v1;

    __shared__ float sbuf[8], ssbuf[8];
    #pragma unroll
    for (int o = 16; o > 0; o >>= 1) {
        s  += __shfl_xor_sync(0xffffffffu, s, o);
        ss += __shfl_xor_sync(0xffffffffu, ss, o);
    }
    if ((tid & 31) == 0) { sbuf[tid >> 5] = s; ssbuf[tid >> 5] = ss; }
    __syncthreads();
    if (tid < 32) {
        s  = (tid < 8) ? sbuf[tid]  : 0.f;
        ss = (tid < 8) ? ssbuf[tid] : 0.f;
        #pragma unroll
        for (int o = 4; o > 0; o >>= 1) {
            s  += __shfl_xor_sync(0xffffffffu, s, o);
            ss += __shfl_xor_sync(0xffffffffu, ss, o);
        }
        if (tid == 0) { sbuf[0] = s; ssbuf[0] = ss; }
    }
    __syncthreads();
    float mean = sbuf[0] * (1.f / 512.f);
    float var  = ssbuf[0] * (1.f / 512.f) - mean * mean;
    float rstd = rsqrtf(var + 1e-5f);
    float o0 = (v0 - mean) * rstd * g[tid]       + b[tid];
    float o1 = (v1 - mean) * rstd * g[tid + 256] + b[tid + 256];
    x[base + tid]       = o0;
    x[base + tid + 256] = o1;
    g_xh[base + tid]       = __float2half_rn(o0);
    g_xh[base + tid + 256] = __float2half_rn(o1);
}

// ---------------- concat [x | qe] -> fp16 hi ----------------
__global__ void concat_kernel() {
    size_t idx = (size_t)blockIdx.x * blockDim.x + threadIdx.x;
    if (idx >= (size_t)Mr * 2 * Dc) return;
    int bs = (int)(idx / (2 * Dc));
    int c  = (int)(idx % (2 * Dc));
    float v = (c < Dc) ? g_x[(size_t)bs * Dc + c]
                       : g_qe[(size_t)bs * Dc + (c - Dc)];
    g_Ch[idx] = __float2half_rn(v);
}

// ---------------- host ----------------
static inline void split_w(const float* W, __half* oh, __half* ol,
                           int K, int N, int Npad) {
    split_w_kernel<<<dim3(Npad / 32, K / 32), dim3(32, 8)>>>(W, oh, ol, K, N);
}
static inline void gemm1F32(const __half* ah, const __half* bh,
                            const float* bias, float* C, int K, int N, int Npad,
                            int relu) {
    gemm1_mma_kernel<<<dim3(Npad / 128, Mr / 128), 256, GEMM1_DSMEM>>>(
        ah, bh, bias, C, nullptr, K, N, relu);
}
static inline void gemm1F16(const __half* ah, const __half* bh,
                            const float* bias, __half* oh, int K, int N,
                            int Npad, int relu) {
    gemm1_mma_kernel<<<dim3(Npad / 128, Mr / 128), 256, GEMM1_DSMEM>>>(
        ah, bh, bias, nullptr, oh, K, N, relu);
}
static inline void gemm2F32(const __half* ah, const __half* bh, const __half* bl,
                            const float* bias, float* C, int K, int N, int Npad,
                            int relu) {
    gemm2_mma_kernel<<<dim3(Npad / 128, Mr / 128), 256, GEMM2_DSMEM>>>(
        ah, bh, bl, bias, C, nullptr, K, N, relu);
}
static inline void gemm2F16(const __half* ah, const __half* bh, const __half* bl,
                            const float* bias, __half* oh, int K, int N,
                            int Npad, int relu) {
    gemm2_mma_kernel<<<dim3(Npad / 128, Mr / 128), 256, GEMM2_DSMEM>>>(
        ah, bh, bl, bias, nullptr, oh, K, N, relu);
}

extern "C" void kernel_launch(void* const* d_in, const int* in_sizes, int n_in,
                              void* d_out, int out_size) {
    const int*   q_data = (const int*)d_in[0];
    const int*   target = (const int*)d_in[1];
    const float* pe     = (const float*)d_in[2];
    const float* q_emb  = (const float*)d_in[3];
    const float* qa_emb = (const float*)d_in[4];
    const float* Wk     = (const float*)d_in[5];
    const float* bk     = (const float*)d_in[6];
    const float* Wv     = (const float*)d_in[7];
    const float* bv     = (const float*)d_in[8];
    const float* Wo     = (const float*)d_in[9];
    const float* bo     = (const float*)d_in[10];
    const float* ln1_g  = (const float*)d_in[11];
    const float* ln1_b  = (const float*)d_in[12];
    const float* W1     = (const float*)d_in[13];
    const float* b1     = (const float*)d_in[14];
    const float* W2     = (const float*)d_in[15];
    const float* b2     = (const float*)d_in[16];
    const float* ln2_g  = (const float*)d_in[17];
    const float* ln2_b  = (const float*)d_in[18];
    const float* Wout1  = (const float*)d_in[19];
    const float* bout1  = (const float*)d_in[20];
    const float* Wout2  = (const float*)d_in[21];
    const float* bout2  = (const float*)d_in[22];
    const float* Wout3  = (const float*)d_in[23];
    const float* bout3  = (const float*)d_in[24];
    float* out = (float*)d_out;

    cudaFuncSetAttribute(gemm1_mma_kernel,
                         cudaFuncAttributeMaxDynamicSharedMemorySize, GEMM1_DSMEM);
    cudaFuncSetAttribute(gemm2_mma_kernel,
                         cudaFuncAttributeMaxDynamicSharedMemorySize, GEMM2_DSMEM);

    float *p_x, *p_K, *p_V, *p_P;
    cudaGetSymbolAddress((void**)&p_x, g_x);
    cudaGetSymbolAddress((void**)&p_K, g_K);
    cudaGetSymbolAddress((void**)&p_V, g_V);
    cudaGetSymbolAddress((void**)&p_P, g_P);

    __half *xh, *yh, *oh, *f1h, *ch, *h1h, *h2h;
    cudaGetSymbolAddress((void**)&xh, g_xh);
    cudaGetSymbolAddress((void**)&yh, g_yh);
    cudaGetSymbolAddress((void**)&oh, g_Oh);
    cudaGetSymbolAddress((void**)&f1h, g_F1h);
    cudaGetSymbolAddress((void**)&ch, g_Ch);
    cudaGetSymbolAddress((void**)&h1h, g_H1h);
    cudaGetSymbolAddress((void**)&h2h, g_H2h);

    __half *wk_h, *wv_h, *wo_h, *w1_h, *w2_h;
    __half *wo1_h, *wo1_l, *wo2_h, *wo2_l, *wo3_h, *wo3_l;
    cudaGetSymbolAddress((void**)&wk_h, g_Wk_h);
    cudaGetSymbolAddress((void**)&wv_h, g_Wv_h);
    cudaGetSymbolAddress((void**)&wo_h, g_Wo_h);
    cudaGetSymbolAddress((void**)&w1_h, g_W1_h);
    cudaGetSymbolAddress((void**)&w2_h, g_W2_h);
    cudaGetSymbolAddress((void**)&wo1_h, g_Wo1_h); cudaGetSymbolAddress((void**)&wo1_l, g_Wo1_l);
    cudaGetSymbolAddress((void**)&wo2_h, g_Wo2_h); cudaGetSymbolAddress((void**)&wo2_l, g_Wo2_l);
    cudaGetSymbolAddress((void**)&wo3_h, g_Wo3_h); cudaGetSymbolAddress((void**)&wo3_l, g_Wo3_l);

    // embed + weight prep
    {
        size_t tot = (size_t)Mr * Dc;
        embed_kernel<<<(unsigned)((tot + 255) / 256), 256>>>(q_data, target, pe,
                                                             q_emb, qa_emb);
    }
    for (int l = 0; l < Lc; l++) {
        size_t oDD = (size_t)l * Dc * Dc;
        size_t oDF = (size_t)l * Dc * DFFc;
        split_w(Wk + oDD, wk_h + oDD, nullptr, Dc, Dc, Dc);
        split_w(Wv + oDD, wv_h + oDD, nullptr, Dc, Dc, Dc);
        split_w(Wo + oDD, wo_h + oDD, nullptr, Dc, Dc, Dc);
        split_w(W1 + oDF, w1_h + oDF, nullptr, Dc, DFFc, DFFc);
        split_w(W2 + oDF, w2_h + oDF, nullptr, DFFc, Dc, Dc);
    }
    split_w(Wout1, wo1_h, wo1_l, 2 * Dc, FC1c, FC1c);
    split_w(Wout2, wo2_h, wo2_l, FC1c, FC2c, FC2c);
    split_w(Wout3, wo3_h, wo3_l, FC2c, NSKc, NSKp);

    // transformer layers
    for (int l = 0; l < Lc; l++) {
        size_t oDD = (size_t)l * Dc * Dc;
        size_t oDF = (size_t)l * Dc * DFFc;
        gemm1F32(xh, wk_h + oDD, bk + l * Dc, p_K, Dc, Dc, Dc, 0);
        gemm1F32(yh, wv_h + oDD, bv + l * Dc, p_V, Dc, Dc, Dc, 0);
        attn_kernel<<<dim3(Sc / 64, Hc, Bc), 256>>>();
        gemm1F32(oh, wo_h + oDD, bo + l * Dc, p_P, Dc, Dc, Dc, 0);
        add_ln_kernel<<<Mr, 256>>>(p_x, p_P, ln1_g + l * Dc, ln1_b + l * Dc);
        gemm1F16(xh, w1_h + oDF, b1 + l * DFFc, f1h, Dc, DFFc, DFFc, 1);
        gemm1F32(f1h, w2_h + oDF, b2 + l * Dc, p_P, DFFc, Dc, Dc, 0);
        add_ln_kernel<<<Mr, 256>>>(p_x, p_P, ln2_g + l * Dc, ln2_b + l * Dc);
    }

    // head
    {
        size_t tot = (size_t)Mr * 2 * Dc;
        concat_kernel<<<(unsigned)((tot + 255) / 256), 256>>>();
    }
    gemm2F16(ch, wo1_h, wo1_l, bout1, h1h, 2 * Dc, FC1c, FC1c, 1);
    gemm2F16(h1h, wo2_h, wo2_l, bout2, h2h, FC1c, FC2c, FC2c, 1);
    gemm2F32(h2h, wo3_h, wo3_l, bout3, out, FC2c, NSKc, NSKp, 0);
}

// round 15
// speedup vs baseline: 3.7697x; 3.3522x over previous
#include <cuda_runtime.h>
#include <cuda_fp16.h>
#include <math.h>
#include <stdint.h>

#define Bc   64
#define Sc   512
#define Dc   512
#define Hc   8
#define DKc  64
#define Lc   4
#define DFFc 2048
#define NSKc 300
#define NSKp 384
#define FC1c 512
#define FC2c 256
#define Mr   (Bc * Sc)

// ---------------- fp32 scratch ----------------
__device__ float g_qe[(size_t)Mr * Dc];
__device__ float g_x [(size_t)Mr * Dc];
__device__ float g_P [(size_t)Mr * Dc];

// ---------------- fp16 activations (hi only) ----------------
__device__ __half g_xh [(size_t)Mr * Dc];
__device__ __half g_yh [(size_t)Mr * Dc];
__device__ __half g_Kh [(size_t)Mr * Dc];
__device__ __half g_Vh [(size_t)Mr * Dc];
__device__ __half g_Oh [(size_t)Mr * Dc];
__device__ __half g_F1h[(size_t)Mr * DFFc];
__device__ __half g_Ch [(size_t)Mr * 2 * Dc];
__device__ __half g_H1h[(size_t)Mr * FC1c];
__device__ __half g_H2h[(size_t)Mr * FC2c];

// ---------------- fp16 weights (transposed [N][K]) ----------------
__device__ __half g_Wk_h[(size_t)Lc * Dc * Dc];
__device__ __half g_Wv_h[(size_t)Lc * Dc * Dc];
__device__ __half g_Wo_h[(size_t)Lc * Dc * Dc];
__device__ __half g_W1_h[(size_t)Lc * Dc * DFFc];
__device__ __half g_W2_h[(size_t)Lc * DFFc * Dc];
__device__ __half g_Wo1_h[(size_t)2 * Dc * FC1c], g_Wo1_l[(size_t)2 * Dc * FC1c];
__device__ __half g_Wo2_h[(size_t)FC1c * FC2c],   g_Wo2_l[(size_t)FC1c * FC2c];
__device__ __half g_Wo3_h[(size_t)NSKp * FC2c],   g_Wo3_l[(size_t)NSKp * FC2c];

// ---------------- helpers ----------------
__device__ __forceinline__ uint32_t smem_u32(const void* p) {
    uint32_t a;
    asm("{ .reg .u64 t; cvta.to.shared.u64 t, %1; cvt.u32.u64 %0, t; }"
        : "=r"(a) : "l"(p));
    return a;
}
__device__ __forceinline__ void split2(float v, __half& h, __half& l) {
    h = __float2half_rn(v);
    l = __float2half_rn(v - __half2float(h));
}

#define CPA16(dst, src)                                                       \
    asm volatile("cp.async.cg.shared.global [%0], [%1], 16;"                  \
                 :: "r"(dst), "l"(src) : "memory")

#define LDMX4(R, addr)                                                        \
    asm volatile("ldmatrix.sync.aligned.m8n8.x4.shared.b16 {%0,%1,%2,%3}, [%4];" \
        : "=r"((R)[0]), "=r"((R)[1]), "=r"((R)[2]), "=r"((R)[3]) : "r"(addr))

#define LDMX4T(R, addr)                                                       \
    asm volatile("ldmatrix.sync.aligned.m8n8.x4.trans.shared.b16 {%0,%1,%2,%3}, [%4];" \
        : "=r"((R)[0]), "=r"((R)[1]), "=r"((R)[2]), "=r"((R)[3]) : "r"(addr))

#define LDMX2(R, addr)                                                        \
    asm volatile("ldmatrix.sync.aligned.m8n8.x2.shared.b16 {%0,%1}, [%2];"    \
        : "=r"((R)[0]), "=r"((R)[1]) : "r"(addr))

#define MMA16816(d, a, b)                                                     \
    asm volatile("mma.sync.aligned.m16n8k16.row.col.f32.f16.f16.f32 "         \
        "{%0,%1,%2,%3}, {%4,%5,%6,%7}, {%8,%9}, {%0,%1,%2,%3};"               \
        : "+f"((d)[0]), "+f"((d)[1]), "+f"((d)[2]), "+f"((d)[3])              \
        : "r"((a)[0]), "r"((a)[1]), "r"((a)[2]), "r"((a)[3]),                 \
          "r"((b)[0]), "r"((b)[1]))

// ---------------- weight prep: transpose + hi/lo split ----------------
__global__ void split_w_kernel(const float* __restrict__ W,
                               __half* __restrict__ Oh, __half* __restrict__ Ol,
                               int K, int N) {
    __shared__ float t[32][33];
    int k0 = blockIdx.y * 32, n0 = blockIdx.x * 32;
    #pragma unroll
    for (int i = 0; i < 4; i++) {
        int k = k0 + threadIdx.y + i * 8;
        int n = n0 + threadIdx.x;
        t[threadIdx.y + i * 8][threadIdx.x] = (n < N) ? W[(size_t)k * N + n] : 0.f;
    }
    __syncthreads();
    #pragma unroll
    for (int i = 0; i < 4; i++) {
        int n = n0 + threadIdx.y + i * 8;
        int k = k0 + threadIdx.x;
        float v = t[threadIdx.x][threadIdx.y + i * 8];
        __half h, l; split2(v, h, l);
        Oh[(size_t)n * K + k] = h;
        if (Ol) Ol[(size_t)n * K + k] = l;
    }
}

// BK = 64: rows of 64 halfs (128 B) + 16 B pad -> APITCH 72 halfs (144 B)
#define APITCH 72
#define TILE_B (128 * APITCH * 2)     // 18432

// ---- shared epilogue ----
__device__ __forceinline__ void gemm_epilogue(
    float acc[4][4][4], const float* bias, float* Cf, __half* Coh,
    int m0, int n0, int warp_m, int warp_n, int lane, int N, int relu) {
    #pragma unroll
    for (int fj = 0; fj < 4; fj++) {
        const int c0 = n0 + warp_n + fj * 8 + 2 * (lane & 3);
        const bool c0ok = (c0 < N), c1ok = (c0 + 1 < N);
        const float b0 = c0ok ? bias[c0] : 0.f;
        const float b1 = c1ok ? bias[c0 + 1] : 0.f;
        #pragma unroll
        for (int fi = 0; fi < 4; fi++) {
            const int r0 = m0 + warp_m + fi * 16 + (lane >> 2);
            float v0 = acc[fi][fj][0] + b0;
            float v1 = acc[fi][fj][1] + b1;
            float v2 = acc[fi][fj][2] + b0;
            float v3 = acc[fi][fj][3] + b1;
            if (relu) {
                v0 = fmaxf(v0, 0.f); v1 = fmaxf(v1, 0.f);
                v2 = fmaxf(v2, 0.f); v3 = fmaxf(v3, 0.f);
            }
            if (Cf) {
                if (c1ok) {
                    *(float2*)(Cf + (size_t)r0 * N + c0)       = make_float2(v0, v1);
                    *(float2*)(Cf + (size_t)(r0 + 8) * N + c0) = make_float2(v2, v3);
                } else if (c0ok) {
                    Cf[(size_t)r0 * N + c0]       = v0;
                    Cf[(size_t)(r0 + 8) * N + c0] = v2;
                }
            } else {
                if (c1ok) {
                    *(__half2*)(Coh + (size_t)r0 * N + c0) =
                        __halves2half2(__float2half_rn(v0), __float2half_rn(v1));
                    *(__half2*)(Coh + (size_t)(r0 + 8) * N + c0) =
                        __halves2half2(__float2half_rn(v2), __float2half_rn(v3));
                } else if (c0ok) {
                    Coh[(size_t)r0 * N + c0]       = __float2half_rn(v0);
                    Coh[(size_t)(r0 + 8) * N + c0] = __float2half_rn(v2);
                }
            }
        }
    }
}

// ================= 1-term GEMM =================
#define STAGE1_B (2 * TILE_B)
#define GEMM1_DSMEM (2 * STAGE1_B)

__device__ __forceinline__ void issue_stage1(
    uint32_t sb, const __half* Ah_g, const __half* Bh_g,
    int m0, int n0, int K, int kk, int tid) {
    #pragma unroll
    for (int p = 0; p < 4; p++) {
        int c = p * 256 + tid;
        int row = c >> 3, q = c & 7;
        uint32_t d = sb + (uint32_t)(row * 144 + q * 16);
        size_t ao = (size_t)(m0 + row) * K + kk + q * 8;
        size_t bo = (size_t)(n0 + row) * K + kk + q * 8;
        CPA16(d,          Ah_g + ao);
        CPA16(d + TILE_B, Bh_g + bo);
    }
    asm volatile("cp.async.commit_group;" ::: "memory");
}

__global__ __launch_bounds__(256, 2)
void gemm1_mma_kernel(const __half* __restrict__ Ah_g,
                      const __half* __restrict__ Bh_g,
                      const float* __restrict__ bias,
                      float* __restrict__ Cf,
                      __half* __restrict__ Coh,
                      int K, int N, int relu) {
    extern __shared__ char smem[];
    const int tid  = threadIdx.x;
    const int wid  = tid >> 5;
    const int lane = tid & 31;
    const int m0 = blockIdx.y * 128;
    const int n0 = blockIdx.x * 128;
    const int warp_m = (wid >> 2) * 64;
    const int warp_n = (wid & 3) * 32;

    const uint32_t sbase = smem_u32(smem);

    float acc[4][4][4];
    #pragma unroll
    for (int i = 0; i < 4; i++)
        #pragma unroll
        for (int j = 0; j < 4; j++)
            #pragma unroll
            for (int e = 0; e < 4; e++) acc[i][j][e] = 0.f;

    const int KT = K >> 6;
    const int r8  = lane & 7;
    const int sub = lane >> 3;
    const uint32_t a_lane_off =
        (uint32_t)(((warp_m + r8 + (sub & 1) * 8) * APITCH + (sub >> 1) * 8) * 2);
    const uint32_t b_lane_off =
        (uint32_t)(((warp_n + r8) * APITCH + (sub & 1) * 8) * 2);

    issue_stage1(sbase, Ah_g, Bh_g, m0, n0, K, 0, tid);

    for (int kt = 0; kt < KT; kt++) {
        asm volatile("cp.async.wait_group 0;" ::: "memory");
        __syncthreads();
        if (kt + 1 < KT)
            issue_stage1(sbase + ((kt + 1) & 1) * STAGE1_B, Ah_g, Bh_g,
                         m0, n0, K, (kt + 1) << 6, tid);

        const uint32_t stoff = (kt & 1) * STAGE1_B;
        const uint32_t abase = sbase + stoff + a_lane_off;
        const uint32_t bbase = sbase + stoff + TILE_B + b_lane_off;

        #pragma unroll
        for (int ks = 0; ks < 4; ks++) {
            const uint32_t ak = abase + ks * 32;
            const uint32_t bk = bbase + ks * 32;

            uint32_t Ahf[4][4], Bhf[4][2];
            #pragma unroll
            for (int fi = 0; fi < 4; fi++)
                LDMX4(Ahf[fi], ak + fi * (16 * APITCH * 2));
            #pragma unroll
            for (int fj = 0; fj < 4; fj++)
                LDMX2(Bhf[fj], bk + fj * (8 * APITCH * 2));
            #pragma unroll
            for (int fi = 0; fi < 4; fi++)
                #pragma unroll
                for (int fj = 0; fj < 4; fj++)
                    MMA16816(acc[fi][fj], Ahf[fi], Bhf[fj]);
        }
    }

    gemm_epilogue(acc, bias, Cf, Coh, m0, n0, warp_m, warp_n, lane, N, relu);
}

// ================= 2-term GEMM (head) =================
#define STAGE2_B (3 * TILE_B)
#define GEMM2_DSMEM (2 * STAGE2_B)

__device__ __forceinline__ void issue_stage2(
    uint32_t sb, const __half* Ah_g, const __half* Bh_g, const __half* Bl_g,
    int m0, int n0, int K, int kk, int tid) {
    #pragma unroll
    for (int p = 0; p < 4; p++) {
        int c = p * 256 + tid;
        int row = c >> 3, q = c & 7;
        uint32_t d = sb + (uint32_t)(row * 144 + q * 16);
        size_t ao = (size_t)(m0 + row) * K + kk + q * 8;
        size_t bo = (size_t)(n0 + row) * K + kk + q * 8;
        CPA16(d,              Ah_g + ao);
        CPA16(d + TILE_B,     Bh_g + bo);
        CPA16(d + 2 * TILE_B, Bl_g + bo);
    }
    asm volatile("cp.async.commit_group;" ::: "memory");
}

__global__ __launch_bounds__(256, 2)
void gemm2_mma_kernel(const __half* __restrict__ Ah_g,
                      const __half* __restrict__ Bh_g,
                      const __half* __restrict__ Bl_g,
                      const float* __restrict__ bias,
                      float* __restrict__ Cf,
                      __half* __restrict__ Coh,
                      int K, int N, int relu) {
    extern __shared__ char smem[];
    const int tid  = threadIdx.x;
    const int wid  = tid >> 5;
    const int lane = tid & 31;
    const int m0 = blockIdx.y * 128;
    const int n0 = blockIdx.x * 128;
    const int warp_m = (wid >> 2) * 64;
    const int warp_n = (wid & 3) * 32;

    const uint32_t sbase = smem_u32(smem);

    float acc[4][4][4];
    #pragma unroll
    for (int i = 0; i < 4; i++)
        #pragma unroll
        for (int j = 0; j < 4; j++)
            #pragma unroll
            for (int e = 0; e < 4; e++) acc[i][j][e] = 0.f;

    const int KT = K >> 6;
    const int r8  = lane & 7;
    const int sub = lane >> 3;
    const uint32_t a_lane_off =
        (uint32_t)(((warp_m + r8 + (sub & 1) * 8) * APITCH + (sub >> 1) * 8) * 2);
    const uint32_t b_lane_off =
        (uint32_t)(((warp_n + r8) * APITCH + (sub & 1) * 8) * 2);

    issue_stage2(sbase, Ah_g, Bh_g, Bl_g, m0, n0, K, 0, tid);

    for (int kt = 0; kt < KT; kt++) {
        asm volatile("cp.async.wait_group 0;" ::: "memory");
        __syncthreads();
        if (kt + 1 < KT)
            issue_stage2(sbase + ((kt + 1) & 1) * STAGE2_B, Ah_g, Bh_g, Bl_g,
                         m0, n0, K, (kt + 1) << 6, tid);

        const uint32_t stoff = (kt & 1) * STAGE2_B;
        const uint32_t abase = sbase + stoff + a_lane_off;
        const uint32_t bbase = sbase + stoff + TILE_B + b_lane_off;

        #pragma unroll
        for (int ks = 0; ks < 4; ks++) {
            const uint32_t ak = abase + ks * 32;
            const uint32_t bk = bbase + ks * 32;

            uint32_t Ahf[4][4], Bhf[4][2], Blf[4][2];
            #pragma unroll
            for (int fi = 0; fi < 4; fi++)
                LDMX4(Ahf[fi], ak + fi * (16 * APITCH * 2));
            #pragma unroll
            for (int fj = 0; fj < 4; fj++)
                LDMX2(Bhf[fj], bk + fj * (8 * APITCH * 2));
            #pragma unroll
            for (int fi = 0; fi < 4; fi++)
                #pragma unroll
                for (int fj = 0; fj < 4; fj++)
                    MMA16816(acc[fi][fj], Ahf[fi], Bhf[fj]);

            #pragma unroll
            for (int fj = 0; fj < 4; fj++)
                LDMX2(Blf[fj], bk + TILE_B + fj * (8 * APITCH * 2));
            #pragma unroll
            for (int fi = 0; fi < 4; fi++)
                #pragma unroll
                for (int fj = 0; fj < 4; fj++)
                    MMA16816(acc[fi][fj], Ahf[fi], Blf[fj]);
        }
    }

    gemm_epilogue(acc, bias, Cf, Coh, m0, n0, warp_m, warp_n, lane, N, relu);
}

// ---------------- embed ----------------
__global__ void embed_kernel(const int* __restrict__ q_data,
                             const int* __restrict__ target,
                             const float* __restrict__ pe,
                             const float* __restrict__ q_emb,
                             const float* __restrict__ qa_emb) {
    size_t idx = (size_t)blockIdx.x * blockDim.x + threadIdx.x;
    if (idx >= (size_t)Mr * Dc) return;
    int bs = (int)(idx / Dc);
    int d  = (int)(idx % Dc);
    int s  = bs % Sc;
    float qe = q_emb[(size_t)q_data[bs] * Dc + d];
    float p  = pe[(size_t)s * Dc + d];
    float x  = qe + p;
    float y  = qa_emb[(size_t)target[bs] * Dc + d] + qe + p;
    g_qe[idx] = qe;
    g_x [idx] = x;
    g_xh[idx] = __float2half_rn(x);
    g_yh[idx] = __float2half_rn(y);
}

// ---------------- tensor-core flash attention ----------------
// grid (8 qtile, 8 head, 64 batch), 128 threads = 4 warps x 16 query rows.
__global__ __launch_bounds__(128)
void attn_tc_kernel() {
    const int qt = blockIdx.x, hh = blockIdx.y, b = blockIdx.z;
    const int tid = threadIdx.x;
    const int w = tid >> 5, lane = tid & 31;
    const int r8 = lane & 7, sub = lane >> 3;
    const int quad = lane >> 2, tq = lane & 3;

    __shared__ __half Qs[64][72];
    __shared__ __half Ks[64][72];
    __shared__ __half Vs[64][72];
    const uint32_t sQ = smem_u32(&Qs[0][0]);
    const uint32_t sK = smem_u32(&Ks[0][0]);
    const uint32_t sV = smem_u32(&Vs[0][0]);

    // load Q tile (pre-scaled by 1/8 — exact in fp16)
    {
        const __half* src = g_Kh + ((size_t)(b * Sc + qt * 64)) * Dc + hh * DKc;
        const __half2 s8 = __half2half2(__float2half_rn(0.125f));
        #pragma unroll
        for (int p = 0; p < 4; p++) {
            int c = p * 128 + tid;
            int row = c >> 3, col = (c & 7) * 8;
            uint4 v = *(const uint4*)(src + (size_t)row * Dc + col);
            __half2* hv = (__half2*)&v;
            hv[0] = __hmul2(hv[0], s8); hv[1] = __hmul2(hv[1], s8);
            hv[2] = __hmul2(hv[2], s8); hv[3] = __hmul2(hv[3], s8);
            *(uint4*)&Qs[row][col] = v;
        }
    }
    __syncthreads();

    uint32_t Qf[4][4];
    #pragma unroll
    for (int ks = 0; ks < 4; ks++)
        LDMX4(Qf[ks], sQ + (uint32_t)(((w * 16 + r8 + (sub & 1) * 8) * 72 +
                                       ks * 16 + (sub >> 1) * 8) * 2));

    float out[8][4];
    #pragma unroll
    for (int f = 0; f < 8; f++)
        #pragma unroll
        for (int e = 0; e < 4; e++) out[f][e] = 0.f;
    float m0 = -1e30f, m1 = -1e30f, l0 = 0.f, l1 = 0.f;
    const int il0 = w * 16 + quad;

    for (int jt = 0; jt <= qt; jt++) {
        __syncthreads();   // protect Ks/Vs reuse
        const __half* ksrc = g_Kh + ((size_t)(b * Sc + jt * 64)) * Dc + hh * DKc;
        const __half* vsrc = g_Vh + ((size_t)(b * Sc + jt * 64)) * Dc + hh * DKc;
        #pragma unroll
        for (int p = 0; p < 4; p++) {
            int c = p * 128 + tid;
            int row = c >> 3, col = (c & 7) * 8;
            *(uint4*)&Ks[row][col] = *(const uint4*)(ksrc + (size_t)row * Dc + col);
            *(uint4*)&Vs[row][col] = *(const uint4*)(vsrc + (size_t)row * Dc + col);
        }
        __syncthreads();

        // scores S = Q K^T (fp32 accum)
        float sc[8][4];
        #pragma unroll
        for (int f = 0; f < 8; f++)
            #pragma unroll
            for (int e = 0; e < 4; e++) sc[f][e] = 0.f;
        #pragma unroll
        for (int ks = 0; ks < 4; ks++) {
            #pragma unroll
            for (int nf2 = 0; nf2 < 4; nf2++) {
                uint32_t Kf[4];
                LDMX4(Kf, sK + (uint32_t)(((nf2 * 16 + (sub >> 1) * 8 + r8) * 72 +
                                           ks * 16 + (sub & 1) * 8) * 2));
                MMA16816(sc[nf2 * 2],     Qf[ks], (Kf));
                MMA16816(sc[nf2 * 2 + 1], Qf[ks], (Kf + 2));
            }
        }

        // strict causal mask on diagonal tile (j < i)
        if (jt == qt) {
            #pragma unroll
            for (int nf = 0; nf < 8; nf++) {
                int jl = nf * 8 + 2 * tq;
                if (jl     >= il0)     sc[nf][0] = -1e30f;
                if (jl + 1 >= il0)     sc[nf][1] = -1e30f;
                if (jl     >= il0 + 8) sc[nf][2] = -1e30f;
                if (jl + 1 >= il0 + 8) sc[nf][3] = -1e30f;
            }
        }

        // tile row max (quad reduce)
        float mt0 = -1e30f, mt1 = -1e30f;
        #pragma unroll
        for (int nf = 0; nf < 8; nf++) {
            mt0 = fmaxf(mt0, fmaxf(sc[nf][0], sc[nf][1]));
            mt1 = fmaxf(mt1, fmaxf(sc[nf][2], sc[nf][3]));
        }
        mt0 = fmaxf(mt0, __shfl_xor_sync(0xffffffffu, mt0, 1));
        mt0 = fmaxf(mt0, __shfl_xor_sync(0xffffffffu, mt0, 2));
        mt1 = fmaxf(mt1, __shfl_xor_sync(0xffffffffu, mt1, 1));
        mt1 = fmaxf(mt1, __shfl_xor_sync(0xffffffffu, mt1, 2));
        float mn0 = fmaxf(m0, mt0), mn1 = fmaxf(m1, mt1);
        float corr0 = __expf(m0 - mn0), corr1 = __expf(m1 - mn1);
        m0 = mn0; m1 = mn1;

        // exp, pack P fragments, partial row sums
        uint32_t Pa[4][4];
        float la0 = 0.f, la1 = 0.f;
        #pragma unroll
        for (int nf = 0; nf < 8; nf++) {
            float p0 = __expf(sc[nf][0] - mn0);
            float p1 = __expf(sc[nf][1] - mn0);
            float p2 = __expf(sc[nf][2] - mn1);
            float p3 = __expf(sc[nf][3] - mn1);
            la0 += p0 + p1; la1 += p2 + p3;
            __half2 h01 = __floats2half2_rn(p0, p1);
            __half2 h23 = __floats2half2_rn(p2, p3);
            Pa[nf >> 1][(nf & 1) * 2 + 0] = *(uint32_t*)&h01;
            Pa[nf >> 1][(nf & 1) * 2 + 1] = *(uint32_t*)&h23;
        }
        l0 = l0 * corr0 + la0;
        l1 = l1 * corr1 + la1;
        #pragma unroll
        for (int f = 0; f < 8; f++) {
            out[f][0] *= corr0; out[f][1] *= corr0;
            out[f][2] *= corr1; out[f][3] *= corr1;
        }

        // O += P V  (V via ldmatrix.trans)
        #pragma unroll
        for (int ks = 0; ks < 4; ks++) {
            #pragma unroll
            for (int df2 = 0; df2 < 4; df2++) {
                uint32_t Vf[4];
                LDMX4T(Vf, sV + (uint32_t)(((ks * 16 + (sub & 1) * 8 + r8) * 72 +
                                            df2 * 16 + (sub >> 1) * 8) * 2));
                MMA16816(out[df2 * 2],     Pa[ks], (Vf));
                MMA16816(out[df2 * 2 + 1], Pa[ks], (Vf + 2));
            }
        }
    }

    // final row-sum reduce + normalize + store
    l0 += __shfl_xor_sync(0xffffffffu, l0, 1);
    l0 += __shfl_xor_sync(0xffffffffu, l0, 2);
    l1 += __shfl_xor_sync(0xffffffffu, l1, 1);
    l1 += __shfl_xor_sync(0xffffffffu, l1, 2);
    const int gi0 = qt * 64 + il0;
    const float inv0 = (gi0 > 0) ? 1.f / l0 : 0.f;
    const float inv1 = 1.f / l1;
    __half* dst = g_Oh + ((size_t)(b * Sc + gi0)) * Dc + hh * DKc;
    #pragma unroll
    for (int df = 0; df < 8; df++) {
        int col = df * 8 + 2 * tq;
        *(__half2*)(dst + col) =
            __floats2half2_rn(out[df][0] * inv0, out[df][1] * inv0);
        *(__half2*)(dst + (size_t)8 * Dc + col) =
            __floats2half2_rn(out[df][2] * inv1, out[df][3] * inv1);
    }
}

// ---------------- fused add + LayerNorm (+ fp16 hi out) ----------------
__global__ __launch_bounds__(256)
void add_ln_kernel(float* __restrict__ x, const float* __restrict__ resid,
                   const float* __restrict__ g, const float* __restrict__ b) {
    const int row = blockIdx.x;
    const int tid = threadIdx.x;
    const size_t base = (size_t)row * Dc;
    float v0 = x[base + tid]       + resid[base + tid];
    float v1 = x[base + tid + 256] + resid[base + tid + 256];
    float s  = v0 + v1;
    float ss = v0 * v0 + v1 * v1;

    __shared__ float sbuf[8], ssbuf[8];
    #pragma unroll
    for (int o = 16; o > 0; o >>= 1) {
        s  += __shfl_xor_sync(0xffffffffu, s, o);
        ss += __shfl_xor_sync(0xffffffffu, ss, o);
    }
    if ((tid & 31) == 0) { sbuf[tid >> 5] = s; ssbuf[tid >> 5] = ss; }
    __syncthreads();
    if (tid < 32) {
        s  = (tid < 8) ? sbuf[tid]  : 0.f;
        ss = (tid < 8) ? ssbuf[tid] : 0.f;
        #pragma unroll
        for (int o = 4; o > 0; o >>= 1) {
            s  += __shfl_xor_sync(0xffffffffu, s, o);
            ss += __shfl_xor_sync(0xffffffffu, ss, o);
        }
        if (tid == 0) { sbuf[0] = s; ssbuf[0] = ss; }
    }
    __syncthreads();
    float mean = sbuf[0] * (1.f / 512.f);
    float var  = ssbuf[0] * (1.f / 512.f) - mean * mean;
    float rstd = rsqrtf(var + 1e-5f);
    float o0 = (v0 - mean) * rstd * g[tid]       + b[tid];
    float o1 = (v1 - mean) * rstd * g[tid + 256] + b[tid + 256];
    x[base + tid]       = o0;
    x[base + tid + 256] = o1;
    g_xh[base + tid]       = __float2half_rn(o0);
    g_xh[base + tid + 256] = __float2half_rn(o1);
}

// ---------------- concat [x | qe] -> fp16 hi ----------------
__global__ void concat_kernel() {
    size_t idx = (size_t)blockIdx.x * blockDim.x + threadIdx.x;
    if (idx >= (size_t)Mr * 2 * Dc) return;
    int bs = (int)(idx / (2 * Dc));
    int c  = (int)(idx % (2 * Dc));
    float v = (c < Dc) ? g_x[(size_t)bs * Dc + c]
                       : g_qe[(size_t)bs * Dc + (c - Dc)];
    g_Ch[idx] = __float2half_rn(v);
}

// ---------------- host ----------------
static inline void split_w(const float* W, __half* oh, __half* ol,
                           int K, int N, int Npad) {
    split_w_kernel<<<dim3(Npad / 32, K / 32), dim3(32, 8)>>>(W, oh, ol, K, N);
}
static inline void gemm1F32(const __half* ah, const __half* bh,
                            const float* bias, float* C, int K, int N, int Npad,
                            int relu) {
    gemm1_mma_kernel<<<dim3(Npad / 128, Mr / 128), 256, GEMM1_DSMEM>>>(
        ah, bh, bias, C, nullptr, K, N, relu);
}
static inline void gemm1F16(const __half* ah, const __half* bh,
                            const float* bias, __half* oh, int K, int N,
                            int Npad, int relu) {
    gemm1_mma_kernel<<<dim3(Npad / 128, Mr / 128), 256, GEMM1_DSMEM>>>(
        ah, bh, bias, nullptr, oh, K, N, relu);
}
static inline void gemm2F32(const __half* ah, const __half* bh, const __half* bl,
                            const float* bias, float* C, int K, int N, int Npad,
                            int relu) {
    gemm2_mma_kernel<<<dim3(Npad / 128, Mr / 128), 256, GEMM2_DSMEM>>>(
        ah, bh, bl, bias, C, nullptr, K, N, relu);
}
static inline void gemm2F16(const __half* ah, const __half* bh, const __half* bl,
                            const float* bias, __half* oh, int K, int N,
                            int Npad, int relu) {
    gemm2_mma_kernel<<<dim3(Npad / 128, Mr / 128), 256, GEMM2_DSMEM>>>(
        ah, bh, bl, bias, nullptr, oh, K, N, relu);
}

extern "C" void kernel_launch(void* const* d_in, const int* in_sizes, int n_in,
                              void* d_out, int out_size) {
    const int*   q_data = (const int*)d_in[0];
    const int*   target = (const int*)d_in[1];
    const float* pe     = (const float*)d_in[2];
    const float* q_emb  = (const float*)d_in[3];
    const float* qa_emb = (const float*)d_in[4];
    const float* Wk     = (const float*)d_in[5];
    const float* bk     = (const float*)d_in[6];
    const float* Wv     = (const float*)d_in[7];
    const float* bv     = (const float*)d_in[8];
    const float* Wo     = (const float*)d_in[9];
    const float* bo     = (const float*)d_in[10];
    const float* ln1_g  = (const float*)d_in[11];
    const float* ln1_b  = (const float*)d_in[12];
    const float* W1     = (const float*)d_in[13];
    const float* b1     = (const float*)d_in[14];
    const float* W2     = (const float*)d_in[15];
    const float* b2     = (const float*)d_in[16];
    const float* ln2_g  = (const float*)d_in[17];
    const float* ln2_b  = (const float*)d_in[18];
    const float* Wout1  = (const float*)d_in[19];
    const float* bout1  = (const float*)d_in[20];
    const float* Wout2  = (const float*)d_in[21];
    const float* bout2  = (const float*)d_in[22];
    const float* Wout3  = (const float*)d_in[23];
    const float* bout3  = (const float*)d_in[24];
    float* out = (float*)d_out;

    cudaFuncSetAttribute(gemm1_mma_kernel,
                         cudaFuncAttributeMaxDynamicSharedMemorySize, GEMM1_DSMEM);
    cudaFuncSetAttribute(gemm2_mma_kernel,
                         cudaFuncAttributeMaxDynamicSharedMemorySize, GEMM2_DSMEM);

    float *p_x, *p_P;
    cudaGetSymbolAddress((void**)&p_x, g_x);
    cudaGetSymbolAddress((void**)&p_P, g_P);

    __half *xh, *yh, *kh, *vh, *oh, *f1h, *ch, *h1h, *h2h;
    cudaGetSymbolAddress((void**)&xh, g_xh);
    cudaGetSymbolAddress((void**)&yh, g_yh);
    cudaGetSymbolAddress((void**)&kh, g_Kh);
    cudaGetSymbolAddress((void**)&vh, g_Vh);
    cudaGetSymbolAddress((void**)&oh, g_Oh);
    cudaGetSymbolAddress((void**)&f1h, g_F1h);
    cudaGetSymbolAddress((void**)&ch, g_Ch);
    cudaGetSymbolAddress((void**)&h1h, g_H1h);
    cudaGetSymbolAddress((void**)&h2h, g_H2h);

    __half *wk_h, *wv_h, *wo_h, *w1_h, *w2_h;
    __half *wo1_h, *wo1_l, *wo2_h, *wo2_l, *wo3_h, *wo3_l;
    cudaGetSymbolAddress((void**)&wk_h, g_Wk_h);
    cudaGetSymbolAddress((void**)&wv_h, g_Wv_h);
    cudaGetSymbolAddress((void**)&wo_h, g_Wo_h);
    cudaGetSymbolAddress((void**)&w1_h, g_W1_h);
    cudaGetSymbolAddress((void**)&w2_h, g_W2_h);
    cudaGetSymbolAddress((void**)&wo1_h, g_Wo1_h); cudaGetSymbolAddress((void**)&wo1_l, g_Wo1_l);
    cudaGetSymbolAddress((void**)&wo2_h, g_Wo2_h); cudaGetSymbolAddress((void**)&wo2_l, g_Wo2_l);
    cudaGetSymbolAddress((void**)&wo3_h, g_Wo3_h); cudaGetSymbolAddress((void**)&wo3_l, g_Wo3_l);

    // embed + weight prep
    {
        size_t tot = (size_t)Mr * Dc;
        embed_kernel<<<(unsigned)((tot + 255) / 256), 256>>>(q_data, target, pe,
                                                             q_emb, qa_emb);
    }
    for (int l = 0; l < Lc; l++) {
        size_t oDD = (size_t)l * Dc * Dc;
        size_t oDF = (size_t)l * Dc * DFFc;
        split_w(Wk + oDD, wk_h + oDD, nullptr, Dc, Dc, Dc);
        split_w(Wv + oDD, wv_h + oDD, nullptr, Dc, Dc, Dc);
        split_w(Wo + oDD, wo_h + oDD, nullptr, Dc, Dc, Dc);
        split_w(W1 + oDF, w1_h + oDF, nullptr, Dc, DFFc, DFFc);
        split_w(W2 + oDF, w2_h + oDF, nullptr, DFFc, Dc, Dc);
    }
    split_w(Wout1, wo1_h, wo1_l, 2 * Dc, FC1c, FC1c);
    split_w(Wout2, wo2_h, wo2_l, FC1c, FC2c, FC2c);
    split_w(Wout3, wo3_h, wo3_l, FC2c, NSKc, NSKp);

    // transformer layers
    for (int l = 0; l < Lc; l++) {
        size_t oDD = (size_t)l * Dc * Dc;
        size_t oDF = (size_t)l * Dc * DFFc;
        gemm1F16(xh, wk_h + oDD, bk + l * Dc, kh, Dc, Dc, Dc, 0);   // K (== Q), fp16
        gemm1F16(yh, wv_h + oDD, bv + l * Dc, vh, Dc, Dc, Dc, 0);   // V, fp16
        attn_tc_kernel<<<dim3(Sc / 64, Hc, Bc), 128>>>();
        gemm1F32(oh, wo_h + oDD, bo + l * Dc, p_P, Dc, Dc, Dc, 0);
        add_ln_kernel<<<Mr, 256>>>(p_x, p_P, ln1_g + l * Dc, ln1_b + l * Dc);
        gemm1F16(xh, w1_h + oDF, b1 + l * DFFc, f1h, Dc, DFFc, DFFc, 1);
        gemm1F32(f1h, w2_h + oDF, b2 + l * Dc, p_P, DFFc, Dc, Dc, 0);
        add_ln_kernel<<<Mr, 256>>>(p_x, p_P, ln2_g + l * Dc, ln2_b + l * Dc);
    }

    // head
    {
        size_t tot = (size_t)Mr * 2 * Dc;
        concat_kernel<<<(unsigned)((tot + 255) / 256), 256>>>();
    }
    gemm2F16(ch, wo1_h, wo1_l, bout1, h1h, 2 * Dc, FC1c, FC1c, 1);
    gemm2F16(h1h, wo2_h, wo2_l, bout2, h2h, FC1c, FC2c, FC2c, 1);
    gemm2F32(h2h, wo3_h, wo3_l, bout3, out, FC2c, NSKc, NSKp, 0);
}

// round 16
// speedup vs baseline: 3.8983x; 1.0341x over previous
#include <cuda_runtime.h>
#include <cuda_fp16.h>
#include <math.h>
#include <stdint.h>

#define Bc   64
#define Sc   512
#define Dc   512
#define Hc   8
#define DKc  64
#define Lc   4
#define DFFc 2048
#define NSKc 300
#define NSKp 384
#define FC1c 512
#define FC2c 256
#define Mr   (Bc * Sc)

// ---------------- fp32 scratch ----------------
__device__ float g_qe[(size_t)Mr * Dc];
__device__ float g_x [(size_t)Mr * Dc];
__device__ float g_P [(size_t)Mr * Dc];

// ---------------- fp16 activations (hi only) ----------------
__device__ __half g_xh [(size_t)Mr * Dc];
__device__ __half g_yh [(size_t)Mr * Dc];
__device__ __half g_Kh [(size_t)Mr * Dc];
__device__ __half g_Vh [(size_t)Mr * Dc];
__device__ __half g_Oh [(size_t)Mr * Dc];
__device__ __half g_F1h[(size_t)Mr * DFFc];
__device__ __half g_Ch [(size_t)Mr * 2 * Dc];
__device__ __half g_H1h[(size_t)Mr * FC1c];
__device__ __half g_H2h[(size_t)Mr * FC2c];

// ---------------- fp16 weights (transposed [N][K]) ----------------
__device__ __half g_Wk_h[(size_t)Lc * Dc * Dc];
__device__ __half g_Wv_h[(size_t)Lc * Dc * Dc];
__device__ __half g_Wo_h[(size_t)Lc * Dc * Dc];
__device__ __half g_W1_h[(size_t)Lc * Dc * DFFc];
__device__ __half g_W2_h[(size_t)Lc * DFFc * Dc];
__device__ __half g_Wo1_h[(size_t)2 * Dc * FC1c], g_Wo1_l[(size_t)2 * Dc * FC1c];
__device__ __half g_Wo2_h[(size_t)FC1c * FC2c],   g_Wo2_l[(size_t)FC1c * FC2c];
__device__ __half g_Wo3_h[(size_t)NSKp * FC2c],   g_Wo3_l[(size_t)NSKp * FC2c];

// ---------------- helpers ----------------
__device__ __forceinline__ uint32_t smem_u32(const void* p) {
    uint32_t a;
    asm("{ .reg .u64 t; cvta.to.shared.u64 t, %1; cvt.u32.u64 %0, t; }"
        : "=r"(a) : "l"(p));
    return a;
}
__device__ __forceinline__ void split2(float v, __half& h, __half& l) {
    h = __float2half_rn(v);
    l = __float2half_rn(v - __half2float(h));
}

#define CPA16(dst, src)                                                       \
    asm volatile("cp.async.cg.shared.global [%0], [%1], 16;"                  \
                 :: "r"(dst), "l"(src) : "memory")

#define LDMX4(R, addr)                                                        \
    asm volatile("ldmatrix.sync.aligned.m8n8.x4.shared.b16 {%0,%1,%2,%3}, [%4];" \
        : "=r"((R)[0]), "=r"((R)[1]), "=r"((R)[2]), "=r"((R)[3]) : "r"(addr))

#define LDMX4T(R, addr)                                                       \
    asm volatile("ldmatrix.sync.aligned.m8n8.x4.trans.shared.b16 {%0,%1,%2,%3}, [%4];" \
        : "=r"((R)[0]), "=r"((R)[1]), "=r"((R)[2]), "=r"((R)[3]) : "r"(addr))

#define LDMX2(R, addr)                                                        \
    asm volatile("ldmatrix.sync.aligned.m8n8.x2.shared.b16 {%0,%1}, [%2];"    \
        : "=r"((R)[0]), "=r"((R)[1]) : "r"(addr))

#define MMA16816(d, a, b)                                                     \
    asm volatile("mma.sync.aligned.m16n8k16.row.col.f32.f16.f16.f32 "         \
        "{%0,%1,%2,%3}, {%4,%5,%6,%7}, {%8,%9}, {%0,%1,%2,%3};"               \
        : "+f"((d)[0]), "+f"((d)[1]), "+f"((d)[2]), "+f"((d)[3])              \
        : "r"((a)[0]), "r"((a)[1]), "r"((a)[2]), "r"((a)[3]),                 \
          "r"((b)[0]), "r"((b)[1]))

// ---------------- weight prep: transpose + hi/lo split ----------------
__global__ void split_w_kernel(const float* __restrict__ W,
                               __half* __restrict__ Oh, __half* __restrict__ Ol,
                               int K, int N) {
    __shared__ float t[32][33];
    int k0 = blockIdx.y * 32, n0 = blockIdx.x * 32;
    #pragma unroll
    for (int i = 0; i < 4; i++) {
        int k = k0 + threadIdx.y + i * 8;
        int n = n0 + threadIdx.x;
        t[threadIdx.y + i * 8][threadIdx.x] = (n < N) ? W[(size_t)k * N + n] : 0.f;
    }
    __syncthreads();
    #pragma unroll
    for (int i = 0; i < 4; i++) {
        int n = n0 + threadIdx.y + i * 8;
        int k = k0 + threadIdx.x;
        float v = t[threadIdx.x][threadIdx.y + i * 8];
        __half h, l; split2(v, h, l);
        Oh[(size_t)n * K + k] = h;
        if (Ol) Ol[(size_t)n * K + k] = l;
    }
}

// BK = 64: rows of 64 halfs (128 B) + 16 B pad -> APITCH 72 halfs (144 B)
#define APITCH 72
#define TILE_B (128 * APITCH * 2)     // 18432

// ---- shared epilogue ----
__device__ __forceinline__ void gemm_epilogue(
    float acc[4][4][4], const float* bias, float* Cf, __half* Coh,
    int m0, int n0, int warp_m, int warp_n, int lane, int N, int relu) {
    #pragma unroll
    for (int fj = 0; fj < 4; fj++) {
        const int c0 = n0 + warp_n + fj * 8 + 2 * (lane & 3);
        const bool c0ok = (c0 < N), c1ok = (c0 + 1 < N);
        const float b0 = c0ok ? bias[c0] : 0.f;
        const float b1 = c1ok ? bias[c0 + 1] : 0.f;
        #pragma unroll
        for (int fi = 0; fi < 4; fi++) {
            const int r0 = m0 + warp_m + fi * 16 + (lane >> 2);
            float v0 = acc[fi][fj][0] + b0;
            float v1 = acc[fi][fj][1] + b1;
            float v2 = acc[fi][fj][2] + b0;
            float v3 = acc[fi][fj][3] + b1;
            if (relu) {
                v0 = fmaxf(v0, 0.f); v1 = fmaxf(v1, 0.f);
                v2 = fmaxf(v2, 0.f); v3 = fmaxf(v3, 0.f);
            }
            if (Cf) {
                if (c1ok) {
                    *(float2*)(Cf + (size_t)r0 * N + c0)       = make_float2(v0, v1);
                    *(float2*)(Cf + (size_t)(r0 + 8) * N + c0) = make_float2(v2, v3);
                } else if (c0ok) {
                    Cf[(size_t)r0 * N + c0]       = v0;
                    Cf[(size_t)(r0 + 8) * N + c0] = v2;
                }
            } else {
                if (c1ok) {
                    *(__half2*)(Coh + (size_t)r0 * N + c0) =
                        __halves2half2(__float2half_rn(v0), __float2half_rn(v1));
                    *(__half2*)(Coh + (size_t)(r0 + 8) * N + c0) =
                        __halves2half2(__float2half_rn(v2), __float2half_rn(v3));
                } else if (c0ok) {
                    Coh[(size_t)r0 * N + c0]       = __float2half_rn(v0);
                    Coh[(size_t)(r0 + 8) * N + c0] = __float2half_rn(v2);
                }
            }
        }
    }
}

// ================= 1-term GEMM (z-select second operand set) ================
#define STAGE1_B (2 * TILE_B)
#define GEMM1_DSMEM (2 * STAGE1_B)

__device__ __forceinline__ void issue_stage1(
    uint32_t sb, const __half* Ah_g, const __half* Bh_g,
    int m0, int n0, int K, int kk, int tid) {
    #pragma unroll
    for (int p = 0; p < 4; p++) {
        int c = p * 256 + tid;
        int row = c >> 3, q = c & 7;
        uint32_t d = sb + (uint32_t)(row * 144 + q * 16);
        size_t ao = (size_t)(m0 + row) * K + kk + q * 8;
        size_t bo = (size_t)(n0 + row) * K + kk + q * 8;
        CPA16(d,          Ah_g + ao);
        CPA16(d + TILE_B, Bh_g + bo);
    }
    asm volatile("cp.async.commit_group;" ::: "memory");
}

__global__ __launch_bounds__(256, 2)
void gemm1_mma_kernel(const __half* __restrict__ Ah_g,
                      const __half* __restrict__ Bh_g,
                      const float* __restrict__ bias,
                      float* __restrict__ Cf,
                      __half* __restrict__ Coh,
                      const __half* __restrict__ Ah2,
                      const __half* __restrict__ Bh2,
                      const float* __restrict__ bias2,
                      __half* __restrict__ Coh2,
                      int K, int N, int relu) {
    if (blockIdx.z) {   // merged second GEMM (e.g. V-proj alongside K-proj)
        Ah_g = Ah2; Bh_g = Bh2; bias = bias2; Coh = Coh2; Cf = nullptr;
    }
    extern __shared__ char smem[];
    const int tid  = threadIdx.x;
    const int wid  = tid >> 5;
    const int lane = tid & 31;
    const int m0 = blockIdx.y * 128;
    const int n0 = blockIdx.x * 128;
    const int warp_m = (wid >> 2) * 64;
    const int warp_n = (wid & 3) * 32;

    const uint32_t sbase = smem_u32(smem);

    float acc[4][4][4];
    #pragma unroll
    for (int i = 0; i < 4; i++)
        #pragma unroll
        for (int j = 0; j < 4; j++)
            #pragma unroll
            for (int e = 0; e < 4; e++) acc[i][j][e] = 0.f;

    const int KT = K >> 6;
    const int r8  = lane & 7;
    const int sub = lane >> 3;
    const uint32_t a_lane_off =
        (uint32_t)(((warp_m + r8 + (sub & 1) * 8) * APITCH + (sub >> 1) * 8) * 2);
    const uint32_t b_lane_off =
        (uint32_t)(((warp_n + r8) * APITCH + (sub & 1) * 8) * 2);

    issue_stage1(sbase, Ah_g, Bh_g, m0, n0, K, 0, tid);

    for (int kt = 0; kt < KT; kt++) {
        asm volatile("cp.async.wait_group 0;" ::: "memory");
        __syncthreads();
        if (kt + 1 < KT)
            issue_stage1(sbase + ((kt + 1) & 1) * STAGE1_B, Ah_g, Bh_g,
                         m0, n0, K, (kt + 1) << 6, tid);

        const uint32_t stoff = (kt & 1) * STAGE1_B;
        const uint32_t abase = sbase + stoff + a_lane_off;
        const uint32_t bbase = sbase + stoff + TILE_B + b_lane_off;

        #pragma unroll
        for (int ks = 0; ks < 4; ks++) {
            const uint32_t ak = abase + ks * 32;
            const uint32_t bk = bbase + ks * 32;

            uint32_t Ahf[4][4], Bhf[4][2];
            #pragma unroll
            for (int fi = 0; fi < 4; fi++)
                LDMX4(Ahf[fi], ak + fi * (16 * APITCH * 2));
            #pragma unroll
            for (int fj = 0; fj < 4; fj++)
                LDMX2(Bhf[fj], bk + fj * (8 * APITCH * 2));
            #pragma unroll
            for (int fi = 0; fi < 4; fi++)
                #pragma unroll
                for (int fj = 0; fj < 4; fj++)
                    MMA16816(acc[fi][fj], Ahf[fi], Bhf[fj]);
        }
    }

    gemm_epilogue(acc, bias, Cf, Coh, m0, n0, warp_m, warp_n, lane, N, relu);
}

// ================= 2-term GEMM (head) =================
#define STAGE2_B (3 * TILE_B)
#define GEMM2_DSMEM (2 * STAGE2_B)

__device__ __forceinline__ void issue_stage2(
    uint32_t sb, const __half* Ah_g, const __half* Bh_g, const __half* Bl_g,
    int m0, int n0, int K, int kk, int tid) {
    #pragma unroll
    for (int p = 0; p < 4; p++) {
        int c = p * 256 + tid;
        int row = c >> 3, q = c & 7;
        uint32_t d = sb + (uint32_t)(row * 144 + q * 16);
        size_t ao = (size_t)(m0 + row) * K + kk + q * 8;
        size_t bo = (size_t)(n0 + row) * K + kk + q * 8;
        CPA16(d,              Ah_g + ao);
        CPA16(d + TILE_B,     Bh_g + bo);
        CPA16(d + 2 * TILE_B, Bl_g + bo);
    }
    asm volatile("cp.async.commit_group;" ::: "memory");
}

__global__ __launch_bounds__(256, 2)
void gemm2_mma_kernel(const __half* __restrict__ Ah_g,
                      const __half* __restrict__ Bh_g,
                      const __half* __restrict__ Bl_g,
                      const float* __restrict__ bias,
                      float* __restrict__ Cf,
                      __half* __restrict__ Coh,
                      int K, int N, int relu) {
    extern __shared__ char smem[];
    const int tid  = threadIdx.x;
    const int wid  = tid >> 5;
    const int lane = tid & 31;
    const int m0 = blockIdx.y * 128;
    const int n0 = blockIdx.x * 128;
    const int warp_m = (wid >> 2) * 64;
    const int warp_n = (wid & 3) * 32;

    const uint32_t sbase = smem_u32(smem);

    float acc[4][4][4];
    #pragma unroll
    for (int i = 0; i < 4; i++)
        #pragma unroll
        for (int j = 0; j < 4; j++)
            #pragma unroll
            for (int e = 0; e < 4; e++) acc[i][j][e] = 0.f;

    const int KT = K >> 6;
    const int r8  = lane & 7;
    const int sub = lane >> 3;
    const uint32_t a_lane_off =
        (uint32_t)(((warp_m + r8 + (sub & 1) * 8) * APITCH + (sub >> 1) * 8) * 2);
    const uint32_t b_lane_off =
        (uint32_t)(((warp_n + r8) * APITCH + (sub & 1) * 8) * 2);

    issue_stage2(sbase, Ah_g, Bh_g, Bl_g, m0, n0, K, 0, tid);

    for (int kt = 0; kt < KT; kt++) {
        asm volatile("cp.async.wait_group 0;" ::: "memory");
        __syncthreads();
        if (kt + 1 < KT)
            issue_stage2(sbase + ((kt + 1) & 1) * STAGE2_B, Ah_g, Bh_g, Bl_g,
                         m0, n0, K, (kt + 1) << 6, tid);

        const uint32_t stoff = (kt & 1) * STAGE2_B;
        const uint32_t abase = sbase + stoff + a_lane_off;
        const uint32_t bbase = sbase + stoff + TILE_B + b_lane_off;

        #pragma unroll
        for (int ks = 0; ks < 4; ks++) {
            const uint32_t ak = abase + ks * 32;
            const uint32_t bk = bbase + ks * 32;

            uint32_t Ahf[4][4], Bhf[4][2], Blf[4][2];
            #pragma unroll
            for (int fi = 0; fi < 4; fi++)
                LDMX4(Ahf[fi], ak + fi * (16 * APITCH * 2));
            #pragma unroll
            for (int fj = 0; fj < 4; fj++)
                LDMX2(Bhf[fj], bk + fj * (8 * APITCH * 2));
            #pragma unroll
            for (int fi = 0; fi < 4; fi++)
                #pragma unroll
                for (int fj = 0; fj < 4; fj++)
                    MMA16816(acc[fi][fj], Ahf[fi], Bhf[fj]);

            #pragma unroll
            for (int fj = 0; fj < 4; fj++)
                LDMX2(Blf[fj], bk + TILE_B + fj * (8 * APITCH * 2));
            #pragma unroll
            for (int fi = 0; fi < 4; fi++)
                #pragma unroll
                for (int fj = 0; fj < 4; fj++)
                    MMA16816(acc[fi][fj], Ahf[fi], Blf[fj]);
        }
    }

    gemm_epilogue(acc, bias, Cf, Coh, m0, n0, warp_m, warp_n, lane, N, relu);
}

// ---------------- embed ----------------
__global__ void embed_kernel(const int* __restrict__ q_data,
                             const int* __restrict__ target,
                             const float* __restrict__ pe,
                             const float* __restrict__ q_emb,
                             const float* __restrict__ qa_emb) {
    size_t idx = (size_t)blockIdx.x * blockDim.x + threadIdx.x;
    if (idx >= (size_t)Mr * Dc) return;
    int bs = (int)(idx / Dc);
    int d  = (int)(idx % Dc);
    int s  = bs % Sc;
    float qe = q_emb[(size_t)q_data[bs] * Dc + d];
    float p  = pe[(size_t)s * Dc + d];
    float x  = qe + p;
    float y  = qa_emb[(size_t)target[bs] * Dc + d] + qe + p;
    g_qe[idx] = qe;
    g_x [idx] = x;
    g_xh[idx] = __float2half_rn(x);
    g_yh[idx] = __float2half_rn(y);
}

// ---------------- tensor-core flash attention ----------------
__global__ __launch_bounds__(128)
void attn_tc_kernel() {
    const int qt = blockIdx.x, hh = blockIdx.y, b = blockIdx.z;
    const int tid = threadIdx.x;
    const int w = tid >> 5, lane = tid & 31;
    const int r8 = lane & 7, sub = lane >> 3;
    const int quad = lane >> 2, tq = lane & 3;

    __shared__ __half Qs[64][72];
    __shared__ __half Ks[64][72];
    __shared__ __half Vs[64][72];
    const uint32_t sQ = smem_u32(&Qs[0][0]);
    const uint32_t sK = smem_u32(&Ks[0][0]);
    const uint32_t sV = smem_u32(&Vs[0][0]);

    {
        const __half* src = g_Kh + ((size_t)(b * Sc + qt * 64)) * Dc + hh * DKc;
        const __half2 s8 = __half2half2(__float2half_rn(0.125f));
        #pragma unroll
        for (int p = 0; p < 4; p++) {
            int c = p * 128 + tid;
            int row = c >> 3, col = (c & 7) * 8;
            uint4 v = *(const uint4*)(src + (size_t)row * Dc + col);
            __half2* hv = (__half2*)&v;
            hv[0] = __hmul2(hv[0], s8); hv[1] = __hmul2(hv[1], s8);
            hv[2] = __hmul2(hv[2], s8); hv[3] = __hmul2(hv[3], s8);
            *(uint4*)&Qs[row][col] = v;
        }
    }
    __syncthreads();

    uint32_t Qf[4][4];
    #pragma unroll
    for (int ks = 0; ks < 4; ks++)
        LDMX4(Qf[ks], sQ + (uint32_t)(((w * 16 + r8 + (sub & 1) * 8) * 72 +
                                       ks * 16 + (sub >> 1) * 8) * 2));

    float out[8][4];
    #pragma unroll
    for (int f = 0; f < 8; f++)
        #pragma unroll
        for (int e = 0; e < 4; e++) out[f][e] = 0.f;
    float m0 = -1e30f, m1 = -1e30f, l0 = 0.f, l1 = 0.f;
    const int il0 = w * 16 + quad;

    for (int jt = 0; jt <= qt; jt++) {
        __syncthreads();
        const __half* ksrc = g_Kh + ((size_t)(b * Sc + jt * 64)) * Dc + hh * DKc;
        const __half* vsrc = g_Vh + ((size_t)(b * Sc + jt * 64)) * Dc + hh * DKc;
        #pragma unroll
        for (int p = 0; p < 4; p++) {
            int c = p * 128 + tid;
            int row = c >> 3, col = (c & 7) * 8;
            *(uint4*)&Ks[row][col] = *(const uint4*)(ksrc + (size_t)row * Dc + col);
            *(uint4*)&Vs[row][col] = *(const uint4*)(vsrc + (size_t)row * Dc + col);
        }
        __syncthreads();

        float sc[8][4];
        #pragma unroll
        for (int f = 0; f < 8; f++)
            #pragma unroll
            for (int e = 0; e < 4; e++) sc[f][e] = 0.f;
        #pragma unroll
        for (int ks = 0; ks < 4; ks++) {
            #pragma unroll
            for (int nf2 = 0; nf2 < 4; nf2++) {
                uint32_t Kf[4];
                LDMX4(Kf, sK + (uint32_t)(((nf2 * 16 + (sub >> 1) * 8 + r8) * 72 +
                                           ks * 16 + (sub & 1) * 8) * 2));
                MMA16816(sc[nf2 * 2],     Qf[ks], (Kf));
                MMA16816(sc[nf2 * 2 + 1], Qf[ks], (Kf + 2));
            }
        }

        if (jt == qt) {
            #pragma unroll
            for (int nf = 0; nf < 8; nf++) {
                int jl = nf * 8 + 2 * tq;
                if (jl     >= il0)     sc[nf][0] = -1e30f;
                if (jl + 1 >= il0)     sc[nf][1] = -1e30f;
                if (jl     >= il0 + 8) sc[nf][2] = -1e30f;
                if (jl + 1 >= il0 + 8) sc[nf][3] = -1e30f;
            }
        }

        float mt0 = -1e30f, mt1 = -1e30f;
        #pragma unroll
        for (int nf = 0; nf < 8; nf++) {
            mt0 = fmaxf(mt0, fmaxf(sc[nf][0], sc[nf][1]));
            mt1 = fmaxf(mt1, fmaxf(sc[nf][2], sc[nf][3]));
        }
        mt0 = fmaxf(mt0, __shfl_xor_sync(0xffffffffu, mt0, 1));
        mt0 = fmaxf(mt0, __shfl_xor_sync(0xffffffffu, mt0, 2));
        mt1 = fmaxf(mt1, __shfl_xor_sync(0xffffffffu, mt1, 1));
        mt1 = fmaxf(mt1, __shfl_xor_sync(0xffffffffu, mt1, 2));
        float mn0 = fmaxf(m0, mt0), mn1 = fmaxf(m1, mt1);
        float corr0 = __expf(m0 - mn0), corr1 = __expf(m1 - mn1);
        m0 = mn0; m1 = mn1;

        uint32_t Pa[4][4];
        float la0 = 0.f, la1 = 0.f;
        #pragma unroll
        for (int nf = 0; nf < 8; nf++) {
            float p0 = __expf(sc[nf][0] - mn0);
            float p1 = __expf(sc[nf][1] - mn0);
            float p2 = __expf(sc[nf][2] - mn1);
            float p3 = __expf(sc[nf][3] - mn1);
            la0 += p0 + p1; la1 += p2 + p3;
            __half2 h01 = __floats2half2_rn(p0, p1);
            __half2 h23 = __floats2half2_rn(p2, p3);
            Pa[nf >> 1][(nf & 1) * 2 + 0] = *(uint32_t*)&h01;
            Pa[nf >> 1][(nf & 1) * 2 + 1] = *(uint32_t*)&h23;
        }
        l0 = l0 * corr0 + la0;
        l1 = l1 * corr1 + la1;
        #pragma unroll
        for (int f = 0; f < 8; f++) {
            out[f][0] *= corr0; out[f][1] *= corr0;
            out[f][2] *= corr1; out[f][3] *= corr1;
        }

        #pragma unroll
        for (int ks = 0; ks < 4; ks++) {
            #pragma unroll
            for (int df2 = 0; df2 < 4; df2++) {
                uint32_t Vf[4];
                LDMX4T(Vf, sV + (uint32_t)(((ks * 16 + (sub & 1) * 8 + r8) * 72 +
                                            df2 * 16 + (sub >> 1) * 8) * 2));
                MMA16816(out[df2 * 2],     Pa[ks], (Vf));
                MMA16816(out[df2 * 2 + 1], Pa[ks], (Vf + 2));
            }
        }
    }

    l0 += __shfl_xor_sync(0xffffffffu, l0, 1);
    l0 += __shfl_xor_sync(0xffffffffu, l0, 2);
    l1 += __shfl_xor_sync(0xffffffffu, l1, 1);
    l1 += __shfl_xor_sync(0xffffffffu, l1, 2);
    const int gi0 = qt * 64 + il0;
    const float inv0 = (gi0 > 0) ? 1.f / l0 : 0.f;
    const float inv1 = 1.f / l1;
    __half* dst = g_Oh + ((size_t)(b * Sc + gi0)) * Dc + hh * DKc;
    #pragma unroll
    for (int df = 0; df < 8; df++) {
        int col = df * 8 + 2 * tq;
        *(__half2*)(dst + col) =
            __floats2half2_rn(out[df][0] * inv0, out[df][1] * inv0);
        *(__half2*)(dst + (size_t)8 * Dc + col) =
            __floats2half2_rn(out[df][2] * inv1, out[df][3] * inv1);
    }
}

// ---------------- warp-per-row add + LayerNorm (+ fp16 hi out) --------------
// 256 threads = 8 warps, one row per warp; pure shuffle reductions.
__global__ __launch_bounds__(256)
void add_ln_kernel(float* __restrict__ x, const float* __restrict__ resid,
                   const float* __restrict__ g, const float* __restrict__ b) {
    const int warp = threadIdx.x >> 5, lane = threadIdx.x & 31;
    const int row = blockIdx.x * 8 + warp;
    const size_t base = (size_t)row * Dc;
    const int c0 = lane * 4;

    float v[16];
    float s = 0.f, ss = 0.f;
    #pragma unroll
    for (int p = 0; p < 4; p++) {
        float4 a = *(const float4*)(x + base + c0 + p * 128);
        float4 r = *(const float4*)(resid + base + c0 + p * 128);
        float t0 = a.x + r.x, t1 = a.y + r.y, t2 = a.z + r.z, t3 = a.w + r.w;
        v[p * 4 + 0] = t0; v[p * 4 + 1] = t1; v[p * 4 + 2] = t2; v[p * 4 + 3] = t3;
        s  += (t0 + t1) + (t2 + t3);
        ss += (t0 * t0 + t1 * t1) + (t2 * t2 + t3 * t3);
    }
    #pragma unroll
    for (int o = 16; o > 0; o >>= 1) {
        s  += __shfl_xor_sync(0xffffffffu, s, o);
        ss += __shfl_xor_sync(0xffffffffu, ss, o);
    }
    float mean = s * (1.f / 512.f);
    float var  = ss * (1.f / 512.f) - mean * mean;
    float rstd = rsqrtf(var + 1e-5f);

    #pragma unroll
    for (int p = 0; p < 4; p++) {
        float4 gg = *(const float4*)(g + c0 + p * 128);
        float4 bb = *(const float4*)(b + c0 + p * 128);
        float o0 = (v[p*4+0] - mean) * rstd * gg.x + bb.x;
        float o1 = (v[p*4+1] - mean) * rstd * gg.y + bb.y;
        float o2 = (v[p*4+2] - mean) * rstd * gg.z + bb.z;
        float o3 = (v[p*4+3] - mean) * rstd * gg.w + bb.w;
        *(float4*)(x + base + c0 + p * 128) = make_float4(o0, o1, o2, o3);
        *(__half2*)(g_xh + base + c0 + p * 128)     = __floats2half2_rn(o0, o1);
        *(__half2*)(g_xh + base + c0 + p * 128 + 2) = __floats2half2_rn(o2, o3);
    }
}

// ---------------- concat [x | qe] -> fp16 hi ----------------
__global__ void concat_kernel() {
    size_t idx = (size_t)blockIdx.x * blockDim.x + threadIdx.x;
    if (idx >= (size_t)Mr * 2 * Dc) return;
    int bs = (int)(idx / (2 * Dc));
    int c  = (int)(idx % (2 * Dc));
    float v = (c < Dc) ? g_x[(size_t)bs * Dc + c]
                       : g_qe[(size_t)bs * Dc + (c - Dc)];
    g_Ch[idx] = __float2half_rn(v);
}

// ---------------- host ----------------
static inline void split_w(const float* W, __half* oh, __half* ol,
                           int K, int N, int Npad) {
    split_w_kernel<<<dim3(Npad / 32, K / 32), dim3(32, 8)>>>(W, oh, ol, K, N);
}
static inline void gemm1F32(const __half* ah, const __half* bh,
                            const float* bias, float* C, int K, int N, int Npad,
                            int relu) {
    gemm1_mma_kernel<<<dim3(Npad / 128, Mr / 128, 1), 256, GEMM1_DSMEM>>>(
        ah, bh, bias, C, nullptr, nullptr, nullptr, nullptr, nullptr, K, N, relu);
}
static inline void gemm1F16(const __half* ah, const __half* bh,
                            const float* bias, __half* oh, int K, int N,
                            int Npad, int relu) {
    gemm1_mma_kernel<<<dim3(Npad / 128, Mr / 128, 1), 256, GEMM1_DSMEM>>>(
        ah, bh, bias, nullptr, oh, nullptr, nullptr, nullptr, nullptr, K, N, relu);
}
// merged dual fp16 GEMM (z = 0/1 selects operand set)
static inline void gemmDualF16(const __half* a1, const __half* b1,
                               const float* bias1, __half* o1,
                               const __half* a2, const __half* b2,
                               const float* bias2, __half* o2,
                               int K, int N, int Npad) {
    gemm1_mma_kernel<<<dim3(Npad / 128, Mr / 128, 2), 256, GEMM1_DSMEM>>>(
        a1, b1, bias1, nullptr, o1, a2, b2, bias2, o2, K, N, 0);
}
static inline void gemm2F32(const __half* ah, const __half* bh, const __half* bl,
                            const float* bias, float* C, int K, int N, int Npad,
                            int relu) {
    gemm2_mma_kernel<<<dim3(Npad / 128, Mr / 128), 256, GEMM2_DSMEM>>>(
        ah, bh, bl, bias, C, nullptr, K, N, relu);
}
static inline void gemm2F16(const __half* ah, const __half* bh, const __half* bl,
                            const float* bias, __half* oh, int K, int N,
                            int Npad, int relu) {
    gemm2_mma_kernel<<<dim3(Npad / 128, Mr / 128), 256, GEMM2_DSMEM>>>(
        ah, bh, bl, bias, nullptr, oh, K, N, relu);
}

extern "C" void kernel_launch(void* const* d_in, const int* in_sizes, int n_in,
                              void* d_out, int out_size) {
    const int*   q_data = (const int*)d_in[0];
    const int*   target = (const int*)d_in[1];
    const float* pe     = (const float*)d_in[2];
    const float* q_emb  = (const float*)d_in[3];
    const float* qa_emb = (const float*)d_in[4];
    const float* Wk     = (const float*)d_in[5];
    const float* bk     = (const float*)d_in[6];
    const float* Wv     = (const float*)d_in[7];
    const float* bv     = (const float*)d_in[8];
    const float* Wo     = (const float*)d_in[9];
    const float* bo     = (const float*)d_in[10];
    const float* ln1_g  = (const float*)d_in[11];
    const float* ln1_b  = (const float*)d_in[12];
    const float* W1     = (const float*)d_in[13];
    const float* b1     = (const float*)d_in[14];
    const float* W2     = (const float*)d_in[15];
    const float* b2     = (const float*)d_in[16];
    const float* ln2_g  = (const float*)d_in[17];
    const float* ln2_b  = (const float*)d_in[18];
    const float* Wout1  = (const float*)d_in[19];
    const float* bout1  = (const float*)d_in[20];
    const float* Wout2  = (const float*)d_in[21];
    const float* bout2  = (const float*)d_in[22];
    const float* Wout3  = (const float*)d_in[23];
    const float* bout3  = (const float*)d_in[24];
    float* out = (float*)d_out;

    cudaFuncSetAttribute(gemm1_mma_kernel,
                         cudaFuncAttributeMaxDynamicSharedMemorySize, GEMM1_DSMEM);
    cudaFuncSetAttribute(gemm2_mma_kernel,
                         cudaFuncAttributeMaxDynamicSharedMemorySize, GEMM2_DSMEM);

    float *p_x, *p_P;
    cudaGetSymbolAddress((void**)&p_x, g_x);
    cudaGetSymbolAddress((void**)&p_P, g_P);

    __half *xh, *yh, *kh, *vh, *oh, *f1h, *ch, *h1h, *h2h;
    cudaGetSymbolAddress((void**)&xh, g_xh);
    cudaGetSymbolAddress((void**)&yh, g_yh);
    cudaGetSymbolAddress((void**)&kh, g_Kh);
    cudaGetSymbolAddress((void**)&vh, g_Vh);
    cudaGetSymbolAddress((void**)&oh, g_Oh);
    cudaGetSymbolAddress((void**)&f1h, g_F1h);
    cudaGetSymbolAddress((void**)&ch, g_Ch);
    cudaGetSymbolAddress((void**)&h1h, g_H1h);
    cudaGetSymbolAddress((void**)&h2h, g_H2h);

    __half *wk_h, *wv_h, *wo_h, *w1_h, *w2_h;
    __half *wo1_h, *wo1_l, *wo2_h, *wo2_l, *wo3_h, *wo3_l;
    cudaGetSymbolAddress((void**)&wk_h, g_Wk_h);
    cudaGetSymbolAddress((void**)&wv_h, g_Wv_h);
    cudaGetSymbolAddress((void**)&wo_h, g_Wo_h);
    cudaGetSymbolAddress((void**)&w1_h, g_W1_h);
    cudaGetSymbolAddress((void**)&w2_h, g_W2_h);
    cudaGetSymbolAddress((void**)&wo1_h, g_Wo1_h); cudaGetSymbolAddress((void**)&wo1_l, g_Wo1_l);
    cudaGetSymbolAddress((void**)&wo2_h, g_Wo2_h); cudaGetSymbolAddress((void**)&wo2_l, g_Wo2_l);
    cudaGetSymbolAddress((void**)&wo3_h, g_Wo3_h); cudaGetSymbolAddress((void**)&wo3_l, g_Wo3_l);

    // launch order: #6 is the merged K/V GEMM (profiled by ncu -s 5 -c 1)
    {
        size_t tot = (size_t)Mr * Dc;
        embed_kernel<<<(unsigned)((tot + 255) / 256), 256>>>(q_data, target, pe,
                                                             q_emb, qa_emb);   // 1
    }
    split_w(Wk, wk_h, nullptr, Dc, Dc, Dc);                                    // 2
    split_w(Wv, wv_h, nullptr, Dc, Dc, Dc);                                    // 3
    split_w(Wo, wo_h, nullptr, Dc, Dc, Dc);                                    // 4
    split_w(W1, w1_h, nullptr, Dc, DFFc, DFFc);                                // 5
    gemmDualF16(xh, wk_h, bk, kh, yh, wv_h, bv, vh, Dc, Dc, Dc);               // 6
    split_w(W2, w2_h, nullptr, DFFc, Dc, Dc);                                  // 7
    for (int l = 1; l < Lc; l++) {
        size_t oDD = (size_t)l * Dc * Dc;
        size_t oDF = (size_t)l * Dc * DFFc;
        split_w(Wk + oDD, wk_h + oDD, nullptr, Dc, Dc, Dc);
        split_w(Wv + oDD, wv_h + oDD, nullptr, Dc, Dc, Dc);
        split_w(Wo + oDD, wo_h + oDD, nullptr, Dc, Dc, Dc);
        split_w(W1 + oDF, w1_h + oDF, nullptr, Dc, DFFc, DFFc);
        split_w(W2 + oDF, w2_h + oDF, nullptr, DFFc, Dc, Dc);
    }
    split_w(Wout1, wo1_h, wo1_l, 2 * Dc, FC1c, FC1c);
    split_w(Wout2, wo2_h, wo2_l, FC1c, FC2c, FC2c);
    split_w(Wout3, wo3_h, wo3_l, FC2c, NSKc, NSKp);

    // transformer layers (layer 0 K/V already launched)
    for (int l = 0; l < Lc; l++) {
        size_t oDD = (size_t)l * Dc * Dc;
        size_t oDF = (size_t)l * Dc * DFFc;
        if (l > 0)
            gemmDualF16(xh, wk_h + oDD, bk + l * Dc, kh,
                        yh, wv_h + oDD, bv + l * Dc, vh, Dc, Dc, Dc);
        attn_tc_kernel<<<dim3(Sc / 64, Hc, Bc), 128>>>();
        gemm1F32(oh, wo_h + oDD, bo + l * Dc, p_P, Dc, Dc, Dc, 0);
        add_ln_kernel<<<Mr / 8, 256>>>(p_x, p_P, ln1_g + l * Dc, ln1_b + l * Dc);
        gemm1F16(xh, w1_h + oDF, b1 + l * DFFc, f1h, Dc, DFFc, DFFc, 1);
        gemm1F32(f1h, w2_h + oDF, b2 + l * Dc, p_P, DFFc, Dc, Dc, 0);
        add_ln_kernel<<<Mr / 8, 256>>>(p_x, p_P, ln2_g + l * Dc, ln2_b + l * Dc);
    }

    // head
    {
        size_t tot = (size_t)Mr * 2 * Dc;
        concat_kernel<<<(unsigned)((tot + 255) / 256), 256>>>();
    }
    gemm2F16(ch, wo1_h, wo1_l, bout1, h1h, 2 * Dc, FC1c, FC1c, 1);
    gemm2F16(h1h, wo2_h, wo2_l, bout2, h2h, FC1c, FC2c, FC2c, 1);
    gemm2F32(h2h, wo3_h, wo3_l, bout3, out, FC2c, NSKc, NSKp, 0);
}

// round 17
// speedup vs baseline: 4.0248x; 1.0324x over previous
#include <cuda_runtime.h>
#include <cuda_fp16.h>
#include <math.h>
#include <stdint.h>

#define Bc   64
#define Sc   512
#define Dc   512
#define Hc   8
#define DKc  64
#define Lc   4
#define DFFc 2048
#define NSKc 300
#define NSKp 384
#define FC1c 512
#define FC2c 256
#define Mr   (Bc * Sc)

// ---------------- fp32 scratch ----------------
__device__ float g_x [(size_t)Mr * Dc];
__device__ float g_P [(size_t)Mr * Dc];

// ---------------- fp16 activations (hi only) ----------------
__device__ __half g_xh [(size_t)Mr * Dc];
__device__ __half g_yh [(size_t)Mr * Dc];
__device__ __half g_Kh [(size_t)Mr * Dc];
__device__ __half g_Vh [(size_t)Mr * Dc];
__device__ __half g_Oh [(size_t)Mr * Dc];
__device__ __half g_F1h[(size_t)Mr * DFFc];
__device__ __half g_Ch [(size_t)Mr * 2 * Dc];
__device__ __half g_H1h[(size_t)Mr * FC1c];
__device__ __half g_H2h[(size_t)Mr * FC2c];

// ---------------- fp16 weights (transposed [N][K]) ----------------
__device__ __half g_Wk_h[(size_t)Lc * Dc * Dc];
__device__ __half g_Wv_h[(size_t)Lc * Dc * Dc];
__device__ __half g_Wo_h[(size_t)Lc * Dc * Dc];
__device__ __half g_W1_h[(size_t)Lc * Dc * DFFc];
__device__ __half g_W2_h[(size_t)Lc * DFFc * Dc];
__device__ __half g_Wo1_h[(size_t)2 * Dc * FC1c], g_Wo1_l[(size_t)2 * Dc * FC1c];
__device__ __half g_Wo2_h[(size_t)FC1c * FC2c],   g_Wo2_l[(size_t)FC1c * FC2c];
__device__ __half g_Wo3_h[(size_t)NSKp * FC2c],   g_Wo3_l[(size_t)NSKp * FC2c];

// ---------------- helpers ----------------
__device__ __forceinline__ uint32_t smem_u32(const void* p) {
    uint32_t a;
    asm("{ .reg .u64 t; cvta.to.shared.u64 t, %1; cvt.u32.u64 %0, t; }"
        : "=r"(a) : "l"(p));
    return a;
}
__device__ __forceinline__ void split2(float v, __half& h, __half& l) {
    h = __float2half_rn(v);
    l = __float2half_rn(v - __half2float(h));
}

#define CPA16(dst, src)                                                       \
    asm volatile("cp.async.cg.shared.global [%0], [%1], 16;"                  \
                 :: "r"(dst), "l"(src) : "memory")

#define LDMX4(R, addr)                                                        \
    asm volatile("ldmatrix.sync.aligned.m8n8.x4.shared.b16 {%0,%1,%2,%3}, [%4];" \
        : "=r"((R)[0]), "=r"((R)[1]), "=r"((R)[2]), "=r"((R)[3]) : "r"(addr))

#define LDMX4T(R, addr)                                                       \
    asm volatile("ldmatrix.sync.aligned.m8n8.x4.trans.shared.b16 {%0,%1,%2,%3}, [%4];" \
        : "=r"((R)[0]), "=r"((R)[1]), "=r"((R)[2]), "=r"((R)[3]) : "r"(addr))

#define LDMX2(R, addr)                                                        \
    asm volatile("ldmatrix.sync.aligned.m8n8.x2.shared.b16 {%0,%1}, [%2];"    \
        : "=r"((R)[0]), "=r"((R)[1]) : "r"(addr))

#define MMA16816(d, a, b)                                                     \
    asm volatile("mma.sync.aligned.m16n8k16.row.col.f32.f16.f16.f32 "         \
        "{%0,%1,%2,%3}, {%4,%5,%6,%7}, {%8,%9}, {%0,%1,%2,%3};"               \
        : "+f"((d)[0]), "+f"((d)[1]), "+f"((d)[2]), "+f"((d)[3])              \
        : "r"((a)[0]), "r"((a)[1]), "r"((a)[2]), "r"((a)[3]),                 \
          "r"((b)[0]), "r"((b)[1]))

// ---------------- weight prep ----------------
// hi-only, batched over layers via blockIdx.z (src/dst contiguous [L,K,N]).
__global__ void split_w_batch_kernel(const float* __restrict__ W,
                                     __half* __restrict__ Oh, int K, int N) {
    __shared__ float t[32][33];
    const size_t zoff = (size_t)blockIdx.z * K * N;
    int k0 = blockIdx.y * 32, n0 = blockIdx.x * 32;
    #pragma unroll
    for (int i = 0; i < 4; i++) {
        int k = k0 + threadIdx.y + i * 8;
        int n = n0 + threadIdx.x;
        t[threadIdx.y + i * 8][threadIdx.x] = W[zoff + (size_t)k * N + n];
    }
    __syncthreads();
    #pragma unroll
    for (int i = 0; i < 4; i++) {
        int n = n0 + threadIdx.y + i * 8;
        int k = k0 + threadIdx.x;
        Oh[zoff + (size_t)n * K + k] =
            __float2half_rn(t[threadIdx.x][threadIdx.y + i * 8]);
    }
}

// hi+lo (head weights), single tensor, zero-padded rows beyond N.
__global__ void split_w_kernel(const float* __restrict__ W,
                               __half* __restrict__ Oh, __half* __restrict__ Ol,
                               int K, int N) {
    __shared__ float t[32][33];
    int k0 = blockIdx.y * 32, n0 = blockIdx.x * 32;
    #pragma unroll
    for (int i = 0; i < 4; i++) {
        int k = k0 + threadIdx.y + i * 8;
        int n = n0 + threadIdx.x;
        t[threadIdx.y + i * 8][threadIdx.x] = (n < N) ? W[(size_t)k * N + n] : 0.f;
    }
    __syncthreads();
    #pragma unroll
    for (int i = 0; i < 4; i++) {
        int n = n0 + threadIdx.y + i * 8;
        int k = k0 + threadIdx.x;
        float v = t[threadIdx.x][threadIdx.y + i * 8];
        __half h, l; split2(v, h, l);
        Oh[(size_t)n * K + k] = h;
        Ol[(size_t)n * K + k] = l;
    }
}

// BK = 64: rows of 64 halfs (128 B) + 16 B pad -> APITCH 72 halfs (144 B)
#define APITCH 72
#define TILE_B (128 * APITCH * 2)     // 18432

// ---- shared epilogue ----
__device__ __forceinline__ void gemm_epilogue(
    float acc[4][4][4], const float* bias, float* Cf, __half* Coh,
    int m0, int n0, int warp_m, int warp_n, int lane, int N, int relu) {
    #pragma unroll
    for (int fj = 0; fj < 4; fj++) {
        const int c0 = n0 + warp_n + fj * 8 + 2 * (lane & 3);
        const bool c0ok = (c0 < N), c1ok = (c0 + 1 < N);
        const float b0 = c0ok ? bias[c0] : 0.f;
        const float b1 = c1ok ? bias[c0 + 1] : 0.f;
        #pragma unroll
        for (int fi = 0; fi < 4; fi++) {
            const int r0 = m0 + warp_m + fi * 16 + (lane >> 2);
            float v0 = acc[fi][fj][0] + b0;
            float v1 = acc[fi][fj][1] + b1;
            float v2 = acc[fi][fj][2] + b0;
            float v3 = acc[fi][fj][3] + b1;
            if (relu) {
                v0 = fmaxf(v0, 0.f); v1 = fmaxf(v1, 0.f);
                v2 = fmaxf(v2, 0.f); v3 = fmaxf(v3, 0.f);
            }
            if (Cf) {
                if (c1ok) {
                    *(float2*)(Cf + (size_t)r0 * N + c0)       = make_float2(v0, v1);
                    *(float2*)(Cf + (size_t)(r0 + 8) * N + c0) = make_float2(v2, v3);
                } else if (c0ok) {
                    Cf[(size_t)r0 * N + c0]       = v0;
                    Cf[(size_t)(r0 + 8) * N + c0] = v2;
                }
            } else {
                if (c1ok) {
                    *(__half2*)(Coh + (size_t)r0 * N + c0) =
                        __halves2half2(__float2half_rn(v0), __float2half_rn(v1));
                    *(__half2*)(Coh + (size_t)(r0 + 8) * N + c0) =
                        __halves2half2(__float2half_rn(v2), __float2half_rn(v3));
                } else if (c0ok) {
                    Coh[(size_t)r0 * N + c0]       = __float2half_rn(v0);
                    Coh[(size_t)(r0 + 8) * N + c0] = __float2half_rn(v2);
                }
            }
        }
    }
}

// ================= 1-term GEMM (z-select second operand set) ================
#define STAGE1_B (2 * TILE_B)
#define GEMM1_DSMEM (2 * STAGE1_B)

__device__ __forceinline__ void issue_stage1(
    uint32_t sb, const __half* Ah_g, const __half* Bh_g,
    int m0, int n0, int K, int kk, int tid) {
    #pragma unroll
    for (int p = 0; p < 4; p++) {
        int c = p * 256 + tid;
        int row = c >> 3, q = c & 7;
        uint32_t d = sb + (uint32_t)(row * 144 + q * 16);
        size_t ao = (size_t)(m0 + row) * K + kk + q * 8;
        size_t bo = (size_t)(n0 + row) * K + kk + q * 8;
        CPA16(d,          Ah_g + ao);
        CPA16(d + TILE_B, Bh_g + bo);
    }
    asm volatile("cp.async.commit_group;" ::: "memory");
}

__global__ __launch_bounds__(256, 2)
void gemm1_mma_kernel(const __half* __restrict__ Ah_g,
                      const __half* __restrict__ Bh_g,
                      const float* __restrict__ bias,
                      float* __restrict__ Cf,
                      __half* __restrict__ Coh,
                      const __half* __restrict__ Ah2,
                      const __half* __restrict__ Bh2,
                      const float* __restrict__ bias2,
                      __half* __restrict__ Coh2,
                      int K, int N, int relu) {
    if (blockIdx.z) {
        Ah_g = Ah2; Bh_g = Bh2; bias = bias2; Coh = Coh2; Cf = nullptr;
    }
    extern __shared__ char smem[];
    const int tid  = threadIdx.x;
    const int wid  = tid >> 5;
    const int lane = tid & 31;
    const int m0 = blockIdx.y * 128;
    const int n0 = blockIdx.x * 128;
    const int warp_m = (wid >> 2) * 64;
    const int warp_n = (wid & 3) * 32;

    const uint32_t sbase = smem_u32(smem);

    float acc[4][4][4];
    #pragma unroll
    for (int i = 0; i < 4; i++)
        #pragma unroll
        for (int j = 0; j < 4; j++)
            #pragma unroll
            for (int e = 0; e < 4; e++) acc[i][j][e] = 0.f;

    const int KT = K >> 6;
    const int r8  = lane & 7;
    const int sub = lane >> 3;
    const uint32_t a_lane_off =
        (uint32_t)(((warp_m + r8 + (sub & 1) * 8) * APITCH + (sub >> 1) * 8) * 2);
    const uint32_t b_lane_off =
        (uint32_t)(((warp_n + r8) * APITCH + (sub & 1) * 8) * 2);

    issue_stage1(sbase, Ah_g, Bh_g, m0, n0, K, 0, tid);

    for (int kt = 0; kt < KT; kt++) {
        asm volatile("cp.async.wait_group 0;" ::: "memory");
        __syncthreads();
        if (kt + 1 < KT)
            issue_stage1(sbase + ((kt + 1) & 1) * STAGE1_B, Ah_g, Bh_g,
                         m0, n0, K, (kt + 1) << 6, tid);

        const uint32_t stoff = (kt & 1) * STAGE1_B;
        const uint32_t abase = sbase + stoff + a_lane_off;
        const uint32_t bbase = sbase + stoff + TILE_B + b_lane_off;

        #pragma unroll
        for (int ks = 0; ks < 4; ks++) {
            const uint32_t ak = abase + ks * 32;
            const uint32_t bk = bbase + ks * 32;

            uint32_t Ahf[4][4], Bhf[4][2];
            #pragma unroll
            for (int fi = 0; fi < 4; fi++)
                LDMX4(Ahf[fi], ak + fi * (16 * APITCH * 2));
            #pragma unroll
            for (int fj = 0; fj < 4; fj++)
                LDMX2(Bhf[fj], bk + fj * (8 * APITCH * 2));
            #pragma unroll
            for (int fi = 0; fi < 4; fi++)
                #pragma unroll
                for (int fj = 0; fj < 4; fj++)
                    MMA16816(acc[fi][fj], Ahf[fi], Bhf[fj]);
        }
    }

    gemm_epilogue(acc, bias, Cf, Coh, m0, n0, warp_m, warp_n, lane, N, relu);
}

// ================= 2-term GEMM (head) =================
#define STAGE2_B (3 * TILE_B)
#define GEMM2_DSMEM (2 * STAGE2_B)

__device__ __forceinline__ void issue_stage2(
    uint32_t sb, const __half* Ah_g, const __half* Bh_g, const __half* Bl_g,
    int m0, int n0, int K, int kk, int tid) {
    #pragma unroll
    for (int p = 0; p < 4; p++) {
        int c = p * 256 + tid;
        int row = c >> 3, q = c & 7;
        uint32_t d = sb + (uint32_t)(row * 144 + q * 16);
        size_t ao = (size_t)(m0 + row) * K + kk + q * 8;
        size_t bo = (size_t)(n0 + row) * K + kk + q * 8;
        CPA16(d,              Ah_g + ao);
        CPA16(d + TILE_B,     Bh_g + bo);
        CPA16(d + 2 * TILE_B, Bl_g + bo);
    }
    asm volatile("cp.async.commit_group;" ::: "memory");
}

__global__ __launch_bounds__(256, 2)
void gemm2_mma_kernel(const __half* __restrict__ Ah_g,
                      const __half* __restrict__ Bh_g,
                      const __half* __restrict__ Bl_g,
                      const float* __restrict__ bias,
                      float* __restrict__ Cf,
                      __half* __restrict__ Coh,
                      int K, int N, int relu) {
    extern __shared__ char smem[];
    const int tid  = threadIdx.x;
    const int wid  = tid >> 5;
    const int lane = tid & 31;
    const int m0 = blockIdx.y * 128;
    const int n0 = blockIdx.x * 128;
    const int warp_m = (wid >> 2) * 64;
    const int warp_n = (wid & 3) * 32;

    const uint32_t sbase = smem_u32(smem);

    float acc[4][4][4];
    #pragma unroll
    for (int i = 0; i < 4; i++)
        #pragma unroll
        for (int j = 0; j < 4; j++)
            #pragma unroll
            for (int e = 0; e < 4; e++) acc[i][j][e] = 0.f;

    const int KT = K >> 6;
    const int r8  = lane & 7;
    const int sub = lane >> 3;
    const uint32_t a_lane_off =
        (uint32_t)(((warp_m + r8 + (sub & 1) * 8) * APITCH + (sub >> 1) * 8) * 2);
    const uint32_t b_lane_off =
        (uint32_t)(((warp_n + r8) * APITCH + (sub & 1) * 8) * 2);

    issue_stage2(sbase, Ah_g, Bh_g, Bl_g, m0, n0, K, 0, tid);

    for (int kt = 0; kt < KT; kt++) {
        asm volatile("cp.async.wait_group 0;" ::: "memory");
        __syncthreads();
        if (kt + 1 < KT)
            issue_stage2(sbase + ((kt + 1) & 1) * STAGE2_B, Ah_g, Bh_g, Bl_g,
                         m0, n0, K, (kt + 1) << 6, tid);

        const uint32_t stoff = (kt & 1) * STAGE2_B;
        const uint32_t abase = sbase + stoff + a_lane_off;
        const uint32_t bbase = sbase + stoff + TILE_B + b_lane_off;

        #pragma unroll
        for (int ks = 0; ks < 4; ks++) {
            const uint32_t ak = abase + ks * 32;
            const uint32_t bk = bbase + ks * 32;

            uint32_t Ahf[4][4], Bhf[4][2], Blf[4][2];
            #pragma unroll
            for (int fi = 0; fi < 4; fi++)
                LDMX4(Ahf[fi], ak + fi * (16 * APITCH * 2));
            #pragma unroll
            for (int fj = 0; fj < 4; fj++)
                LDMX2(Bhf[fj], bk + fj * (8 * APITCH * 2));
            #pragma unroll
            for (int fi = 0; fi < 4; fi++)
                #pragma unroll
                for (int fj = 0; fj < 4; fj++)
                    MMA16816(acc[fi][fj], Ahf[fi], Bhf[fj]);

            #pragma unroll
            for (int fj = 0; fj < 4; fj++)
                LDMX2(Blf[fj], bk + TILE_B + fj * (8 * APITCH * 2));
            #pragma unroll
            for (int fi = 0; fi < 4; fi++)
                #pragma unroll
                for (int fj = 0; fj < 4; fj++)
                    MMA16816(acc[fi][fj], Ahf[fi], Blf[fj]);
        }
    }

    gemm_epilogue(acc, bias, Cf, Coh, m0, n0, warp_m, warp_n, lane, N, relu);
}

// ---------------- embed (also fills Ch second half with qe) ----------------
__global__ void embed_kernel(const int* __restrict__ q_data,
                             const int* __restrict__ target,
                             const float* __restrict__ pe,
                             const float* __restrict__ q_emb,
                             const float* __restrict__ qa_emb) {
    size_t idx = (size_t)blockIdx.x * blockDim.x + threadIdx.x;
    if (idx >= (size_t)Mr * Dc) return;
    int bs = (int)(idx / Dc);
    int d  = (int)(idx % Dc);
    int s  = bs % Sc;
    float qe = q_emb[(size_t)q_data[bs] * Dc + d];
    float p  = pe[(size_t)s * Dc + d];
    float x  = qe + p;
    float y  = qa_emb[(size_t)target[bs] * Dc + d] + qe + p;
    g_x [idx] = x;
    g_xh[idx] = __float2half_rn(x);
    g_yh[idx] = __float2half_rn(y);
    g_Ch[(size_t)bs * 2 * Dc + Dc + d] = __float2half_rn(qe);
}

// ---------------- tensor-core flash attention ----------------
__global__ __launch_bounds__(128)
void attn_tc_kernel() {
    const int qt = blockIdx.x, hh = blockIdx.y, b = blockIdx.z;
    const int tid = threadIdx.x;
    const int w = tid >> 5, lane = tid & 31;
    const int r8 = lane & 7, sub = lane >> 3;
    const int quad = lane >> 2, tq = lane & 3;

    __shared__ __half Qs[64][72];
    __shared__ __half Ks[64][72];
    __shared__ __half Vs[64][72];
    const uint32_t sQ = smem_u32(&Qs[0][0]);
    const uint32_t sK = smem_u32(&Ks[0][0]);
    const uint32_t sV = smem_u32(&Vs[0][0]);

    {
        const __half* src = g_Kh + ((size_t)(b * Sc + qt * 64)) * Dc + hh * DKc;
        const __half2 s8 = __half2half2(__float2half_rn(0.125f));
        #pragma unroll
        for (int p = 0; p < 4; p++) {
            int c = p * 128 + tid;
            int row = c >> 3, col = (c & 7) * 8;
            uint4 v = *(const uint4*)(src + (size_t)row * Dc + col);
            __half2* hv = (__half2*)&v;
            hv[0] = __hmul2(hv[0], s8); hv[1] = __hmul2(hv[1], s8);
            hv[2] = __hmul2(hv[2], s8); hv[3] = __hmul2(hv[3], s8);
            *(uint4*)&Qs[row][col] = v;
        }
    }
    __syncthreads();

    uint32_t Qf[4][4];
    #pragma unroll
    for (int ks = 0; ks < 4; ks++)
        LDMX4(Qf[ks], sQ + (uint32_t)(((w * 16 + r8 + (sub & 1) * 8) * 72 +
                                       ks * 16 + (sub >> 1) * 8) * 2));

    float out[8][4];
    #pragma unroll
    for (int f = 0; f < 8; f++)
        #pragma unroll
        for (int e = 0; e < 4; e++) out[f][e] = 0.f;
    float m0 = -1e30f, m1 = -1e30f, l0 = 0.f, l1 = 0.f;
    const int il0 = w * 16 + quad;

    for (int jt = 0; jt <= qt; jt++) {
        __syncthreads();
        const __half* ksrc = g_Kh + ((size_t)(b * Sc + jt * 64)) * Dc + hh * DKc;
        const __half* vsrc = g_Vh + ((size_t)(b * Sc + jt * 64)) * Dc + hh * DKc;
        #pragma unroll
        for (int p = 0; p < 4; p++) {
            int c = p * 128 + tid;
            int row = c >> 3, col = (c & 7) * 8;
            *(uint4*)&Ks[row][col] = *(const uint4*)(ksrc + (size_t)row * Dc + col);
            *(uint4*)&Vs[row][col] = *(const uint4*)(vsrc + (size_t)row * Dc + col);
        }
        __syncthreads();

        float sc[8][4];
        #pragma unroll
        for (int f = 0; f < 8; f++)
            #pragma unroll
            for (int e = 0; e < 4; e++) sc[f][e] = 0.f;
        #pragma unroll
        for (int ks = 0; ks < 4; ks++) {
            #pragma unroll
            for (int nf2 = 0; nf2 < 4; nf2++) {
                uint32_t Kf[4];
                LDMX4(Kf, sK + (uint32_t)(((nf2 * 16 + (sub >> 1) * 8 + r8) * 72 +
                                           ks * 16 + (sub & 1) * 8) * 2));
                MMA16816(sc[nf2 * 2],     Qf[ks], (Kf));
                MMA16816(sc[nf2 * 2 + 1], Qf[ks], (Kf + 2));
            }
        }

        if (jt == qt) {
            #pragma unroll
            for (int nf = 0; nf < 8; nf++) {
                int jl = nf * 8 + 2 * tq;
                if (jl     >= il0)     sc[nf][0] = -1e30f;
                if (jl + 1 >= il0)     sc[nf][1] = -1e30f;
                if (jl     >= il0 + 8) sc[nf][2] = -1e30f;
                if (jl + 1 >= il0 + 8) sc[nf][3] = -1e30f;
            }
        }

        float mt0 = -1e30f, mt1 = -1e30f;
        #pragma unroll
        for (int nf = 0; nf < 8; nf++) {
            mt0 = fmaxf(mt0, fmaxf(sc[nf][0], sc[nf][1]));
            mt1 = fmaxf(mt1, fmaxf(sc[nf][2], sc[nf][3]));
        }
        mt0 = fmaxf(mt0, __shfl_xor_sync(0xffffffffu, mt0, 1));
        mt0 = fmaxf(mt0, __shfl_xor_sync(0xffffffffu, mt0, 2));
        mt1 = fmaxf(mt1, __shfl_xor_sync(0xffffffffu, mt1, 1));
        mt1 = fmaxf(mt1, __shfl_xor_sync(0xffffffffu, mt1, 2));
        float mn0 = fmaxf(m0, mt0), mn1 = fmaxf(m1, mt1);
        float corr0 = __expf(m0 - mn0), corr1 = __expf(m1 - mn1);
        m0 = mn0; m1 = mn1;

        uint32_t Pa[4][4];
        float la0 = 0.f, la1 = 0.f;
        #pragma unroll
        for (int nf = 0; nf < 8; nf++) {
            float p0 = __expf(sc[nf][0] - mn0);
            float p1 = __expf(sc[nf][1] - mn0);
            float p2 = __expf(sc[nf][2] - mn1);
            float p3 = __expf(sc[nf][3] - mn1);
            la0 += p0 + p1; la1 += p2 + p3;
            __half2 h01 = __floats2half2_rn(p0, p1);
            __half2 h23 = __floats2half2_rn(p2, p3);
            Pa[nf >> 1][(nf & 1) * 2 + 0] = *(uint32_t*)&h01;
            Pa[nf >> 1][(nf & 1) * 2 + 1] = *(uint32_t*)&h23;
        }
        l0 = l0 * corr0 + la0;
        l1 = l1 * corr1 + la1;
        #pragma unroll
        for (int f = 0; f < 8; f++) {
            out[f][0] *= corr0; out[f][1] *= corr0;
            out[f][2] *= corr1; out[f][3] *= corr1;
        }

        #pragma unroll
        for (int ks = 0; ks < 4; ks++) {
            #pragma unroll
            for (int df2 = 0; df2 < 4; df2++) {
                uint32_t Vf[4];
                LDMX4T(Vf, sV + (uint32_t)(((ks * 16 + (sub & 1) * 8 + r8) * 72 +
                                            df2 * 16 + (sub >> 1) * 8) * 2));
                MMA16816(out[df2 * 2],     Pa[ks], (Vf));
                MMA16816(out[df2 * 2 + 1], Pa[ks], (Vf + 2));
            }
        }
    }

    l0 += __shfl_xor_sync(0xffffffffu, l0, 1);
    l0 += __shfl_xor_sync(0xffffffffu, l0, 2);
    l1 += __shfl_xor_sync(0xffffffffu, l1, 1);
    l1 += __shfl_xor_sync(0xffffffffu, l1, 2);
    const int gi0 = qt * 64 + il0;
    const float inv0 = (gi0 > 0) ? 1.f / l0 : 0.f;
    const float inv1 = 1.f / l1;
    __half* dst = g_Oh + ((size_t)(b * Sc + gi0)) * Dc + hh * DKc;
    #pragma unroll
    for (int df = 0; df < 8; df++) {
        int col = df * 8 + 2 * tq;
        *(__half2*)(dst + col) =
            __floats2half2_rn(out[df][0] * inv0, out[df][1] * inv0);
        *(__half2*)(dst + (size_t)8 * Dc + col) =
            __floats2half2_rn(out[df][2] * inv1, out[df][3] * inv1);
    }
}

// ---------------- warp-per-row add + LayerNorm (+ fp16 hi, opt Ch) ----------
__global__ __launch_bounds__(256)
void add_ln_kernel(float* __restrict__ x, const float* __restrict__ resid,
                   const float* __restrict__ g, const float* __restrict__ b,
                   __half* __restrict__ ch) {
    const int warp = threadIdx.x >> 5, lane = threadIdx.x & 31;
    const int row = blockIdx.x * 8 + warp;
    const size_t base = (size_t)row * Dc;
    const int c0 = lane * 4;

    float v[16];
    float s = 0.f, ss = 0.f;
    #pragma unroll
    for (int p = 0; p < 4; p++) {
        float4 a = *(const float4*)(x + base + c0 + p * 128);
        float4 r = *(const float4*)(resid + base + c0 + p * 128);
        float t0 = a.x + r.x, t1 = a.y + r.y, t2 = a.z + r.z, t3 = a.w + r.w;
        v[p * 4 + 0] = t0; v[p * 4 + 1] = t1; v[p * 4 + 2] = t2; v[p * 4 + 3] = t3;
        s  += (t0 + t1) + (t2 + t3);
        ss += (t0 * t0 + t1 * t1) + (t2 * t2 + t3 * t3);
    }
    #pragma unroll
    for (int o = 16; o > 0; o >>= 1) {
        s  += __shfl_xor_sync(0xffffffffu, s, o);
        ss += __shfl_xor_sync(0xffffffffu, ss, o);
    }
    float mean = s * (1.f / 512.f);
    float var  = ss * (1.f / 512.f) - mean * mean;
    float rstd = rsqrtf(var + 1e-5f);

    const size_t cbase = (size_t)row * 2 * Dc;
    #pragma unroll
    for (int p = 0; p < 4; p++) {
        float4 gg = *(const float4*)(g + c0 + p * 128);
        float4 bb = *(const float4*)(b + c0 + p * 128);
        float o0 = (v[p*4+0] - mean) * rstd * gg.x + bb.x;
        float o1 = (v[p*4+1] - mean) * rstd * gg.y + bb.y;
        float o2 = (v[p*4+2] - mean) * rstd * gg.z + bb.z;
        float o3 = (v[p*4+3] - mean) * rstd * gg.w + bb.w;
        *(float4*)(x + base + c0 + p * 128) = make_float4(o0, o1, o2, o3);
        __half2 h01 = __floats2half2_rn(o0, o1);
        __half2 h23 = __floats2half2_rn(o2, o3);
        *(__half2*)(g_xh + base + c0 + p * 128)     = h01;
        *(__half2*)(g_xh + base + c0 + p * 128 + 2) = h23;
        if (ch) {
            *(__half2*)(ch + cbase + c0 + p * 128)     = h01;
            *(__half2*)(ch + cbase + c0 + p * 128 + 2) = h23;
        }
    }
}

// ---------------- host ----------------
static inline void gemm1F32(const __half* ah, const __half* bh,
                            const float* bias, float* C, int K, int N, int Npad,
                            int relu) {
    gemm1_mma_kernel<<<dim3(Npad / 128, Mr / 128, 1), 256, GEMM1_DSMEM>>>(
        ah, bh, bias, C, nullptr, nullptr, nullptr, nullptr, nullptr, K, N, relu);
}
static inline void gemm1F16(const __half* ah, const __half* bh,
                            const float* bias, __half* oh, int K, int N,
                            int Npad, int relu) {
    gemm1_mma_kernel<<<dim3(Npad / 128, Mr / 128, 1), 256, GEMM1_DSMEM>>>(
        ah, bh, bias, nullptr, oh, nullptr, nullptr, nullptr, nullptr, K, N, relu);
}
static inline void gemmDualF16(const __half* a1, const __half* b1,
                               const float* bias1, __half* o1,
                               const __half* a2, const __half* b2,
                               const float* bias2, __half* o2,
                               int K, int N, int Npad) {
    gemm1_mma_kernel<<<dim3(Npad / 128, Mr / 128, 2), 256, GEMM1_DSMEM>>>(
        a1, b1, bias1, nullptr, o1, a2, b2, bias2, o2, K, N, 0);
}
static inline void gemm2F32(const __half* ah, const __half* bh, const __half* bl,
                            const float* bias, float* C, int K, int N, int Npad,
                            int relu) {
    gemm2_mma_kernel<<<dim3(Npad / 128, Mr / 128), 256, GEMM2_DSMEM>>>(
        ah, bh, bl, bias, C, nullptr, K, N, relu);
}
static inline void gemm2F16(const __half* ah, const __half* bh, const __half* bl,
                            const float* bias, __half* oh, int K, int N,
                            int Npad, int relu) {
    gemm2_mma_kernel<<<dim3(Npad / 128, Mr / 128), 256, GEMM2_DSMEM>>>(
        ah, bh, bl, bias, nullptr, oh, K, N, relu);
}

extern "C" void kernel_launch(void* const* d_in, const int* in_sizes, int n_in,
                              void* d_out, int out_size) {
    const int*   q_data = (const int*)d_in[0];
    const int*   target = (const int*)d_in[1];
    const float* pe     = (const float*)d_in[2];
    const float* q_emb  = (const float*)d_in[3];
    const float* qa_emb = (const float*)d_in[4];
    const float* Wk     = (const float*)d_in[5];
    const float* bk     = (const float*)d_in[6];
    const float* Wv     = (const float*)d_in[7];
    const float* bv     = (const float*)d_in[8];
    const float* Wo     = (const float*)d_in[9];
    const float* bo     = (const float*)d_in[10];
    const float* ln1_g  = (const float*)d_in[11];
    const float* ln1_b  = (const float*)d_in[12];
    const float* W1     = (const float*)d_in[13];
    const float* b1     = (const float*)d_in[14];
    const float* W2     = (const float*)d_in[15];
    const float* b2     = (const float*)d_in[16];
    const float* ln2_g  = (const float*)d_in[17];
    const float* ln2_b  = (const float*)d_in[18];
    const float* Wout1  = (const float*)d_in[19];
    const float* bout1  = (const float*)d_in[20];
    const float* Wout2  = (const float*)d_in[21];
    const float* bout2  = (const float*)d_in[22];
    const float* Wout3  = (const float*)d_in[23];
    const float* bout3  = (const float*)d_in[24];
    float* out = (float*)d_out;

    cudaFuncSetAttribute(gemm1_mma_kernel,
                         cudaFuncAttributeMaxDynamicSharedMemorySize, GEMM1_DSMEM);
    cudaFuncSetAttribute(gemm2_mma_kernel,
                         cudaFuncAttributeMaxDynamicSharedMemorySize, GEMM2_DSMEM);

    float *p_x, *p_P;
    cudaGetSymbolAddress((void**)&p_x, g_x);
    cudaGetSymbolAddress((void**)&p_P, g_P);

    __half *xh, *yh, *kh, *vh, *oh, *f1h, *ch, *h1h, *h2h;
    cudaGetSymbolAddress((void**)&xh, g_xh);
    cudaGetSymbolAddress((void**)&yh, g_yh);
    cudaGetSymbolAddress((void**)&kh, g_Kh);
    cudaGetSymbolAddress((void**)&vh, g_Vh);
    cudaGetSymbolAddress((void**)&oh, g_Oh);
    cudaGetSymbolAddress((void**)&f1h, g_F1h);
    cudaGetSymbolAddress((void**)&ch, g_Ch);
    cudaGetSymbolAddress((void**)&h1h, g_H1h);
    cudaGetSymbolAddress((void**)&h2h, g_H2h);

    __half *wk_h, *wv_h, *wo_h, *w1_h, *w2_h;
    __half *wo1_h, *wo1_l, *wo2_h, *wo2_l, *wo3_h, *wo3_l;
    cudaGetSymbolAddress((void**)&wk_h, g_Wk_h);
    cudaGetSymbolAddress((void**)&wv_h, g_Wv_h);
    cudaGetSymbolAddress((void**)&wo_h, g_Wo_h);
    cudaGetSymbolAddress((void**)&w1_h, g_W1_h);
    cudaGetSymbolAddress((void**)&w2_h, g_W2_h);
    cudaGetSymbolAddress((void**)&wo1_h, g_Wo1_h); cudaGetSymbolAddress((void**)&wo1_l, g_Wo1_l);
    cudaGetSymbolAddress((void**)&wo2_h, g_Wo2_h); cudaGetSymbolAddress((void**)&wo2_l, g_Wo2_l);
    cudaGetSymbolAddress((void**)&wo3_h, g_Wo3_h); cudaGetSymbolAddress((void**)&wo3_l, g_Wo3_l);

    // embed (+ Ch second half)
    {
        size_t tot = (size_t)Mr * Dc;
        embed_kernel<<<(unsigned)((tot + 255) / 256), 256>>>(q_data, target, pe,
                                                             q_emb, qa_emb);
    }
    // batched weight prep: one launch per weight type
    split_w_batch_kernel<<<dim3(Dc / 32, Dc / 32, Lc), dim3(32, 8)>>>(Wk, wk_h, Dc, Dc);
    split_w_batch_kernel<<<dim3(Dc / 32, Dc / 32, Lc), dim3(32, 8)>>>(Wv, wv_h, Dc, Dc);
    split_w_batch_kernel<<<dim3(Dc / 32, Dc / 32, Lc), dim3(32, 8)>>>(Wo, wo_h, Dc, Dc);
    split_w_batch_kernel<<<dim3(DFFc / 32, Dc / 32, Lc), dim3(32, 8)>>>(W1, w1_h, Dc, DFFc);
    split_w_batch_kernel<<<dim3(Dc / 32, DFFc / 32, Lc), dim3(32, 8)>>>(W2, w2_h, DFFc, Dc);
    split_w_kernel<<<dim3(FC1c / 32, 2 * Dc / 32), dim3(32, 8)>>>(Wout1, wo1_h, wo1_l, 2 * Dc, FC1c);
    split_w_kernel<<<dim3(FC2c / 32, FC1c / 32), dim3(32, 8)>>>(Wout2, wo2_h, wo2_l, FC1c, FC2c);
    split_w_kernel<<<dim3(NSKp / 32, FC2c / 32), dim3(32, 8)>>>(Wout3, wo3_h, wo3_l, FC2c, NSKc);

    // transformer layers
    for (int l = 0; l < Lc; l++) {
        size_t oDD = (size_t)l * Dc * Dc;
        size_t oDF = (size_t)l * Dc * DFFc;
        gemmDualF16(xh, wk_h + oDD, bk + l * Dc, kh,
                    yh, wv_h + oDD, bv + l * Dc, vh, Dc, Dc, Dc);
        attn_tc_kernel<<<dim3(Sc / 64, Hc, Bc), 128>>>();
        gemm1F32(oh, wo_h + oDD, bo + l * Dc, p_P, Dc, Dc, Dc, 0);
        add_ln_kernel<<<Mr / 8, 256>>>(p_x, p_P, ln1_g + l * Dc, ln1_b + l * Dc,
                                       nullptr);
        gemm1F16(xh, w1_h + oDF, b1 + l * DFFc, f1h, Dc, DFFc, DFFc, 1);
        gemm1F32(f1h, w2_h + oDF, b2 + l * Dc, p_P, DFFc, Dc, Dc, 0);
        add_ln_kernel<<<Mr / 8, 256>>>(p_x, p_P, ln2_g + l * Dc, ln2_b + l * Dc,
                                       (l == Lc - 1) ? ch : nullptr);
    }

    // head (concat already materialized in Ch)
    gemm2F16(ch, wo1_h, wo1_l, bout1, h1h, 2 * Dc, FC1c, FC1c, 1);
    gemm2F16(h1h, wo2_h, wo2_l, bout2, h2h, FC1c, FC2c, FC2c, 1);
    gemm2F32(h2h, wo3_h, wo3_l, bout3, out, FC2c, NSKc, NSKp, 0);
}